// round 1
// baseline (speedup 1.0000x reference)
#include <cuda_runtime.h>
#include <math.h>

#define B_  2
#define S_  2048
#define D_  1024
#define H_  16
#define HD_ 64
#define M_  (B_*S_)   // 4096

// Scratch (allocation-free rule: __device__ globals)
__device__ float g_q[(size_t)B_*H_*S_*HD_];
__device__ float g_k[(size_t)B_*H_*S_*HD_];
__device__ float g_v[(size_t)B_*H_*S_*HD_];
__device__ float g_ctx[(size_t)M_*D_];

// ---------------------------------------------------------------------------
// Tiled SGEMM: Y = X[M,K] @ W[K,N] + bias, M=4096, N=K=1024.
// BM=BN=64, BK=16, 256 threads, 4x4 per thread.
// SPLIT=true: scatter output into head-split layout [B,H,S,HD] (n = h*64+hd).
// ---------------------------------------------------------------------------
template<bool SPLIT>
__global__ __launch_bounds__(256) void sgemm_bias_kernel(
    const float* __restrict__ X, const float* __restrict__ W,
    const float* __restrict__ bias, float* __restrict__ Y)
{
    const int K = D_, N = D_;
    __shared__ float As[16][68];   // [k][m], pitch 68 (16B-aligned rows, conflict-ok)
    __shared__ float Bs[16][64];   // [k][n]

    int tid = threadIdx.x;
    int tx = tid & 15, ty = tid >> 4;
    int m0 = blockIdx.y * 64, n0 = blockIdx.x * 64;

    float acc[4][4];
    #pragma unroll
    for (int i = 0; i < 4; i++)
        #pragma unroll
        for (int j = 0; j < 4; j++) acc[i][j] = 0.f;

    int lrow = tid >> 2, lq = tid & 3;        // A loader: row 0..63, quad 0..3
    int bk = tid >> 4, bc = (tid & 15) << 2;  // B loader: k 0..15, col quad

    for (int k0 = 0; k0 < K; k0 += 16) {
        float4 a = *(const float4*)(X + (size_t)(m0 + lrow) * K + k0 + lq * 4);
        As[lq*4+0][lrow] = a.x; As[lq*4+1][lrow] = a.y;
        As[lq*4+2][lrow] = a.z; As[lq*4+3][lrow] = a.w;
        float4 b = *(const float4*)(W + (size_t)(k0 + bk) * N + n0 + bc);
        *(float4*)&Bs[bk][bc] = b;
        __syncthreads();

        #pragma unroll
        for (int k = 0; k < 16; k++) {
            float4 ra4 = *(const float4*)&As[k][ty * 4];
            float4 rb4 = *(const float4*)&Bs[k][tx * 4];
            float ra[4] = {ra4.x, ra4.y, ra4.z, ra4.w};
            float rb[4] = {rb4.x, rb4.y, rb4.z, rb4.w};
            #pragma unroll
            for (int i = 0; i < 4; i++)
                #pragma unroll
                for (int j = 0; j < 4; j++)
                    acc[i][j] = fmaf(ra[i], rb[j], acc[i][j]);
        }
        __syncthreads();
    }

    #pragma unroll
    for (int i = 0; i < 4; i++) {
        int m = m0 + ty * 4 + i;
        #pragma unroll
        for (int j = 0; j < 4; j++) {
            int n = n0 + tx * 4 + j;
            float v = acc[i][j] + bias[n];
            if (SPLIT) {
                int b = m >> 11, s = m & (S_ - 1);
                int h = n >> 6,  hd = n & (HD_ - 1);
                Y[(((size_t)(b * H_ + h)) * S_ + s) * HD_ + hd] = v;
            } else {
                Y[(size_t)m * N + n] = v;
            }
        }
    }
}

// ---------------------------------------------------------------------------
// Flash attention: one CTA per (q-tile of 64 rows, head, batch).
// Br=Bc=64, HD=64. 256 threads, 4x4 register tiling for S=QK^T and O+=PV.
// Online softmax, half-warp shfl row reductions (row owned by 16 lanes, same ty).
// ---------------------------------------------------------------------------
__global__ __launch_bounds__(256) void flash_kernel(
    const float* __restrict__ gq, const float* __restrict__ gk,
    const float* __restrict__ gv, float* __restrict__ ctx)
{
    extern __shared__ float sm[];
    float* Qs = sm;              // [64][68]  row-major (r,d)
    float* Kt = Qs + 64 * 68;    // [64][68]  transposed (d,c)
    float* Vs = Kt + 64 * 68;    // [64][64]  row-major (c,d)
    float* Ps = Vs + 64 * 64;    // [64][68]  row-major (r,c)

    int tid = threadIdx.x;
    int tx = tid & 15, ty = tid >> 4;
    int qt = blockIdx.x, h = blockIdx.y, b = blockIdx.z;

    const size_t bh = (size_t)(b * H_ + h);
    const float* qb = gq + (bh * S_ + (size_t)qt * 64) * HD_;
    const float* kb = gk + bh * S_ * HD_;
    const float* vb = gv + bh * S_ * HD_;

    // Load Q tile (scaled by 1/sqrt(HD) = 0.125)
    for (int e = tid * 4; e < 64 * 64; e += 256 * 4) {
        int rr = e >> 6, dd = e & 63;
        float4 t = *(const float4*)(qb + rr * 64 + dd);
        t.x *= 0.125f; t.y *= 0.125f; t.z *= 0.125f; t.w *= 0.125f;
        *(float4*)(Qs + rr * 68 + dd) = t;
    }

    float m_[4], l_[4], o[4][4];
    #pragma unroll
    for (int i = 0; i < 4; i++) {
        m_[i] = -1e30f; l_[i] = 0.f;
        #pragma unroll
        for (int j = 0; j < 4; j++) o[i][j] = 0.f;
    }

    for (int kt = 0; kt < S_ / 64; kt++) {
        __syncthreads();  // all PV reads of previous tiles done; Qs visible (1st iter)
        const float* kp = kb + (size_t)kt * 64 * 64;
        const float* vp = vb + (size_t)kt * 64 * 64;
        for (int e = tid * 4; e < 4096; e += 1024)
            *(float4*)(Vs + e) = *(const float4*)(vp + e);
        for (int e = tid; e < 4096; e += 256) {
            int cc = e >> 6, dd = e & 63;
            Kt[dd * 68 + cc] = kp[e];
        }
        __syncthreads();

        // S = Q K^T  (4x4 per thread: rows ty*4+i, cols tx*4+j)
        float s[4][4];
        #pragma unroll
        for (int i = 0; i < 4; i++)
            #pragma unroll
            for (int j = 0; j < 4; j++) s[i][j] = 0.f;

        #pragma unroll 4
        for (int d = 0; d < 64; d++) {
            float4 kv4 = *(const float4*)(Kt + d * 68 + tx * 4);
            float kv[4] = {kv4.x, kv4.y, kv4.z, kv4.w};
            #pragma unroll
            for (int i = 0; i < 4; i++) {
                float qv = Qs[(ty * 4 + i) * 68 + d];
                #pragma unroll
                for (int j = 0; j < 4; j++)
                    s[i][j] = fmaf(qv, kv[j], s[i][j]);
            }
        }

        // Online softmax per row (row owned by 16 lanes with same ty)
        #pragma unroll
        for (int i = 0; i < 4; i++) {
            float mx = fmaxf(fmaxf(s[i][0], s[i][1]), fmaxf(s[i][2], s[i][3]));
            mx = fmaxf(mx, __shfl_xor_sync(0xffffffffu, mx, 1));
            mx = fmaxf(mx, __shfl_xor_sync(0xffffffffu, mx, 2));
            mx = fmaxf(mx, __shfl_xor_sync(0xffffffffu, mx, 4));
            mx = fmaxf(mx, __shfl_xor_sync(0xffffffffu, mx, 8));
            float mn = fmaxf(m_[i], mx);
            float corr = __expf(m_[i] - mn);
            m_[i] = mn;
            float ls = 0.f;
            #pragma unroll
            for (int j = 0; j < 4; j++) {
                s[i][j] = __expf(s[i][j] - mn);
                ls += s[i][j];
            }
            ls += __shfl_xor_sync(0xffffffffu, ls, 1);
            ls += __shfl_xor_sync(0xffffffffu, ls, 2);
            ls += __shfl_xor_sync(0xffffffffu, ls, 4);
            ls += __shfl_xor_sync(0xffffffffu, ls, 8);
            l_[i] = l_[i] * corr + ls;
            #pragma unroll
            for (int j = 0; j < 4; j++) o[i][j] *= corr;
            float4 pw = make_float4(s[i][0], s[i][1], s[i][2], s[i][3]);
            *(float4*)(Ps + (ty * 4 + i) * 68 + tx * 4) = pw;
        }
        __syncthreads();

        // O += P V  (rows ty*4+i, d-cols tx*4+j)
        #pragma unroll 4
        for (int c = 0; c < 64; c++) {
            float4 vv4 = *(const float4*)(Vs + c * 64 + tx * 4);
            float vv[4] = {vv4.x, vv4.y, vv4.z, vv4.w};
            #pragma unroll
            for (int i = 0; i < 4; i++) {
                float pv = Ps[(ty * 4 + i) * 68 + c];
                #pragma unroll
                for (int j = 0; j < 4; j++)
                    o[i][j] = fmaf(pv, vv[j], o[i][j]);
            }
        }
    }

    // Epilogue: write to ctx[b, s, h*64 + d] (context layout for O-projection)
    #pragma unroll
    for (int i = 0; i < 4; i++) {
        float inv = 1.0f / l_[i];
        int row = qt * 64 + ty * 4 + i;
        float4 r = make_float4(o[i][0] * inv, o[i][1] * inv,
                               o[i][2] * inv, o[i][3] * inv);
        *(float4*)(ctx + ((size_t)b * S_ + row) * D_ + h * 64 + tx * 4) = r;
    }
}

// ---------------------------------------------------------------------------
extern "C" void kernel_launch(void* const* d_in, const int* in_sizes, int n_in,
                              void* d_out, int out_size)
{
    const float* xq = (const float*)d_in[0];
    const float* xk = (const float*)d_in[1];
    const float* xv = (const float*)d_in[2];
    const float* Wq = (const float*)d_in[3];
    const float* bq = (const float*)d_in[4];
    const float* Wk = (const float*)d_in[5];
    const float* bk = (const float*)d_in[6];
    const float* Wv = (const float*)d_in[7];
    const float* bv = (const float*)d_in[8];
    const float* Wo = (const float*)d_in[9];
    const float* bo = (const float*)d_in[10];
    float* out = (float*)d_out;

    float *q, *k, *v, *ctx;
    cudaGetSymbolAddress((void**)&q,   g_q);
    cudaGetSymbolAddress((void**)&k,   g_k);
    cudaGetSymbolAddress((void**)&v,   g_v);
    cudaGetSymbolAddress((void**)&ctx, g_ctx);

    static bool attr_done = false;
    if (!attr_done) {
        cudaFuncSetAttribute(flash_kernel,
                             cudaFuncAttributeMaxDynamicSharedMemorySize,
                             (64*68*3 + 64*64) * 4);
        attr_done = true;
    }

    dim3 ggrid(D_ / 64, M_ / 64);  // (16, 64)
    sgemm_bias_kernel<true><<<ggrid, 256>>>(xq, Wq, bq, q);
    sgemm_bias_kernel<true><<<ggrid, 256>>>(xk, Wk, bk, k);
    sgemm_bias_kernel<true><<<ggrid, 256>>>(xv, Wv, bv, v);

    flash_kernel<<<dim3(S_ / 64, H_, B_), 256, (64*68*3 + 64*64) * 4>>>(q, k, v, ctx);

    sgemm_bias_kernel<false><<<ggrid, 256>>>(ctx, Wo, bo, out);
}

// round 2
// speedup vs baseline: 1.0008x; 1.0008x over previous
#include <cuda_runtime.h>
#include <math.h>

#define B_  2
#define S_  2048
#define D_  1024
#define H_  16
#define HD_ 64
#define M_  (B_*S_)   // 4096

// Scratch (allocation-free rule: __device__ globals)
__device__ float g_q[(size_t)B_*H_*S_*HD_];
__device__ float g_k[(size_t)B_*H_*S_*HD_];
__device__ float g_v[(size_t)B_*H_*S_*HD_];
__device__ float g_ctx[(size_t)M_*D_];

// ---------------------------------------------------------------------------
// Tiled SGEMM: Y = X[M,K] @ W[K,N] + bias, M=4096, N=K=1024.
// BM=BN=64, BK=16, 256 threads, 4x4 per thread.
// SPLIT=true: scatter output into head-split layout [B,H,S,HD] (n = h*64+hd).
// ---------------------------------------------------------------------------
template<bool SPLIT>
__global__ __launch_bounds__(256) void sgemm_bias_kernel(
    const float* __restrict__ X, const float* __restrict__ W,
    const float* __restrict__ bias, float* __restrict__ Y)
{
    const int K = D_, N = D_;
    __shared__ float As[16][68];   // [k][m], pitch 68 (16B-aligned rows, conflict-ok)
    __shared__ float Bs[16][64];   // [k][n]

    int tid = threadIdx.x;
    int tx = tid & 15, ty = tid >> 4;
    int m0 = blockIdx.y * 64, n0 = blockIdx.x * 64;

    float acc[4][4];
    #pragma unroll
    for (int i = 0; i < 4; i++)
        #pragma unroll
        for (int j = 0; j < 4; j++) acc[i][j] = 0.f;

    int lrow = tid >> 2, lq = tid & 3;        // A loader: row 0..63, quad 0..3
    int bk = tid >> 4, bc = (tid & 15) << 2;  // B loader: k 0..15, col quad

    for (int k0 = 0; k0 < K; k0 += 16) {
        float4 a = *(const float4*)(X + (size_t)(m0 + lrow) * K + k0 + lq * 4);
        As[lq*4+0][lrow] = a.x; As[lq*4+1][lrow] = a.y;
        As[lq*4+2][lrow] = a.z; As[lq*4+3][lrow] = a.w;
        float4 b = *(const float4*)(W + (size_t)(k0 + bk) * N + n0 + bc);
        *(float4*)&Bs[bk][bc] = b;
        __syncthreads();

        #pragma unroll
        for (int k = 0; k < 16; k++) {
            float4 ra4 = *(const float4*)&As[k][ty * 4];
            float4 rb4 = *(const float4*)&Bs[k][tx * 4];
            float ra[4] = {ra4.x, ra4.y, ra4.z, ra4.w};
            float rb[4] = {rb4.x, rb4.y, rb4.z, rb4.w};
            #pragma unroll
            for (int i = 0; i < 4; i++)
                #pragma unroll
                for (int j = 0; j < 4; j++)
                    acc[i][j] = fmaf(ra[i], rb[j], acc[i][j]);
        }
        __syncthreads();
    }

    #pragma unroll
    for (int i = 0; i < 4; i++) {
        int m = m0 + ty * 4 + i;
        #pragma unroll
        for (int j = 0; j < 4; j++) {
            int n = n0 + tx * 4 + j;
            float v = acc[i][j] + bias[n];
            if (SPLIT) {
                int b = m >> 11, s = m & (S_ - 1);
                int h = n >> 6,  hd = n & (HD_ - 1);
                Y[(((size_t)(b * H_ + h)) * S_ + s) * HD_ + hd] = v;
            } else {
                Y[(size_t)m * N + n] = v;
            }
        }
    }
}

// ---------------------------------------------------------------------------
// Flash attention: one CTA per (q-tile of 64 rows, head, batch).
// Br=Bc=64, HD=64. 256 threads, 4x4 register tiling for S=QK^T and O+=PV.
// Online softmax, half-warp shfl row reductions (row owned by 16 lanes, same ty).
// ---------------------------------------------------------------------------
__global__ __launch_bounds__(256) void flash_kernel(
    const float* __restrict__ gq, const float* __restrict__ gk,
    const float* __restrict__ gv, float* __restrict__ ctx)
{
    extern __shared__ float sm[];
    float* Qs = sm;              // [64][68]  row-major (r,d)
    float* Kt = Qs + 64 * 68;    // [64][68]  transposed (d,c)
    float* Vs = Kt + 64 * 68;    // [64][64]  row-major (c,d)
    float* Ps = Vs + 64 * 64;    // [64][68]  row-major (r,c)

    int tid = threadIdx.x;
    int tx = tid & 15, ty = tid >> 4;
    int qt = blockIdx.x, h = blockIdx.y, b = blockIdx.z;

    const size_t bh = (size_t)(b * H_ + h);
    const float* qb = gq + (bh * S_ + (size_t)qt * 64) * HD_;
    const float* kb = gk + bh * S_ * HD_;
    const float* vb = gv + bh * S_ * HD_;

    // Load Q tile (scaled by 1/sqrt(HD) = 0.125)
    for (int e = tid * 4; e < 64 * 64; e += 256 * 4) {
        int rr = e >> 6, dd = e & 63;
        float4 t = *(const float4*)(qb + rr * 64 + dd);
        t.x *= 0.125f; t.y *= 0.125f; t.z *= 0.125f; t.w *= 0.125f;
        *(float4*)(Qs + rr * 68 + dd) = t;
    }

    float m_[4], l_[4], o[4][4];
    #pragma unroll
    for (int i = 0; i < 4; i++) {
        m_[i] = -1e30f; l_[i] = 0.f;
        #pragma unroll
        for (int j = 0; j < 4; j++) o[i][j] = 0.f;
    }

    for (int kt = 0; kt < S_ / 64; kt++) {
        __syncthreads();  // all PV reads of previous tiles done; Qs visible (1st iter)
        const float* kp = kb + (size_t)kt * 64 * 64;
        const float* vp = vb + (size_t)kt * 64 * 64;
        for (int e = tid * 4; e < 4096; e += 1024)
            *(float4*)(Vs + e) = *(const float4*)(vp + e);
        for (int e = tid; e < 4096; e += 256) {
            int cc = e >> 6, dd = e & 63;
            Kt[dd * 68 + cc] = kp[e];
        }
        __syncthreads();

        // S = Q K^T  (4x4 per thread: rows ty*4+i, cols tx*4+j)
        float s[4][4];
        #pragma unroll
        for (int i = 0; i < 4; i++)
            #pragma unroll
            for (int j = 0; j < 4; j++) s[i][j] = 0.f;

        #pragma unroll 4
        for (int d = 0; d < 64; d++) {
            float4 kv4 = *(const float4*)(Kt + d * 68 + tx * 4);
            float kv[4] = {kv4.x, kv4.y, kv4.z, kv4.w};
            #pragma unroll
            for (int i = 0; i < 4; i++) {
                float qv = Qs[(ty * 4 + i) * 68 + d];
                #pragma unroll
                for (int j = 0; j < 4; j++)
                    s[i][j] = fmaf(qv, kv[j], s[i][j]);
            }
        }

        // Online softmax per row (row owned by 16 lanes with same ty)
        #pragma unroll
        for (int i = 0; i < 4; i++) {
            float mx = fmaxf(fmaxf(s[i][0], s[i][1]), fmaxf(s[i][2], s[i][3]));
            mx = fmaxf(mx, __shfl_xor_sync(0xffffffffu, mx, 1));
            mx = fmaxf(mx, __shfl_xor_sync(0xffffffffu, mx, 2));
            mx = fmaxf(mx, __shfl_xor_sync(0xffffffffu, mx, 4));
            mx = fmaxf(mx, __shfl_xor_sync(0xffffffffu, mx, 8));
            float mn = fmaxf(m_[i], mx);
            float corr = __expf(m_[i] - mn);
            m_[i] = mn;
            float ls = 0.f;
            #pragma unroll
            for (int j = 0; j < 4; j++) {
                s[i][j] = __expf(s[i][j] - mn);
                ls += s[i][j];
            }
            ls += __shfl_xor_sync(0xffffffffu, ls, 1);
            ls += __shfl_xor_sync(0xffffffffu, ls, 2);
            ls += __shfl_xor_sync(0xffffffffu, ls, 4);
            ls += __shfl_xor_sync(0xffffffffu, ls, 8);
            l_[i] = l_[i] * corr + ls;
            #pragma unroll
            for (int j = 0; j < 4; j++) o[i][j] *= corr;
            float4 pw = make_float4(s[i][0], s[i][1], s[i][2], s[i][3]);
            *(float4*)(Ps + (ty * 4 + i) * 68 + tx * 4) = pw;
        }
        __syncthreads();

        // O += P V  (rows ty*4+i, d-cols tx*4+j)
        #pragma unroll 4
        for (int c = 0; c < 64; c++) {
            float4 vv4 = *(const float4*)(Vs + c * 64 + tx * 4);
            float vv[4] = {vv4.x, vv4.y, vv4.z, vv4.w};
            #pragma unroll
            for (int i = 0; i < 4; i++) {
                float pv = Ps[(ty * 4 + i) * 68 + c];
                #pragma unroll
                for (int j = 0; j < 4; j++)
                    o[i][j] = fmaf(pv, vv[j], o[i][j]);
            }
        }
    }

    // Epilogue: write to ctx[b, s, h*64 + d] (context layout for O-projection)
    #pragma unroll
    for (int i = 0; i < 4; i++) {
        float inv = 1.0f / l_[i];
        int row = qt * 64 + ty * 4 + i;
        float4 r = make_float4(o[i][0] * inv, o[i][1] * inv,
                               o[i][2] * inv, o[i][3] * inv);
        *(float4*)(ctx + ((size_t)b * S_ + row) * D_ + h * 64 + tx * 4) = r;
    }
}

// ---------------------------------------------------------------------------
extern "C" void kernel_launch(void* const* d_in, const int* in_sizes, int n_in,
                              void* d_out, int out_size)
{
    const float* xq = (const float*)d_in[0];
    const float* xk = (const float*)d_in[1];
    const float* xv = (const float*)d_in[2];
    const float* Wq = (const float*)d_in[3];
    const float* bq = (const float*)d_in[4];
    const float* Wk = (const float*)d_in[5];
    const float* bk = (const float*)d_in[6];
    const float* Wv = (const float*)d_in[7];
    const float* bv = (const float*)d_in[8];
    const float* Wo = (const float*)d_in[9];
    const float* bo = (const float*)d_in[10];
    float* out = (float*)d_out;

    float *q, *k, *v, *ctx;
    cudaGetSymbolAddress((void**)&q,   g_q);
    cudaGetSymbolAddress((void**)&k,   g_k);
    cudaGetSymbolAddress((void**)&v,   g_v);
    cudaGetSymbolAddress((void**)&ctx, g_ctx);

    static bool attr_done = false;
    if (!attr_done) {
        cudaFuncSetAttribute(flash_kernel,
                             cudaFuncAttributeMaxDynamicSharedMemorySize,
                             (64*68*3 + 64*64) * 4);
        attr_done = true;
    }

    dim3 ggrid(D_ / 64, M_ / 64);  // (16, 64)
    sgemm_bias_kernel<true><<<ggrid, 256>>>(xq, Wq, bq, q);
    sgemm_bias_kernel<true><<<ggrid, 256>>>(xk, Wk, bk, k);
    sgemm_bias_kernel<true><<<ggrid, 256>>>(xv, Wv, bv, v);

    flash_kernel<<<dim3(S_ / 64, H_, B_), 256, (64*68*3 + 64*64) * 4>>>(q, k, v, ctx);

    sgemm_bias_kernel<false><<<ggrid, 256>>>(ctx, Wo, bo, out);
}

// round 3
// speedup vs baseline: 1.0678x; 1.0670x over previous
#include <cuda_runtime.h>
#include <math.h>

#define B_  2
#define S_  2048
#define D_  1024
#define H_  16
#define HD_ 64
#define M_  (B_*S_)   // 4096

typedef unsigned long long u64t;

// Scratch (allocation-free rule: __device__ globals)
__device__ float g_q[(size_t)B_*H_*S_*HD_];
__device__ float g_k[(size_t)B_*H_*S_*HD_];
__device__ float g_v[(size_t)B_*H_*S_*HD_];
__device__ float g_ctx[(size_t)M_*D_];

// ---- packed f32x2 helpers (Blackwell sm_103a FFMA2 path) ---------------------
__device__ __forceinline__ u64t bcast2(float x) {
    u64t r;
    asm("mov.b64 %0, {%1, %1};" : "=l"(r) : "r"(__float_as_uint(x)));
    return r;
}
__device__ __forceinline__ u64t pk2(float x, float y) {
    u64t r;
    asm("mov.b64 %0, {%1, %2};" : "=l"(r) : "r"(__float_as_uint(x)), "r"(__float_as_uint(y)));
    return r;
}
__device__ __forceinline__ float2 upk2(u64t v) {
    unsigned int lo, hi;
    asm("mov.b64 {%0, %1}, %2;" : "=r"(lo), "=r"(hi) : "l"(v));
    return make_float2(__uint_as_float(lo), __uint_as_float(hi));
}
__device__ __forceinline__ u64t fma2(u64t a, u64t b, u64t c) {
    u64t d;
    asm("fma.rn.f32x2 %0, %1, %2, %3;" : "=l"(d) : "l"(a), "l"(b), "l"(c));
    return d;
}
__device__ __forceinline__ u64t mul2(u64t a, u64t b) {
    u64t d;
    asm("mul.rn.f32x2 %0, %1, %2;" : "=l"(d) : "l"(a), "l"(b));
    return d;
}

// ---------------------------------------------------------------------------
// Tiled SGEMM: Y = X[M,K] @ W[K,N] + bias, M=4096, N=K=1024.
// BM=BN=64, BK=16, 256 threads, 4x4 per thread, f32x2 packed FMA inner loop.
// SPLIT=true: scatter output into head-split layout [B,H,S,HD] (n = h*64+hd).
// ---------------------------------------------------------------------------
template<bool SPLIT>
__global__ __launch_bounds__(256) void sgemm_bias_kernel(
    const float* __restrict__ X, const float* __restrict__ W,
    const float* __restrict__ bias, float* __restrict__ Y)
{
    const int K = D_, N = D_;
    __shared__ float As[16][68];   // [k][m], pitch 68
    __shared__ float Bs[16][64];   // [k][n]

    int tid = threadIdx.x;
    int tx = tid & 15, ty = tid >> 4;
    int m0 = blockIdx.y * 64, n0 = blockIdx.x * 64;

    u64t acc2[4][2];   // 4 rows x (2 packed col-pairs) = 4x4 scalars
    #pragma unroll
    for (int i = 0; i < 4; i++) { acc2[i][0] = 0ULL; acc2[i][1] = 0ULL; }

    int lrow = tid >> 2, lq = tid & 3;        // A loader: row 0..63, quad 0..3
    int bk = tid >> 4, bc = (tid & 15) << 2;  // B loader: k 0..15, col quad

    for (int k0 = 0; k0 < K; k0 += 16) {
        float4 a = *(const float4*)(X + (size_t)(m0 + lrow) * K + k0 + lq * 4);
        As[lq*4+0][lrow] = a.x; As[lq*4+1][lrow] = a.y;
        As[lq*4+2][lrow] = a.z; As[lq*4+3][lrow] = a.w;
        float4 b = *(const float4*)(W + (size_t)(k0 + bk) * N + n0 + bc);
        *(float4*)&Bs[bk][bc] = b;
        __syncthreads();

        #pragma unroll
        for (int k = 0; k < 16; k++) {
            float4 ra4 = *(const float4*)&As[k][ty * 4];
            ulonglong2 rb = *(const ulonglong2*)&Bs[k][tx * 4];
            u64t a0 = bcast2(ra4.x), a1 = bcast2(ra4.y);
            u64t a2 = bcast2(ra4.z), a3 = bcast2(ra4.w);
            acc2[0][0] = fma2(a0, rb.x, acc2[0][0]);
            acc2[0][1] = fma2(a0, rb.y, acc2[0][1]);
            acc2[1][0] = fma2(a1, rb.x, acc2[1][0]);
            acc2[1][1] = fma2(a1, rb.y, acc2[1][1]);
            acc2[2][0] = fma2(a2, rb.x, acc2[2][0]);
            acc2[2][1] = fma2(a2, rb.y, acc2[2][1]);
            acc2[3][0] = fma2(a3, rb.x, acc2[3][0]);
            acc2[3][1] = fma2(a3, rb.y, acc2[3][1]);
        }
        __syncthreads();
    }

    #pragma unroll
    for (int i = 0; i < 4; i++) {
        int m = m0 + ty * 4 + i;
        float vals[4];
        float2 v0 = upk2(acc2[i][0]), v1 = upk2(acc2[i][1]);
        vals[0] = v0.x; vals[1] = v0.y; vals[2] = v1.x; vals[3] = v1.y;
        #pragma unroll
        for (int j = 0; j < 4; j++) {
            int n = n0 + tx * 4 + j;
            float v = vals[j] + bias[n];
            if (SPLIT) {
                int b = m >> 11, s = m & (S_ - 1);
                int h = n >> 6,  hd = n & (HD_ - 1);
                Y[(((size_t)(b * H_ + h)) * S_ + s) * HD_ + hd] = v;
            } else {
                Y[(size_t)m * N + n] = v;
            }
        }
    }
}

// ---------------------------------------------------------------------------
// Flash attention: one CTA per (q-tile of 64 rows, head, batch).
// Br=Bc=64, HD=64. 256 threads, 4x4 tiling with f32x2 packed FMA.
// Online softmax, half-warp shfl row reductions.
// ---------------------------------------------------------------------------
__global__ __launch_bounds__(256) void flash_kernel(
    const float* __restrict__ gq, const float* __restrict__ gk,
    const float* __restrict__ gv, float* __restrict__ ctx)
{
    extern __shared__ float sm[];
    float* Qs = sm;              // [64][68]  row-major (r,d)
    float* Kt = Qs + 64 * 68;    // [64][68]  transposed (d,c)
    float* Vs = Kt + 64 * 68;    // [64][64]  row-major (c,d)
    float* Ps = Vs + 64 * 64;    // [64][68]  row-major (r,c)

    int tid = threadIdx.x;
    int tx = tid & 15, ty = tid >> 4;
    int qt = blockIdx.x, h = blockIdx.y, b = blockIdx.z;

    const size_t bh = (size_t)(b * H_ + h);
    const float* qb = gq + (bh * S_ + (size_t)qt * 64) * HD_;
    const float* kb = gk + bh * S_ * HD_;
    const float* vb = gv + bh * S_ * HD_;

    // Load Q tile (scaled by 1/sqrt(HD) = 0.125)
    for (int e = tid * 4; e < 64 * 64; e += 256 * 4) {
        int rr = e >> 6, dd = e & 63;
        float4 t = *(const float4*)(qb + rr * 64 + dd);
        t.x *= 0.125f; t.y *= 0.125f; t.z *= 0.125f; t.w *= 0.125f;
        *(float4*)(Qs + rr * 68 + dd) = t;
    }

    float m_[4], l_[4];
    u64t o2[4][2];
    #pragma unroll
    for (int i = 0; i < 4; i++) {
        m_[i] = -1e30f; l_[i] = 0.f;
        o2[i][0] = 0ULL; o2[i][1] = 0ULL;
    }

    for (int kt = 0; kt < S_ / 64; kt++) {
        __syncthreads();  // prev PV reads done; Qs visible (1st iter)
        const float* kp = kb + (size_t)kt * 64 * 64;
        const float* vp = vb + (size_t)kt * 64 * 64;
        for (int e = tid * 4; e < 4096; e += 1024)
            *(float4*)(Vs + e) = *(const float4*)(vp + e);
        for (int e = tid; e < 4096; e += 256) {
            int cc = e >> 6, dd = e & 63;
            Kt[dd * 68 + cc] = kp[e];
        }
        __syncthreads();

        // S = Q K^T  (rows ty*4+i, packed col pairs at tx*4)
        u64t s2[4][2];
        #pragma unroll
        for (int i = 0; i < 4; i++) { s2[i][0] = 0ULL; s2[i][1] = 0ULL; }

        #pragma unroll 4
        for (int d = 0; d < 64; d++) {
            ulonglong2 kv = *(const ulonglong2*)(Kt + d * 68 + tx * 4);
            #pragma unroll
            for (int i = 0; i < 4; i++) {
                u64t q2 = bcast2(Qs[(ty * 4 + i) * 68 + d]);
                s2[i][0] = fma2(q2, kv.x, s2[i][0]);
                s2[i][1] = fma2(q2, kv.y, s2[i][1]);
            }
        }

        // Online softmax per row (row owned by 16 lanes with same ty)
        #pragma unroll
        for (int i = 0; i < 4; i++) {
            float2 e0 = upk2(s2[i][0]), e1 = upk2(s2[i][1]);
            float mx = fmaxf(fmaxf(e0.x, e0.y), fmaxf(e1.x, e1.y));
            mx = fmaxf(mx, __shfl_xor_sync(0xffffffffu, mx, 1));
            mx = fmaxf(mx, __shfl_xor_sync(0xffffffffu, mx, 2));
            mx = fmaxf(mx, __shfl_xor_sync(0xffffffffu, mx, 4));
            mx = fmaxf(mx, __shfl_xor_sync(0xffffffffu, mx, 8));
            float mn = fmaxf(m_[i], mx);
            float corr = __expf(m_[i] - mn);
            m_[i] = mn;
            e0.x = __expf(e0.x - mn); e0.y = __expf(e0.y - mn);
            e1.x = __expf(e1.x - mn); e1.y = __expf(e1.y - mn);
            float ls = (e0.x + e0.y) + (e1.x + e1.y);
            ls += __shfl_xor_sync(0xffffffffu, ls, 1);
            ls += __shfl_xor_sync(0xffffffffu, ls, 2);
            ls += __shfl_xor_sync(0xffffffffu, ls, 4);
            ls += __shfl_xor_sync(0xffffffffu, ls, 8);
            l_[i] = l_[i] * corr + ls;
            u64t c2 = bcast2(corr);
            o2[i][0] = mul2(o2[i][0], c2);
            o2[i][1] = mul2(o2[i][1], c2);
            ulonglong2 pw;
            pw.x = pk2(e0.x, e0.y);
            pw.y = pk2(e1.x, e1.y);
            *(ulonglong2*)(Ps + (ty * 4 + i) * 68 + tx * 4) = pw;
        }
        __syncthreads();

        // O += P V  (rows ty*4+i, packed d-col pairs at tx*4)
        #pragma unroll 4
        for (int c = 0; c < 64; c++) {
            ulonglong2 vv = *(const ulonglong2*)(Vs + c * 64 + tx * 4);
            #pragma unroll
            for (int i = 0; i < 4; i++) {
                u64t p2 = bcast2(Ps[(ty * 4 + i) * 68 + c]);
                o2[i][0] = fma2(p2, vv.x, o2[i][0]);
                o2[i][1] = fma2(p2, vv.y, o2[i][1]);
            }
        }
    }

    // Epilogue: write to ctx[b, s, h*64 + d] (context layout for O-projection)
    #pragma unroll
    for (int i = 0; i < 4; i++) {
        float inv = 1.0f / l_[i];
        int row = qt * 64 + ty * 4 + i;
        float2 a = upk2(o2[i][0]), c = upk2(o2[i][1]);
        float4 r = make_float4(a.x * inv, a.y * inv, c.x * inv, c.y * inv);
        *(float4*)(ctx + ((size_t)b * S_ + row) * D_ + h * 64 + tx * 4) = r;
    }
}

// ---------------------------------------------------------------------------
extern "C" void kernel_launch(void* const* d_in, const int* in_sizes, int n_in,
                              void* d_out, int out_size)
{
    const float* xq = (const float*)d_in[0];
    const float* xk = (const float*)d_in[1];
    const float* xv = (const float*)d_in[2];
    const float* Wq = (const float*)d_in[3];
    const float* bq = (const float*)d_in[4];
    const float* Wk = (const float*)d_in[5];
    const float* bk = (const float*)d_in[6];
    const float* Wv = (const float*)d_in[7];
    const float* bv = (const float*)d_in[8];
    const float* Wo = (const float*)d_in[9];
    const float* bo = (const float*)d_in[10];
    float* out = (float*)d_out;

    float *q, *k, *v, *ctx;
    cudaGetSymbolAddress((void**)&q,   g_q);
    cudaGetSymbolAddress((void**)&k,   g_k);
    cudaGetSymbolAddress((void**)&v,   g_v);
    cudaGetSymbolAddress((void**)&ctx, g_ctx);

    static bool attr_done = false;
    if (!attr_done) {
        cudaFuncSetAttribute(flash_kernel,
                             cudaFuncAttributeMaxDynamicSharedMemorySize,
                             (64*68*3 + 64*64) * 4);
        attr_done = true;
    }

    dim3 ggrid(D_ / 64, M_ / 64);  // (16, 64)
    sgemm_bias_kernel<true><<<ggrid, 256>>>(xq, Wq, bq, q);
    sgemm_bias_kernel<true><<<ggrid, 256>>>(xk, Wk, bk, k);
    sgemm_bias_kernel<true><<<ggrid, 256>>>(xv, Wv, bv, v);

    flash_kernel<<<dim3(S_ / 64, H_, B_), 256, (64*68*3 + 64*64) * 4>>>(q, k, v, ctx);

    sgemm_bias_kernel<false><<<ggrid, 256>>>(ctx, Wo, bo, out);
}

// round 5
// speedup vs baseline: 1.5087x; 1.4129x over previous
#include <cuda_runtime.h>
#include <cuda_bf16.h>
#include <cstdint>
#include <math.h>

#define B_  2
#define S_  2048
#define D_  1024
#define H_  16
#define HD_ 64
#define M_  (B_*S_)   // 4096

typedef unsigned long long u64t;

// ---------------- scratch (__device__ globals; no allocs allowed) ----------
__device__ float g_q[(size_t)B_*H_*S_*HD_];
__device__ float g_k[(size_t)B_*H_*S_*HD_];
__device__ float g_v[(size_t)B_*H_*S_*HD_];
__device__ float g_ctx[(size_t)M_*D_];
__device__ __nv_bfloat16 g_xh[(size_t)M_*D_];
__device__ __nv_bfloat16 g_xl[(size_t)M_*D_];
__device__ __nv_bfloat16 g_wh[(size_t)D_*D_];
__device__ __nv_bfloat16 g_wl[(size_t)D_*D_];

// ---------------- helpers ---------------------------------------------------
__device__ __forceinline__ uint32_t smem_u32(const void* p) {
    uint32_t a;
    asm("{ .reg .u64 t; cvta.to.shared.u64 t, %1; cvt.u32.u64 %0, t; }" : "=r"(a) : "l"(p));
    return a;
}
__device__ __forceinline__ void ldsm_x4(uint32_t* r, uint32_t addr) {
    asm volatile("ldmatrix.sync.aligned.m8n8.x4.shared.b16 {%0,%1,%2,%3}, [%4];"
                 : "=r"(r[0]), "=r"(r[1]), "=r"(r[2]), "=r"(r[3]) : "r"(addr));
}
__device__ __forceinline__ void ldsm_x2(uint32_t* r, uint32_t addr) {
    asm volatile("ldmatrix.sync.aligned.m8n8.x2.shared.b16 {%0,%1}, [%2];"
                 : "=r"(r[0]), "=r"(r[1]) : "r"(addr));
}
__device__ __forceinline__ void mma16816(float* d, const uint32_t* a,
                                         const uint32_t* b) {
    asm volatile("mma.sync.aligned.m16n8k16.row.col.f32.bf16.bf16.f32 "
        "{%0,%1,%2,%3}, {%4,%5,%6,%7}, {%8,%9}, {%0,%1,%2,%3};"
        : "+f"(d[0]), "+f"(d[1]), "+f"(d[2]), "+f"(d[3])
        : "r"(a[0]), "r"(a[1]), "r"(a[2]), "r"(a[3]), "r"(b[0]), "r"(b[1]));
}
#define CP_ASYNC16(dst, src) \
    asm volatile("cp.async.cg.shared.global [%0], [%1], 16;" :: "r"(dst), "l"(src))
#define CP_COMMIT() asm volatile("cp.async.commit_group;" ::: "memory")
#define CP_WAIT1()  asm volatile("cp.async.wait_group 1;" ::: "memory")
#define CP_WAIT0()  asm volatile("cp.async.wait_group 0;" ::: "memory")

// ---- packed f32x2 helpers ---------------------------------------------------
__device__ __forceinline__ u64t bcast2(float x) {
    u64t r; asm("mov.b64 %0, {%1, %1};" : "=l"(r) : "r"(__float_as_uint(x))); return r;
}
__device__ __forceinline__ u64t pk2(float x, float y) {
    u64t r;
    asm("mov.b64 %0, {%1, %2};" : "=l"(r) : "r"(__float_as_uint(x)), "r"(__float_as_uint(y)));
    return r;
}
__device__ __forceinline__ float2 upk2(u64t v) {
    unsigned int lo, hi;
    asm("mov.b64 {%0, %1}, %2;" : "=r"(lo), "=r"(hi) : "l"(v));
    return make_float2(__uint_as_float(lo), __uint_as_float(hi));
}
__device__ __forceinline__ u64t fma2(u64t a, u64t b, u64t c) {
    u64t d; asm("fma.rn.f32x2 %0, %1, %2, %3;" : "=l"(d) : "l"(a), "l"(b), "l"(c)); return d;
}
__device__ __forceinline__ u64t mul2(u64t a, u64t b) {
    u64t d; asm("mul.rn.f32x2 %0, %1, %2;" : "=l"(d) : "l"(a), "l"(b)); return d;
}

// ---------------------------------------------------------------------------
// fp32 -> bf16 hi/lo split (elementwise, float4 granularity)
// ---------------------------------------------------------------------------
__global__ __launch_bounds__(256) void convert_hl_kernel(
    const float* __restrict__ X, __nv_bfloat16* __restrict__ Xh,
    __nv_bfloat16* __restrict__ Xl)
{
    int i = blockIdx.x * blockDim.x + threadIdx.x;   // float4 index
    float4 x = ((const float4*)X)[i];
    __nv_bfloat16 h0 = __float2bfloat16(x.x), h1 = __float2bfloat16(x.y);
    __nv_bfloat16 h2 = __float2bfloat16(x.z), h3 = __float2bfloat16(x.w);
    __nv_bfloat16 l0 = __float2bfloat16(x.x - __bfloat162float(h0));
    __nv_bfloat16 l1 = __float2bfloat16(x.y - __bfloat162float(h1));
    __nv_bfloat16 l2 = __float2bfloat16(x.z - __bfloat162float(h2));
    __nv_bfloat16 l3 = __float2bfloat16(x.w - __bfloat162float(h3));
    __nv_bfloat162 ph0; ph0.x = h0; ph0.y = h1;
    __nv_bfloat162 ph1; ph1.x = h2; ph1.y = h3;
    __nv_bfloat162 pl0; pl0.x = l0; pl0.y = l1;
    __nv_bfloat162 pl1; pl1.x = l2; pl1.y = l3;
    ((__nv_bfloat162*)Xh)[2*i]   = ph0;
    ((__nv_bfloat162*)Xh)[2*i+1] = ph1;
    ((__nv_bfloat162*)Xl)[2*i]   = pl0;
    ((__nv_bfloat162*)Xl)[2*i+1] = pl1;
}

// ---------------------------------------------------------------------------
// W [K,N] fp32 -> transposed Wt [N,K] bf16 hi/lo
// ---------------------------------------------------------------------------
__global__ __launch_bounds__(256) void convert_wT_kernel(
    const float* __restrict__ W, __nv_bfloat16* __restrict__ Wth,
    __nv_bfloat16* __restrict__ Wtl)
{
    __shared__ float t[32][33];
    int tx = threadIdx.x, ty = threadIdx.y;           // (32, 8)
    int n0 = blockIdx.x * 32, k0 = blockIdx.y * 32;
    #pragma unroll
    for (int i = 0; i < 4; i++)
        t[ty + 8*i][tx] = W[(size_t)(k0 + ty + 8*i) * D_ + n0 + tx];
    __syncthreads();
    #pragma unroll
    for (int i = 0; i < 4; i++) {
        float v = t[tx][ty + 8*i];
        __nv_bfloat16 h = __float2bfloat16(v);
        __nv_bfloat16 l = __float2bfloat16(v - __bfloat162float(h));
        size_t o = (size_t)(n0 + ty + 8*i) * D_ + k0 + tx;
        Wth[o] = h; Wtl[o] = l;
    }
}

// ---------------------------------------------------------------------------
// mma.sync GEMM: Y[M,N] = X @ W + bias via 3-term bf16 split.
// CTA 128x128, 8 warps (warp tile 32x64), BK=32, cp.async double buffer.
// smem tile: 128 rows x 32 bf16, pitch 40 bf16 (80B) -> conflict-free ldmatrix.
// Buffer layout per buf: Ah@0, Al@10240, Bh@20480, Bl@30720 (40960B/buf).
// ---------------------------------------------------------------------------
#define GP 80                       // row pitch, bytes
#define TILE_BYTES 10240            // 128 * 80
#define BUF_BYTES  40960
#define G_SMEM_TOTAL (2 * BUF_BYTES)

template<bool SPLIT>
__global__ __launch_bounds__(256) void gemm_mma_kernel(
    const __nv_bfloat16* __restrict__ Ah, const __nv_bfloat16* __restrict__ Al,
    const __nv_bfloat16* __restrict__ Bh, const __nv_bfloat16* __restrict__ Bl,
    const float* __restrict__ bias, float* __restrict__ Y)
{
    extern __shared__ char smem[];
    uint32_t sb = smem_u32(smem);

    int tid = threadIdx.x, wid = tid >> 5, lid = tid & 31;
    int m0 = blockIdx.y * 128, n0 = blockIdx.x * 128;
    int wm = (wid >> 1) * 32, wn = (wid & 1) * 64;

    const __nv_bfloat16* srcs[4] = {Ah, Al, Bh, Bl};
    const int rb0 = m0, rb1 = m0, rb2 = n0, rb3 = n0;
    const int rbase[4] = {rb0, rb1, rb2, rb3};

    // per-thread load slots: 8 x 16B per chunk
    int slot_tile[8], slot_r[8], slot_q[8];
    #pragma unroll
    for (int it = 0; it < 8; it++) {
        int j = tid + it * 256;
        slot_tile[it] = j >> 9;
        int rem = j & 511;
        slot_r[it] = rem >> 2;
        slot_q[it] = rem & 3;
    }

    float acc[2][8][4];
    #pragma unroll
    for (int mt = 0; mt < 2; mt++)
        #pragma unroll
        for (int nt = 0; nt < 8; nt++)
            #pragma unroll
            for (int c = 0; c < 4; c++) acc[mt][nt][c] = 0.f;

    // prefetch chunk 0 -> buf 0
    #pragma unroll
    for (int it = 0; it < 8; it++) {
        uint32_t dst = sb + slot_tile[it] * TILE_BYTES + slot_r[it] * GP + slot_q[it] * 16;
        const __nv_bfloat16* src = srcs[slot_tile[it]] +
            (size_t)(rbase[slot_tile[it]] + slot_r[it]) * D_ + slot_q[it] * 8;
        CP_ASYNC16(dst, src);
    }
    CP_COMMIT();

    for (int kc = 0; kc < 32; kc++) {
        int buf = kc & 1;
        uint32_t bufb = sb + buf * BUF_BYTES;
        if (kc + 1 < 32) {
            uint32_t ob = sb + (buf ^ 1) * BUF_BYTES;
            #pragma unroll
            for (int it = 0; it < 8; it++) {
                uint32_t dst = ob + slot_tile[it] * TILE_BYTES + slot_r[it] * GP + slot_q[it] * 16;
                const __nv_bfloat16* src = srcs[slot_tile[it]] +
                    (size_t)(rbase[slot_tile[it]] + slot_r[it]) * D_ + (kc + 1) * 32 + slot_q[it] * 8;
                CP_ASYNC16(dst, src);
            }
            CP_COMMIT();
            CP_WAIT1();
        } else {
            CP_WAIT0();
        }
        __syncthreads();

        #pragma unroll
        for (int ks = 0; ks < 2; ks++) {
            // A fragments (Ah, Al) for 2 m-tiles
            uint32_t ah[2][4], al[2][4];
            #pragma unroll
            for (int mt = 0; mt < 2; mt++) {
                uint32_t ra = (uint32_t)(wm + mt * 16 + (lid & 15)) * GP +
                              ks * 32 + (lid >> 4) * 16;
                ldsm_x4(ah[mt], bufb + 0 * TILE_BYTES + ra);
                ldsm_x4(al[mt], bufb + 1 * TILE_BYTES + ra);
            }
            #pragma unroll
            for (int nt = 0; nt < 8; nt++) {
                uint32_t rbadr = (uint32_t)(wn + nt * 8 + (lid & 7)) * GP +
                                 ks * 32 + ((lid >> 3) & 1) * 16;
                uint32_t bh[2], bl[2];
                ldsm_x2(bh, bufb + 2 * TILE_BYTES + rbadr);
                ldsm_x2(bl, bufb + 3 * TILE_BYTES + rbadr);
                #pragma unroll
                for (int mt = 0; mt < 2; mt++) {
                    mma16816(acc[mt][nt], ah[mt], bh);
                    mma16816(acc[mt][nt], al[mt], bh);
                    mma16816(acc[mt][nt], ah[mt], bl);
                }
            }
        }
        __syncthreads();
    }

    // epilogue: lane (l) owns rows l/4, l/4+8; cols (l%4)*2, +1 of each 16x8 tile
    #pragma unroll
    for (int mt = 0; mt < 2; mt++) {
        #pragma unroll
        for (int nt = 0; nt < 8; nt++) {
            int mA = m0 + wm + mt * 16 + (lid >> 2);
            int nA = n0 + wn + nt * 8 + (lid & 3) * 2;
            float b0 = bias[nA], b1 = bias[nA + 1];
            float2 r0 = make_float2(acc[mt][nt][0] + b0, acc[mt][nt][1] + b1);
            float2 r1 = make_float2(acc[mt][nt][2] + b0, acc[mt][nt][3] + b1);
            if (SPLIT) {
                int h = nA >> 6, hd = nA & 63;
                int b = mA >> 11, s = mA & (S_ - 1);
                size_t base0 = (((size_t)(b * H_ + h)) * S_ + s) * HD_ + hd;
                *(float2*)(Y + base0) = r0;
                size_t base1 = (((size_t)(b * H_ + h)) * S_ + (s + 8)) * HD_ + hd;
                *(float2*)(Y + base1) = r1;
            } else {
                *(float2*)(Y + (size_t)mA * D_ + nA) = r0;
                *(float2*)(Y + (size_t)(mA + 8) * D_ + nA) = r1;
            }
        }
    }
}

// ---------------------------------------------------------------------------
// Flash attention (unchanged): f32x2 scalar path.
// ---------------------------------------------------------------------------
__global__ __launch_bounds__(256) void flash_kernel(
    const float* __restrict__ gq, const float* __restrict__ gk,
    const float* __restrict__ gv, float* __restrict__ ctx)
{
    extern __shared__ float sm[];
    float* Qs = sm;
    float* Kt = Qs + 64 * 68;
    float* Vs = Kt + 64 * 68;
    float* Ps = Vs + 64 * 64;

    int tid = threadIdx.x;
    int tx = tid & 15, ty = tid >> 4;
    int qt = blockIdx.x, h = blockIdx.y, b = blockIdx.z;

    const size_t bh = (size_t)(b * H_ + h);
    const float* qb = gq + (bh * S_ + (size_t)qt * 64) * HD_;
    const float* kb = gk + bh * S_ * HD_;
    const float* vb = gv + bh * S_ * HD_;

    for (int e = tid * 4; e < 64 * 64; e += 256 * 4) {
        int rr = e >> 6, dd = e & 63;
        float4 t = *(const float4*)(qb + rr * 64 + dd);
        t.x *= 0.125f; t.y *= 0.125f; t.z *= 0.125f; t.w *= 0.125f;
        *(float4*)(Qs + rr * 68 + dd) = t;
    }

    float m_[4], l_[4];
    u64t o2[4][2];
    #pragma unroll
    for (int i = 0; i < 4; i++) {
        m_[i] = -1e30f; l_[i] = 0.f;
        o2[i][0] = 0ULL; o2[i][1] = 0ULL;
    }

    for (int kt = 0; kt < S_ / 64; kt++) {
        __syncthreads();
        const float* kp = kb + (size_t)kt * 64 * 64;
        const float* vp = vb + (size_t)kt * 64 * 64;
        for (int e = tid * 4; e < 4096; e += 1024)
            *(float4*)(Vs + e) = *(const float4*)(vp + e);
        for (int e = tid; e < 4096; e += 256) {
            int cc = e >> 6, dd = e & 63;
            Kt[dd * 68 + cc] = kp[e];
        }
        __syncthreads();

        u64t s2[4][2];
        #pragma unroll
        for (int i = 0; i < 4; i++) { s2[i][0] = 0ULL; s2[i][1] = 0ULL; }

        #pragma unroll 4
        for (int d = 0; d < 64; d++) {
            ulonglong2 kv = *(const ulonglong2*)(Kt + d * 68 + tx * 4);
            #pragma unroll
            for (int i = 0; i < 4; i++) {
                u64t q2 = bcast2(Qs[(ty * 4 + i) * 68 + d]);
                s2[i][0] = fma2(q2, kv.x, s2[i][0]);
                s2[i][1] = fma2(q2, kv.y, s2[i][1]);
            }
        }

        #pragma unroll
        for (int i = 0; i < 4; i++) {
            float2 e0 = upk2(s2[i][0]), e1 = upk2(s2[i][1]);
            float mx = fmaxf(fmaxf(e0.x, e0.y), fmaxf(e1.x, e1.y));
            mx = fmaxf(mx, __shfl_xor_sync(0xffffffffu, mx, 1));
            mx = fmaxf(mx, __shfl_xor_sync(0xffffffffu, mx, 2));
            mx = fmaxf(mx, __shfl_xor_sync(0xffffffffu, mx, 4));
            mx = fmaxf(mx, __shfl_xor_sync(0xffffffffu, mx, 8));
            float mn = fmaxf(m_[i], mx);
            float corr = __expf(m_[i] - mn);
            m_[i] = mn;
            e0.x = __expf(e0.x - mn); e0.y = __expf(e0.y - mn);
            e1.x = __expf(e1.x - mn); e1.y = __expf(e1.y - mn);
            float ls = (e0.x + e0.y) + (e1.x + e1.y);
            ls += __shfl_xor_sync(0xffffffffu, ls, 1);
            ls += __shfl_xor_sync(0xffffffffu, ls, 2);
            ls += __shfl_xor_sync(0xffffffffu, ls, 4);
            ls += __shfl_xor_sync(0xffffffffu, ls, 8);
            l_[i] = l_[i] * corr + ls;
            u64t c2 = bcast2(corr);
            o2[i][0] = mul2(o2[i][0], c2);
            o2[i][1] = mul2(o2[i][1], c2);
            ulonglong2 pw;
            pw.x = pk2(e0.x, e0.y);
            pw.y = pk2(e1.x, e1.y);
            *(ulonglong2*)(Ps + (ty * 4 + i) * 68 + tx * 4) = pw;
        }
        __syncthreads();

        #pragma unroll 4
        for (int c = 0; c < 64; c++) {
            ulonglong2 vv = *(const ulonglong2*)(Vs + c * 64 + tx * 4);
            #pragma unroll
            for (int i = 0; i < 4; i++) {
                u64t p2 = bcast2(Ps[(ty * 4 + i) * 68 + c]);
                o2[i][0] = fma2(p2, vv.x, o2[i][0]);
                o2[i][1] = fma2(p2, vv.y, o2[i][1]);
            }
        }
    }

    #pragma unroll
    for (int i = 0; i < 4; i++) {
        float inv = 1.0f / l_[i];
        int row = qt * 64 + ty * 4 + i;
        float2 a = upk2(o2[i][0]), c = upk2(o2[i][1]);
        float4 r = make_float4(a.x * inv, a.y * inv, c.x * inv, c.y * inv);
        *(float4*)(ctx + ((size_t)b * S_ + row) * D_ + h * 64 + tx * 4) = r;
    }
}

// ---------------------------------------------------------------------------
extern "C" void kernel_launch(void* const* d_in, const int* in_sizes, int n_in,
                              void* d_out, int out_size)
{
    const float* xq = (const float*)d_in[0];
    const float* xk = (const float*)d_in[1];
    const float* xv = (const float*)d_in[2];
    const float* Wq = (const float*)d_in[3];
    const float* bq = (const float*)d_in[4];
    const float* Wk = (const float*)d_in[5];
    const float* bk = (const float*)d_in[6];
    const float* Wv = (const float*)d_in[7];
    const float* bv = (const float*)d_in[8];
    const float* Wo = (const float*)d_in[9];
    const float* bo = (const float*)d_in[10];
    float* out = (float*)d_out;

    float *q, *k, *v, *ctx;
    __nv_bfloat16 *xh, *xl, *wh, *wl;
    cudaGetSymbolAddress((void**)&q,   g_q);
    cudaGetSymbolAddress((void**)&k,   g_k);
    cudaGetSymbolAddress((void**)&v,   g_v);
    cudaGetSymbolAddress((void**)&ctx, g_ctx);
    cudaGetSymbolAddress((void**)&xh,  g_xh);
    cudaGetSymbolAddress((void**)&xl,  g_xl);
    cudaGetSymbolAddress((void**)&wh,  g_wh);
    cudaGetSymbolAddress((void**)&wl,  g_wl);

    static bool attr_done = false;
    if (!attr_done) {
        cudaFuncSetAttribute(flash_kernel,
                             cudaFuncAttributeMaxDynamicSharedMemorySize,
                             (64*68*3 + 64*64) * 4);
        cudaFuncSetAttribute(gemm_mma_kernel<true>,
                             cudaFuncAttributeMaxDynamicSharedMemorySize, G_SMEM_TOTAL);
        cudaFuncSetAttribute(gemm_mma_kernel<false>,
                             cudaFuncAttributeMaxDynamicSharedMemorySize, G_SMEM_TOTAL);
        attr_done = true;
    }

    dim3 cgrid(4096, 1), cblk(256, 1);
    dim3 wgrid(32, 32), wblk(32, 8);
    dim3 ggrid(D_ / 128, M_ / 128);                    // (8, 32)

    // Q projection
    convert_hl_kernel<<<cgrid, cblk>>>(xq, xh, xl);
    convert_wT_kernel<<<wgrid, wblk>>>(Wq, wh, wl);
    gemm_mma_kernel<true><<<ggrid, 256, G_SMEM_TOTAL>>>(xh, xl, wh, wl, bq, q);
    // K projection
    convert_hl_kernel<<<cgrid, cblk>>>(xk, xh, xl);
    convert_wT_kernel<<<wgrid, wblk>>>(Wk, wh, wl);
    gemm_mma_kernel<true><<<ggrid, 256, G_SMEM_TOTAL>>>(xh, xl, wh, wl, bk, k);
    // V projection
    convert_hl_kernel<<<cgrid, cblk>>>(xv, xh, xl);
    convert_wT_kernel<<<wgrid, wblk>>>(Wv, wh, wl);
    gemm_mma_kernel<true><<<ggrid, 256, G_SMEM_TOTAL>>>(xh, xl, wh, wl, bv, v);

    // Attention
    flash_kernel<<<dim3(S_ / 64, H_, B_), 256, (64*68*3 + 64*64) * 4>>>(q, k, v, ctx);

    // Output projection
    convert_hl_kernel<<<cgrid, cblk>>>(ctx, xh, xl);
    convert_wT_kernel<<<wgrid, wblk>>>(Wo, wh, wl);
    gemm_mma_kernel<false><<<ggrid, 256, G_SMEM_TOTAL>>>(xh, xl, wh, wl, bo, out);
}

// round 6
// speedup vs baseline: 2.7202x; 1.8030x over previous
#include <cuda_runtime.h>
#include <cuda_bf16.h>
#include <cstdint>
#include <math.h>

#define B_  2
#define S_  2048
#define D_  1024
#define H_  16
#define HD_ 64
#define M_  (B_*S_)   // 4096

typedef __nv_bfloat16 bf16;
typedef __nv_bfloat162 bf162;

// ---------------- scratch (__device__ globals; no allocs allowed) ----------
__device__ bf16 g_qh[(size_t)M_*D_];
__device__ bf16 g_ql[(size_t)M_*D_];
__device__ bf16 g_kh[(size_t)M_*D_];
__device__ bf16 g_kl[(size_t)M_*D_];
__device__ bf16 g_vth[(size_t)M_*D_];   // [B,H,HD,S]
__device__ bf16 g_vtl[(size_t)M_*D_];
__device__ bf16 g_ctxh[(size_t)M_*D_];  // [B,S,D]
__device__ bf16 g_ctxl[(size_t)M_*D_];
__device__ bf16 g_xh[(size_t)M_*D_];
__device__ bf16 g_xl[(size_t)M_*D_];
__device__ bf16 g_wh[(size_t)D_*D_];
__device__ bf16 g_wl[(size_t)D_*D_];

// ---------------- helpers ---------------------------------------------------
__device__ __forceinline__ uint32_t smem_u32(const void* p) {
    uint32_t a;
    asm("{ .reg .u64 t; cvta.to.shared.u64 t, %1; cvt.u32.u64 %0, t; }" : "=r"(a) : "l"(p));
    return a;
}
__device__ __forceinline__ void ldsm_x4(uint32_t* r, uint32_t addr) {
    asm volatile("ldmatrix.sync.aligned.m8n8.x4.shared.b16 {%0,%1,%2,%3}, [%4];"
                 : "=r"(r[0]), "=r"(r[1]), "=r"(r[2]), "=r"(r[3]) : "r"(addr));
}
__device__ __forceinline__ void ldsm_x2(uint32_t* r, uint32_t addr) {
    asm volatile("ldmatrix.sync.aligned.m8n8.x2.shared.b16 {%0,%1}, [%2];"
                 : "=r"(r[0]), "=r"(r[1]) : "r"(addr));
}
__device__ __forceinline__ void mma16816(float* d, const uint32_t* a,
                                         const uint32_t* b) {
    asm volatile("mma.sync.aligned.m16n8k16.row.col.f32.bf16.bf16.f32 "
        "{%0,%1,%2,%3}, {%4,%5,%6,%7}, {%8,%9}, {%0,%1,%2,%3};"
        : "+f"(d[0]), "+f"(d[1]), "+f"(d[2]), "+f"(d[3])
        : "r"(a[0]), "r"(a[1]), "r"(a[2]), "r"(a[3]), "r"(b[0]), "r"(b[1]));
}
#define CP_ASYNC16(dst, src) \
    asm volatile("cp.async.cg.shared.global [%0], [%1], 16;" :: "r"(dst), "l"(src))
#define CP_COMMIT() asm volatile("cp.async.commit_group;" ::: "memory")
#define CP_WAIT1()  asm volatile("cp.async.wait_group 1;" ::: "memory")
#define CP_WAIT0()  asm volatile("cp.async.wait_group 0;" ::: "memory")

__device__ __forceinline__ void split_store(bf16* Yh, bf16* Yl, size_t idx, float v) {
    bf16 h = __float2bfloat16(v);
    Yh[idx] = h;
    Yl[idx] = __float2bfloat16(v - __bfloat162float(h));
}
__device__ __forceinline__ bf162 mk2(float a, float b) {
    bf162 r; r.x = __float2bfloat16(a); r.y = __float2bfloat16(b); return r;
}

// ---------------------------------------------------------------------------
// fp32 -> bf16 hi/lo split (elementwise, float4 granularity)
// ---------------------------------------------------------------------------
__global__ __launch_bounds__(256) void convert_hl_kernel(
    const float* __restrict__ X, bf16* __restrict__ Xh, bf16* __restrict__ Xl)
{
    int i = blockIdx.x * blockDim.x + threadIdx.x;   // float4 index
    float4 x = ((const float4*)X)[i];
    bf16 h0 = __float2bfloat16(x.x), h1 = __float2bfloat16(x.y);
    bf16 h2 = __float2bfloat16(x.z), h3 = __float2bfloat16(x.w);
    bf16 l0 = __float2bfloat16(x.x - __bfloat162float(h0));
    bf16 l1 = __float2bfloat16(x.y - __bfloat162float(h1));
    bf16 l2 = __float2bfloat16(x.z - __bfloat162float(h2));
    bf16 l3 = __float2bfloat16(x.w - __bfloat162float(h3));
    bf162 ph0; ph0.x = h0; ph0.y = h1;
    bf162 ph1; ph1.x = h2; ph1.y = h3;
    bf162 pl0; pl0.x = l0; pl0.y = l1;
    bf162 pl1; pl1.x = l2; pl1.y = l3;
    ((bf162*)Xh)[2*i]   = ph0;
    ((bf162*)Xh)[2*i+1] = ph1;
    ((bf162*)Xl)[2*i]   = pl0;
    ((bf162*)Xl)[2*i+1] = pl1;
}

// ---------------------------------------------------------------------------
// W [K,N] fp32 -> transposed Wt [N,K] bf16 hi/lo
// ---------------------------------------------------------------------------
__global__ __launch_bounds__(256) void convert_wT_kernel(
    const float* __restrict__ W, bf16* __restrict__ Wth, bf16* __restrict__ Wtl)
{
    __shared__ float t[32][33];
    int tx = threadIdx.x, ty = threadIdx.y;           // (32, 8)
    int n0 = blockIdx.x * 32, k0 = blockIdx.y * 32;
    #pragma unroll
    for (int i = 0; i < 4; i++)
        t[ty + 8*i][tx] = W[(size_t)(k0 + ty + 8*i) * D_ + n0 + tx];
    __syncthreads();
    #pragma unroll
    for (int i = 0; i < 4; i++) {
        float v = t[tx][ty + 8*i];
        split_store(Wth, Wtl, (size_t)(n0 + ty + 8*i) * D_ + k0 + tx, v);
    }
}

// ---------------------------------------------------------------------------
// mma.sync GEMM: Y[M,N] = (X @ W + bias) * scale via 3-term bf16 split.
// CTA 128x128, 8 warps (warp tile 32x64), BK=32, cp.async double buffer.
// MODE 0: fp32 row-major out. MODE 1: bf16 hi/lo [B,H,S,HD]. MODE 2: bf16 hi/lo
// transposed [B,H,HD,S] (for V).
// ---------------------------------------------------------------------------
#define GP 80                       // row pitch, bytes
#define TILE_BYTES 10240            // 128 * 80
#define BUF_BYTES  40960
#define G_SMEM_TOTAL (2 * BUF_BYTES)

template<int MODE>
__global__ __launch_bounds__(256) void gemm_mma_kernel(
    const bf16* __restrict__ Ah, const bf16* __restrict__ Al,
    const bf16* __restrict__ Bh, const bf16* __restrict__ Bl,
    const float* __restrict__ bias, float scale,
    void* __restrict__ Y0, void* __restrict__ Y1)
{
    extern __shared__ char smem[];
    uint32_t sb = smem_u32(smem);

    int tid = threadIdx.x, wid = tid >> 5, lid = tid & 31;
    int m0 = blockIdx.y * 128, n0 = blockIdx.x * 128;
    int wm = (wid >> 1) * 32, wn = (wid & 1) * 64;

    const bf16* srcs[4] = {Ah, Al, Bh, Bl};
    const int rbase[4] = {m0, m0, n0, n0};

    int slot_tile[8], slot_r[8], slot_q[8];
    #pragma unroll
    for (int it = 0; it < 8; it++) {
        int j = tid + it * 256;
        slot_tile[it] = j >> 9;
        int rem = j & 511;
        slot_r[it] = rem >> 2;
        slot_q[it] = rem & 3;
    }

    float acc[2][8][4];
    #pragma unroll
    for (int mt = 0; mt < 2; mt++)
        #pragma unroll
        for (int nt = 0; nt < 8; nt++)
            #pragma unroll
            for (int c = 0; c < 4; c++) acc[mt][nt][c] = 0.f;

    #pragma unroll
    for (int it = 0; it < 8; it++) {
        uint32_t dst = sb + slot_tile[it] * TILE_BYTES + slot_r[it] * GP + slot_q[it] * 16;
        const bf16* src = srcs[slot_tile[it]] +
            (size_t)(rbase[slot_tile[it]] + slot_r[it]) * D_ + slot_q[it] * 8;
        CP_ASYNC16(dst, src);
    }
    CP_COMMIT();

    for (int kc = 0; kc < 32; kc++) {
        int buf = kc & 1;
        uint32_t bufb = sb + buf * BUF_BYTES;
        if (kc + 1 < 32) {
            uint32_t ob = sb + (buf ^ 1) * BUF_BYTES;
            #pragma unroll
            for (int it = 0; it < 8; it++) {
                uint32_t dst = ob + slot_tile[it] * TILE_BYTES + slot_r[it] * GP + slot_q[it] * 16;
                const bf16* src = srcs[slot_tile[it]] +
                    (size_t)(rbase[slot_tile[it]] + slot_r[it]) * D_ + (kc + 1) * 32 + slot_q[it] * 8;
                CP_ASYNC16(dst, src);
            }
            CP_COMMIT();
            CP_WAIT1();
        } else {
            CP_WAIT0();
        }
        __syncthreads();

        #pragma unroll
        for (int ks = 0; ks < 2; ks++) {
            uint32_t ah[2][4], al[2][4];
            #pragma unroll
            for (int mt = 0; mt < 2; mt++) {
                uint32_t ra = (uint32_t)(wm + mt * 16 + (lid & 15)) * GP +
                              ks * 32 + (lid >> 4) * 16;
                ldsm_x4(ah[mt], bufb + 0 * TILE_BYTES + ra);
                ldsm_x4(al[mt], bufb + 1 * TILE_BYTES + ra);
            }
            #pragma unroll
            for (int nt = 0; nt < 8; nt++) {
                uint32_t rbadr = (uint32_t)(wn + nt * 8 + (lid & 7)) * GP +
                                 ks * 32 + ((lid >> 3) & 1) * 16;
                uint32_t bh[2], bl[2];
                ldsm_x2(bh, bufb + 2 * TILE_BYTES + rbadr);
                ldsm_x2(bl, bufb + 3 * TILE_BYTES + rbadr);
                #pragma unroll
                for (int mt = 0; mt < 2; mt++) {
                    mma16816(acc[mt][nt], ah[mt], bh);
                    mma16816(acc[mt][nt], al[mt], bh);
                    mma16816(acc[mt][nt], ah[mt], bl);
                }
            }
        }
        __syncthreads();
    }

    #pragma unroll
    for (int mt = 0; mt < 2; mt++) {
        #pragma unroll
        for (int nt = 0; nt < 8; nt++) {
            int mA = m0 + wm + mt * 16 + (lid >> 2);
            int nA = n0 + wn + nt * 8 + (lid & 3) * 2;
            float b0 = bias[nA], b1 = bias[nA + 1];
            float v0 = (acc[mt][nt][0] + b0) * scale;
            float v1 = (acc[mt][nt][1] + b1) * scale;
            float v2 = (acc[mt][nt][2] + b0) * scale;
            float v3 = (acc[mt][nt][3] + b1) * scale;
            if (MODE == 0) {
                float* Y = (float*)Y0;
                *(float2*)(Y + (size_t)mA * D_ + nA) = make_float2(v0, v1);
                *(float2*)(Y + (size_t)(mA + 8) * D_ + nA) = make_float2(v2, v3);
            } else if (MODE == 1) {
                bf16* Yh = (bf16*)Y0; bf16* Yl = (bf16*)Y1;
                int h = nA >> 6, hd = nA & 63;
                int b = mA >> 11, s = mA & (S_ - 1);
                size_t base0 = (((size_t)(b * H_ + h)) * S_ + s) * HD_ + hd;
                size_t base1 = (((size_t)(b * H_ + h)) * S_ + (s + 8)) * HD_ + hd;
                *(bf162*)(Yh + base0) = mk2(v0, v1);
                *(bf162*)(Yh + base1) = mk2(v2, v3);
                *(bf162*)(Yl + base0) = mk2(v0 - __bfloat162float(__float2bfloat16(v0)),
                                            v1 - __bfloat162float(__float2bfloat16(v1)));
                *(bf162*)(Yl + base1) = mk2(v2 - __bfloat162float(__float2bfloat16(v2)),
                                            v3 - __bfloat162float(__float2bfloat16(v3)));
            } else {
                bf16* Yh = (bf16*)Y0; bf16* Yl = (bf16*)Y1;
                int h = nA >> 6, hd = nA & 63;
                int b = mA >> 11, s = mA & (S_ - 1);
                size_t rb = (size_t)(b * H_ + h) * HD_;
                split_store(Yh, Yl, (rb + hd)     * S_ + s,     v0);
                split_store(Yh, Yl, (rb + hd + 1) * S_ + s,     v1);
                split_store(Yh, Yl, (rb + hd)     * S_ + s + 8, v2);
                split_store(Yh, Yl, (rb + hd + 1) * S_ + s + 8, v3);
            }
        }
    }
}

// ---------------------------------------------------------------------------
// Flash attention via mma.sync. CTA = 128 q-rows x (b,h). 8 warps x 16 rows.
// kv tiles of 64, double-buffered cp.async. 3-term bf16 split on both MMAs.
// smem pitch 144B (9x16B -> conflict-free ldmatrix).
// Layout: Qh@0, Ql@18432 | KVbuf0@36864 (Kh,Kl,Vh,Vl x 9216) | KVbuf1@73728
//         Ph@110592, Pl@129024. Total 147456.
// ---------------------------------------------------------------------------
#define FQH 0
#define FQL 18432
#define FKV 36864
#define FKVB 36864
#define FPH 110592
#define FPL 129024
#define F_SMEM_TOTAL 147456

__device__ __forceinline__ void flash_issue_kv(
    uint32_t sb, int buf, int kt, size_t bh, int tid,
    const bf16* kh, const bf16* kl, const bf16* vth, const bf16* vtl)
{
    #pragma unroll
    for (int it = 0; it < 8; it++) {
        int j = tid + it * 256;
        int sub = j >> 9, rem = j & 511, r = rem >> 3, c = rem & 7;
        uint32_t dst = sb + FKV + buf * FKVB + sub * 9216 + r * 144 + c * 16;
        const bf16* src;
        if (sub == 0)      src = kh  + (bh * S_ + (size_t)kt * 64 + r) * HD_ + c * 8;
        else if (sub == 1) src = kl  + (bh * S_ + (size_t)kt * 64 + r) * HD_ + c * 8;
        else if (sub == 2) src = vth + (bh * HD_ + r) * S_ + kt * 64 + c * 8;
        else               src = vtl + (bh * HD_ + r) * S_ + kt * 64 + c * 8;
        CP_ASYNC16(dst, src);
    }
    CP_COMMIT();
}

__global__ __launch_bounds__(256) void flash_mma_kernel(
    const bf16* __restrict__ qh, const bf16* __restrict__ ql,
    const bf16* __restrict__ kh, const bf16* __restrict__ kl,
    const bf16* __restrict__ vth, const bf16* __restrict__ vtl,
    bf16* __restrict__ ctxh, bf16* __restrict__ ctxl)
{
    extern __shared__ char smem[];
    uint32_t sb = smem_u32(smem);

    int tid = threadIdx.x, wid = tid >> 5, lid = tid & 31;
    int qblk = blockIdx.x, h = blockIdx.y, b = blockIdx.z;
    size_t bh = (size_t)(b * H_ + h);
    int mw = wid * 16;

    // Q load: 2048 16B chunks (Qh then Ql), rows = 128
    #pragma unroll
    for (int it = 0; it < 8; it++) {
        int j = tid + it * 256;
        int sub = j >> 10, rem = j & 1023, r = rem >> 3, c = rem & 7;
        uint32_t dst = sb + sub * 18432 + r * 144 + c * 16;
        const bf16* src = (sub ? ql : qh) +
            (bh * S_ + (size_t)qblk * 128 + r) * HD_ + c * 8;
        CP_ASYNC16(dst, src);
    }
    CP_COMMIT();
    flash_issue_kv(sb, 0, 0, bh, tid, kh, kl, vth, vtl);

    float m0 = -1e30f, m1 = -1e30f, l0 = 0.f, l1 = 0.f;
    float oacc[8][4];
    #pragma unroll
    for (int nt = 0; nt < 8; nt++)
        #pragma unroll
        for (int c = 0; c < 4; c++) oacc[nt][c] = 0.f;

    for (int kt = 0; kt < S_ / 64; kt++) {
        int buf = kt & 1;
        if (kt + 1 < S_ / 64) {
            flash_issue_kv(sb, (kt + 1) & 1, kt + 1, bh, tid, kh, kl, vth, vtl);
            CP_WAIT1();
        } else {
            CP_WAIT0();
        }
        __syncthreads();
        uint32_t kvb = sb + FKV + buf * FKVB;

        // ---- S = Q K^T (3-term split), warp rows mw..mw+15, kv cols 0..63
        float sacc[8][4];
        #pragma unroll
        for (int nt = 0; nt < 8; nt++)
            #pragma unroll
            for (int c = 0; c < 4; c++) sacc[nt][c] = 0.f;

        #pragma unroll
        for (int ks = 0; ks < 4; ks++) {
            uint32_t ah[4], al[4];
            uint32_t ra = sb + FQH + (uint32_t)(mw + (lid & 15)) * 144 +
                          ks * 32 + (lid >> 4) * 16;
            ldsm_x4(ah, ra);
            ldsm_x4(al, ra + (FQL - FQH));
            #pragma unroll
            for (int nt = 0; nt < 8; nt++) {
                uint32_t rbadr = kvb + (uint32_t)(nt * 8 + (lid & 7)) * 144 +
                                 ks * 32 + ((lid >> 3) & 1) * 16;
                uint32_t bkh[2], bkl[2];
                ldsm_x2(bkh, rbadr);
                ldsm_x2(bkl, rbadr + 9216);
                mma16816(sacc[nt], ah, bkh);
                mma16816(sacc[nt], al, bkh);
                mma16816(sacc[nt], ah, bkl);
            }
        }

        // ---- online softmax. regs [0,1] -> row r0 = mw + lid/4; [2,3] -> r0+8
        float mx0 = -1e30f, mx1 = -1e30f;
        #pragma unroll
        for (int nt = 0; nt < 8; nt++) {
            mx0 = fmaxf(mx0, fmaxf(sacc[nt][0], sacc[nt][1]));
            mx1 = fmaxf(mx1, fmaxf(sacc[nt][2], sacc[nt][3]));
        }
        mx0 = fmaxf(mx0, __shfl_xor_sync(0xffffffffu, mx0, 1));
        mx0 = fmaxf(mx0, __shfl_xor_sync(0xffffffffu, mx0, 2));
        mx1 = fmaxf(mx1, __shfl_xor_sync(0xffffffffu, mx1, 1));
        mx1 = fmaxf(mx1, __shfl_xor_sync(0xffffffffu, mx1, 2));
        float mn0 = fmaxf(m0, mx0), mn1 = fmaxf(m1, mx1);
        float corr0 = __expf(m0 - mn0), corr1 = __expf(m1 - mn1);
        m0 = mn0; m1 = mn1;

        int r0 = mw + (lid >> 2);
        uint32_t pcol = (uint32_t)((lid & 3) * 2) * 2;  // byte offset of col pair
        float sum0 = 0.f, sum1 = 0.f;
        #pragma unroll
        for (int nt = 0; nt < 8; nt++) {
            float p00 = __expf(sacc[nt][0] - mn0);
            float p01 = __expf(sacc[nt][1] - mn0);
            float p10 = __expf(sacc[nt][2] - mn1);
            float p11 = __expf(sacc[nt][3] - mn1);
            sum0 += p00 + p01; sum1 += p10 + p11;
            uint32_t off0 = (uint32_t)r0 * 144 + nt * 16 + pcol;
            bf162 h0 = mk2(p00, p01), h1 = mk2(p10, p11);
            *(bf162*)(smem + FPH + off0) = h0;
            *(bf162*)(smem + FPH + off0 + 8 * 144) = h1;
            *(bf162*)(smem + FPL + off0) =
                mk2(p00 - __bfloat162float(h0.x), p01 - __bfloat162float(h0.y));
            *(bf162*)(smem + FPL + off0 + 8 * 144) =
                mk2(p10 - __bfloat162float(h1.x), p11 - __bfloat162float(h1.y));
        }
        sum0 += __shfl_xor_sync(0xffffffffu, sum0, 1);
        sum0 += __shfl_xor_sync(0xffffffffu, sum0, 2);
        sum1 += __shfl_xor_sync(0xffffffffu, sum1, 1);
        sum1 += __shfl_xor_sync(0xffffffffu, sum1, 2);
        l0 = l0 * corr0 + sum0;
        l1 = l1 * corr1 + sum1;
        #pragma unroll
        for (int nt = 0; nt < 8; nt++) {
            oacc[nt][0] *= corr0; oacc[nt][1] *= corr0;
            oacc[nt][2] *= corr1; oacc[nt][3] *= corr1;
        }
        __syncwarp();

        // ---- O += P V  (A = P rows, B = Vt [hd rows][kv cols], 3-term split)
        #pragma unroll
        for (int ks = 0; ks < 4; ks++) {
            uint32_t ap[4], apl[4];
            uint32_t ra = sb + FPH + (uint32_t)(mw + (lid & 15)) * 144 +
                          ks * 32 + (lid >> 4) * 16;
            ldsm_x4(ap, ra);
            ldsm_x4(apl, ra + (FPL - FPH));
            #pragma unroll
            for (int nt = 0; nt < 8; nt++) {
                uint32_t rbadr = kvb + 18432 + (uint32_t)(nt * 8 + (lid & 7)) * 144 +
                                 ks * 32 + ((lid >> 3) & 1) * 16;
                uint32_t bvh[2], bvl[2];
                ldsm_x2(bvh, rbadr);
                ldsm_x2(bvl, rbadr + 9216);
                mma16816(oacc[nt], ap, bvh);
                mma16816(oacc[nt], apl, bvh);
                mma16816(oacc[nt], ap, bvl);
            }
        }
        __syncthreads();
    }

    // ---- epilogue: ctx[b, s, h*64+hd] bf16 hi/lo
    float inv0 = 1.0f / l0, inv1 = 1.0f / l1;
    int s0 = qblk * 128 + mw + (lid >> 2);
    #pragma unroll
    for (int nt = 0; nt < 8; nt++) {
        int cidx = nt * 8 + (lid & 3) * 2;
        float v0 = oacc[nt][0] * inv0, v1 = oacc[nt][1] * inv0;
        float v2 = oacc[nt][2] * inv1, v3 = oacc[nt][3] * inv1;
        size_t base0 = ((size_t)b * S_ + s0) * D_ + h * 64 + cidx;
        size_t base1 = ((size_t)b * S_ + s0 + 8) * D_ + h * 64 + cidx;
        bf162 h0 = mk2(v0, v1), h1 = mk2(v2, v3);
        *(bf162*)(ctxh + base0) = h0;
        *(bf162*)(ctxh + base1) = h1;
        *(bf162*)(ctxl + base0) = mk2(v0 - __bfloat162float(h0.x),
                                      v1 - __bfloat162float(h0.y));
        *(bf162*)(ctxl + base1) = mk2(v2 - __bfloat162float(h1.x),
                                      v3 - __bfloat162float(h1.y));
    }
}

// ---------------------------------------------------------------------------
extern "C" void kernel_launch(void* const* d_in, const int* in_sizes, int n_in,
                              void* d_out, int out_size)
{
    const float* xq = (const float*)d_in[0];
    const float* xk = (const float*)d_in[1];
    const float* xv = (const float*)d_in[2];
    const float* Wq = (const float*)d_in[3];
    const float* bq = (const float*)d_in[4];
    const float* Wk = (const float*)d_in[5];
    const float* bk = (const float*)d_in[6];
    const float* Wv = (const float*)d_in[7];
    const float* bv = (const float*)d_in[8];
    const float* Wo = (const float*)d_in[9];
    const float* bo = (const float*)d_in[10];
    float* out = (float*)d_out;

    bf16 *qh, *ql, *kh, *kl, *vth, *vtl, *ctxh, *ctxl, *xh, *xl, *wh, *wl;
    cudaGetSymbolAddress((void**)&qh,   g_qh);
    cudaGetSymbolAddress((void**)&ql,   g_ql);
    cudaGetSymbolAddress((void**)&kh,   g_kh);
    cudaGetSymbolAddress((void**)&kl,   g_kl);
    cudaGetSymbolAddress((void**)&vth,  g_vth);
    cudaGetSymbolAddress((void**)&vtl,  g_vtl);
    cudaGetSymbolAddress((void**)&ctxh, g_ctxh);
    cudaGetSymbolAddress((void**)&ctxl, g_ctxl);
    cudaGetSymbolAddress((void**)&xh,   g_xh);
    cudaGetSymbolAddress((void**)&xl,   g_xl);
    cudaGetSymbolAddress((void**)&wh,   g_wh);
    cudaGetSymbolAddress((void**)&wl,   g_wl);

    static bool attr_done = false;
    if (!attr_done) {
        cudaFuncSetAttribute(gemm_mma_kernel<0>,
                             cudaFuncAttributeMaxDynamicSharedMemorySize, G_SMEM_TOTAL);
        cudaFuncSetAttribute(gemm_mma_kernel<1>,
                             cudaFuncAttributeMaxDynamicSharedMemorySize, G_SMEM_TOTAL);
        cudaFuncSetAttribute(gemm_mma_kernel<2>,
                             cudaFuncAttributeMaxDynamicSharedMemorySize, G_SMEM_TOTAL);
        cudaFuncSetAttribute(flash_mma_kernel,
                             cudaFuncAttributeMaxDynamicSharedMemorySize, F_SMEM_TOTAL);
        attr_done = true;
    }

    dim3 cgrid(4096, 1), cblk(256, 1);
    dim3 wgrid(32, 32), wblk(32, 8);
    dim3 ggrid(D_ / 128, M_ / 128);                    // (8, 32)

    // Q projection (scaled by 1/sqrt(HD))
    convert_wT_kernel<<<wgrid, wblk>>>(Wq, wh, wl);
    convert_hl_kernel<<<cgrid, cblk>>>(xq, xh, xl);
    gemm_mma_kernel<1><<<ggrid, 256, G_SMEM_TOTAL>>>(xh, xl, wh, wl, bq, 0.125f, qh, ql);
    // K projection
    convert_wT_kernel<<<wgrid, wblk>>>(Wk, wh, wl);
    convert_hl_kernel<<<cgrid, cblk>>>(xk, xh, xl);
    gemm_mma_kernel<1><<<ggrid, 256, G_SMEM_TOTAL>>>(xh, xl, wh, wl, bk, 1.0f, kh, kl);
    // V projection -> transposed [B,H,HD,S]
    convert_wT_kernel<<<wgrid, wblk>>>(Wv, wh, wl);
    convert_hl_kernel<<<cgrid, cblk>>>(xv, xh, xl);
    gemm_mma_kernel<2><<<ggrid, 256, G_SMEM_TOTAL>>>(xh, xl, wh, wl, bv, 1.0f, vth, vtl);

    // Attention (outputs ctx bf16 hi/lo directly)
    flash_mma_kernel<<<dim3(S_ / 128, H_, B_), 256, F_SMEM_TOTAL>>>(
        qh, ql, kh, kl, vth, vtl, ctxh, ctxl);

    // Output projection (fp32 out)
    convert_wT_kernel<<<wgrid, wblk>>>(Wo, wh, wl);
    gemm_mma_kernel<0><<<ggrid, 256, G_SMEM_TOTAL>>>(ctxh, ctxl, wh, wl, bo, 1.0f, out, nullptr);
}

// round 7
// speedup vs baseline: 2.7890x; 1.0253x over previous
#include <cuda_runtime.h>
#include <cuda_bf16.h>
#include <cstdint>
#include <math.h>

#define B_  2
#define S_  2048
#define D_  1024
#define H_  16
#define HD_ 64
#define M_  (B_*S_)   // 4096

typedef __nv_bfloat16 bf16;
typedef __nv_bfloat162 bf162;

// ---------------- scratch (__device__ globals; no allocs allowed) ----------
__device__ bf16 g_qh[(size_t)M_*D_];
__device__ bf16 g_ql[(size_t)M_*D_];
__device__ bf16 g_kh[(size_t)M_*D_];
__device__ bf16 g_kl[(size_t)M_*D_];
__device__ bf16 g_vth[(size_t)M_*D_];   // [B,H,HD,S]
__device__ bf16 g_vtl[(size_t)M_*D_];
__device__ bf16 g_ctxh[(size_t)M_*D_];  // [B,S,D]
__device__ bf16 g_ctxl[(size_t)M_*D_];
__device__ bf16 g_xh[(size_t)3*M_*D_];  // 3 inputs
__device__ bf16 g_xl[(size_t)3*M_*D_];
__device__ bf16 g_wh[(size_t)4*D_*D_];  // 4 weights (transposed)
__device__ bf16 g_wl[(size_t)4*D_*D_];

// ---------------- helpers ---------------------------------------------------
__device__ __forceinline__ uint32_t smem_u32(const void* p) {
    uint32_t a;
    asm("{ .reg .u64 t; cvta.to.shared.u64 t, %1; cvt.u32.u64 %0, t; }" : "=r"(a) : "l"(p));
    return a;
}
__device__ __forceinline__ void ldsm_x4(uint32_t* r, uint32_t addr) {
    asm volatile("ldmatrix.sync.aligned.m8n8.x4.shared.b16 {%0,%1,%2,%3}, [%4];"
                 : "=r"(r[0]), "=r"(r[1]), "=r"(r[2]), "=r"(r[3]) : "r"(addr));
}
__device__ __forceinline__ void mma16816(float* d, const uint32_t* a,
                                         const uint32_t* b) {
    asm volatile("mma.sync.aligned.m16n8k16.row.col.f32.bf16.bf16.f32 "
        "{%0,%1,%2,%3}, {%4,%5,%6,%7}, {%8,%9}, {%0,%1,%2,%3};"
        : "+f"(d[0]), "+f"(d[1]), "+f"(d[2]), "+f"(d[3])
        : "r"(a[0]), "r"(a[1]), "r"(a[2]), "r"(a[3]), "r"(b[0]), "r"(b[1]));
}
#define CP_ASYNC16(dst, src) \
    asm volatile("cp.async.cg.shared.global [%0], [%1], 16;" :: "r"(dst), "l"(src))
#define CP_COMMIT() asm volatile("cp.async.commit_group;" ::: "memory")
#define CP_WAIT1()  asm volatile("cp.async.wait_group 1;" ::: "memory")
#define CP_WAIT0()  asm volatile("cp.async.wait_group 0;" ::: "memory")

__device__ __forceinline__ void split_store(bf16* Yh, bf16* Yl, size_t idx, float v) {
    bf16 h = __float2bfloat16(v);
    Yh[idx] = h;
    Yl[idx] = __float2bfloat16(v - __bfloat162float(h));
}
__device__ __forceinline__ bf162 mk2(float a, float b) {
    bf162 r; r.x = __float2bfloat16(a); r.y = __float2bfloat16(b); return r;
}

// ---------------------------------------------------------------------------
// Fused fp32 -> bf16 hi/lo split for 3 inputs (blockIdx.y selects input)
// ---------------------------------------------------------------------------
__global__ __launch_bounds__(256) void convert_hl_kernel(
    const float* __restrict__ X0, const float* __restrict__ X1,
    const float* __restrict__ X2, bf16* __restrict__ Xh, bf16* __restrict__ Xl)
{
    const float* Xs[3] = {X0, X1, X2};
    const float* X = Xs[blockIdx.y];
    size_t off2 = (size_t)blockIdx.y * (M_ * (size_t)D_ / 2);  // bf162 offset
    int i = blockIdx.x * blockDim.x + threadIdx.x;   // float4 index
    float4 x = ((const float4*)X)[i];
    bf16 h0 = __float2bfloat16(x.x), h1 = __float2bfloat16(x.y);
    bf16 h2 = __float2bfloat16(x.z), h3 = __float2bfloat16(x.w);
    bf162 ph0; ph0.x = h0; ph0.y = h1;
    bf162 ph1; ph1.x = h2; ph1.y = h3;
    bf162 pl0; pl0.x = __float2bfloat16(x.x - __bfloat162float(h0));
    pl0.y = __float2bfloat16(x.y - __bfloat162float(h1));
    bf162 pl1; pl1.x = __float2bfloat16(x.z - __bfloat162float(h2));
    pl1.y = __float2bfloat16(x.w - __bfloat162float(h3));
    ((bf162*)Xh)[off2 + 2*i]   = ph0;
    ((bf162*)Xh)[off2 + 2*i+1] = ph1;
    ((bf162*)Xl)[off2 + 2*i]   = pl0;
    ((bf162*)Xl)[off2 + 2*i+1] = pl1;
}

// ---------------------------------------------------------------------------
// Fused W [K,N] fp32 -> transposed Wt [N,K] bf16 hi/lo, 4 weights via blockIdx.z
// ---------------------------------------------------------------------------
__global__ __launch_bounds__(256) void convert_wT_kernel(
    const float* __restrict__ W0, const float* __restrict__ W1,
    const float* __restrict__ W2, const float* __restrict__ W3,
    bf16* __restrict__ Wth, bf16* __restrict__ Wtl)
{
    const float* Ws[4] = {W0, W1, W2, W3};
    const float* W = Ws[blockIdx.z];
    size_t off = (size_t)blockIdx.z * D_ * D_;
    __shared__ float t[32][33];
    int tx = threadIdx.x, ty = threadIdx.y;           // (32, 8)
    int n0 = blockIdx.x * 32, k0 = blockIdx.y * 32;
    #pragma unroll
    for (int i = 0; i < 4; i++)
        t[ty + 8*i][tx] = W[(size_t)(k0 + ty + 8*i) * D_ + n0 + tx];
    __syncthreads();
    #pragma unroll
    for (int i = 0; i < 4; i++) {
        float v = t[tx][ty + 8*i];
        split_store(Wth, Wtl, off + (size_t)(n0 + ty + 8*i) * D_ + k0 + tx, v);
    }
}

// ---------------------------------------------------------------------------
// mma.sync GEMM: Y[M,N] = (X @ W + bias) * scale via 3-term bf16 split.
// CTA 128x128, 8 warps (warp tile 32x64), BK=32, cp.async double buffer.
// B-fragments via paired ldmatrix.x4 (2 n-tiles per ldsm).
// ---------------------------------------------------------------------------
#define GP 80                       // row pitch, bytes
#define TILE_BYTES 10240            // 128 * 80
#define BUF_BYTES  40960
#define G_SMEM_TOTAL (2 * BUF_BYTES)

template<int MODE>
__global__ __launch_bounds__(256, 2) void gemm_mma_kernel(
    const bf16* __restrict__ Ah, const bf16* __restrict__ Al,
    const bf16* __restrict__ Bh, const bf16* __restrict__ Bl,
    const float* __restrict__ bias, float scale,
    void* __restrict__ Y0, void* __restrict__ Y1)
{
    extern __shared__ char smem[];
    uint32_t sb = smem_u32(smem);

    int tid = threadIdx.x, wid = tid >> 5, lid = tid & 31;
    int m0 = blockIdx.y * 128, n0 = blockIdx.x * 128;
    int wm = (wid >> 1) * 32, wn = (wid & 1) * 64;
    int g = lid >> 3;

    const bf16* srcs[4] = {Ah, Al, Bh, Bl};
    const int rbase[4] = {m0, m0, n0, n0};

    int slot_tile[8], slot_r[8], slot_q[8];
    #pragma unroll
    for (int it = 0; it < 8; it++) {
        int j = tid + it * 256;
        slot_tile[it] = j >> 9;
        int rem = j & 511;
        slot_r[it] = rem >> 2;
        slot_q[it] = rem & 3;
    }

    float acc[2][8][4];
    #pragma unroll
    for (int mt = 0; mt < 2; mt++)
        #pragma unroll
        for (int nt = 0; nt < 8; nt++)
            #pragma unroll
            for (int c = 0; c < 4; c++) acc[mt][nt][c] = 0.f;

    #pragma unroll
    for (int it = 0; it < 8; it++) {
        uint32_t dst = sb + slot_tile[it] * TILE_BYTES + slot_r[it] * GP + slot_q[it] * 16;
        const bf16* src = srcs[slot_tile[it]] +
            (size_t)(rbase[slot_tile[it]] + slot_r[it]) * D_ + slot_q[it] * 8;
        CP_ASYNC16(dst, src);
    }
    CP_COMMIT();

    for (int kc = 0; kc < 32; kc++) {
        int buf = kc & 1;
        uint32_t bufb = sb + buf * BUF_BYTES;
        if (kc + 1 < 32) {
            uint32_t ob = sb + (buf ^ 1) * BUF_BYTES;
            #pragma unroll
            for (int it = 0; it < 8; it++) {
                uint32_t dst = ob + slot_tile[it] * TILE_BYTES + slot_r[it] * GP + slot_q[it] * 16;
                const bf16* src = srcs[slot_tile[it]] +
                    (size_t)(rbase[slot_tile[it]] + slot_r[it]) * D_ + (kc + 1) * 32 + slot_q[it] * 8;
                CP_ASYNC16(dst, src);
            }
            CP_COMMIT();
            CP_WAIT1();
        } else {
            CP_WAIT0();
        }
        __syncthreads();

        #pragma unroll
        for (int ks = 0; ks < 2; ks++) {
            uint32_t ah[2][4], al[2][4];
            #pragma unroll
            for (int mt = 0; mt < 2; mt++) {
                uint32_t ra = (uint32_t)(wm + mt * 16 + (lid & 15)) * GP +
                              ks * 32 + (lid >> 4) * 16;
                ldsm_x4(ah[mt], bufb + 0 * TILE_BYTES + ra);
                ldsm_x4(al[mt], bufb + 1 * TILE_BYTES + ra);
            }
            #pragma unroll
            for (int p = 0; p < 4; p++) {
                uint32_t row = (uint32_t)(wn + p * 16 + ((g >> 1) << 3) + (lid & 7));
                uint32_t rbadr = row * GP + ks * 32 + (g & 1) * 16;
                uint32_t bh4[4], bl4[4];
                ldsm_x4(bh4, bufb + 2 * TILE_BYTES + rbadr);
                ldsm_x4(bl4, bufb + 3 * TILE_BYTES + rbadr);
                #pragma unroll
                for (int mt = 0; mt < 2; mt++) {
                    mma16816(acc[mt][2*p],   ah[mt], bh4);
                    mma16816(acc[mt][2*p],   al[mt], bh4);
                    mma16816(acc[mt][2*p],   ah[mt], bl4);
                    mma16816(acc[mt][2*p+1], ah[mt], bh4 + 2);
                    mma16816(acc[mt][2*p+1], al[mt], bh4 + 2);
                    mma16816(acc[mt][2*p+1], ah[mt], bl4 + 2);
                }
            }
        }
        __syncthreads();
    }

    #pragma unroll
    for (int mt = 0; mt < 2; mt++) {
        #pragma unroll
        for (int nt = 0; nt < 8; nt++) {
            int mA = m0 + wm + mt * 16 + (lid >> 2);
            int nA = n0 + wn + nt * 8 + (lid & 3) * 2;
            float b0 = bias[nA], b1 = bias[nA + 1];
            float v0 = (acc[mt][nt][0] + b0) * scale;
            float v1 = (acc[mt][nt][1] + b1) * scale;
            float v2 = (acc[mt][nt][2] + b0) * scale;
            float v3 = (acc[mt][nt][3] + b1) * scale;
            if (MODE == 0) {
                float* Y = (float*)Y0;
                *(float2*)(Y + (size_t)mA * D_ + nA) = make_float2(v0, v1);
                *(float2*)(Y + (size_t)(mA + 8) * D_ + nA) = make_float2(v2, v3);
            } else if (MODE == 1) {
                bf16* Yh = (bf16*)Y0; bf16* Yl = (bf16*)Y1;
                int h = nA >> 6, hd = nA & 63;
                int b = mA >> 11, s = mA & (S_ - 1);
                size_t base0 = (((size_t)(b * H_ + h)) * S_ + s) * HD_ + hd;
                size_t base1 = (((size_t)(b * H_ + h)) * S_ + (s + 8)) * HD_ + hd;
                bf162 h0 = mk2(v0, v1), h1 = mk2(v2, v3);
                *(bf162*)(Yh + base0) = h0;
                *(bf162*)(Yh + base1) = h1;
                *(bf162*)(Yl + base0) = mk2(v0 - __bfloat162float(h0.x),
                                            v1 - __bfloat162float(h0.y));
                *(bf162*)(Yl + base1) = mk2(v2 - __bfloat162float(h1.x),
                                            v3 - __bfloat162float(h1.y));
            } else {
                bf16* Yh = (bf16*)Y0; bf16* Yl = (bf16*)Y1;
                int h = nA >> 6, hd = nA & 63;
                int b = mA >> 11, s = mA & (S_ - 1);
                size_t rb = (size_t)(b * H_ + h) * HD_;
                split_store(Yh, Yl, (rb + hd)     * S_ + s,     v0);
                split_store(Yh, Yl, (rb + hd + 1) * S_ + s,     v1);
                split_store(Yh, Yl, (rb + hd)     * S_ + s + 8, v2);
                split_store(Yh, Yl, (rb + hd + 1) * S_ + s + 8, v3);
            }
        }
    }
}

// ---------------------------------------------------------------------------
// Flash attention via mma.sync. CTA = 128 q-rows x (b,h). 8 warps x 16 rows.
// Bc=32 kv tiles, double-buffered cp.async, 94KB smem -> 2 CTAs/SM.
// Layout: Qh@0(18432) Ql@18432 | KV buf{0,1}@36864+buf*19456:
//   Kh@+0(4608,pitch144) Kl@+4608 Vth@+9216(5120,pitch80) Vtl@+14336
// Ph@75776(10240,pitch80) Pl@86016. Total 96256.
// ---------------------------------------------------------------------------
#define FQL  18432
#define FKV  36864
#define FKVB 19456
#define FPH  75776
#define FPL  86016
#define F_SMEM_TOTAL 96256

__device__ __forceinline__ void flash_issue_kv(
    uint32_t sb, int buf, int kt, size_t bh, int tid,
    const bf16* kh, const bf16* kl, const bf16* vth, const bf16* vtl)
{
    uint32_t kvbase = sb + FKV + buf * FKVB;
    #pragma unroll
    for (int it = 0; it < 4; it++) {
        int j = tid + it * 256;
        int sub = j >> 8, rem = j & 255;
        uint32_t dst; const bf16* src;
        if (sub < 2) {
            int r = rem >> 3, c = rem & 7;
            dst = kvbase + sub * 4608 + r * 144 + c * 16;
            src = (sub ? kl : kh) + (bh * S_ + (size_t)kt * 32 + r) * HD_ + c * 8;
        } else {
            int r = rem >> 2, c = rem & 3;
            dst = kvbase + 9216 + (sub - 2) * 5120 + r * 80 + c * 16;
            src = (sub == 2 ? vth : vtl) + (bh * HD_ + r) * S_ + kt * 32 + c * 8;
        }
        CP_ASYNC16(dst, src);
    }
    CP_COMMIT();
}

__global__ __launch_bounds__(256, 2) void flash_mma_kernel(
    const bf16* __restrict__ qh, const bf16* __restrict__ ql,
    const bf16* __restrict__ kh, const bf16* __restrict__ kl,
    const bf16* __restrict__ vth, const bf16* __restrict__ vtl,
    bf16* __restrict__ ctxh, bf16* __restrict__ ctxl)
{
    extern __shared__ char smem[];
    uint32_t sb = smem_u32(smem);

    int tid = threadIdx.x, wid = tid >> 5, lid = tid & 31;
    int qblk = blockIdx.x, h = blockIdx.y, b = blockIdx.z;
    size_t bh = (size_t)(b * H_ + h);
    int mw = wid * 16;
    int g = lid >> 3;

    // Q load: 2048 16B chunks (Qh then Ql), 128 rows, pitch 144
    #pragma unroll
    for (int it = 0; it < 8; it++) {
        int j = tid + it * 256;
        int sub = j >> 10, rem = j & 1023, r = rem >> 3, c = rem & 7;
        uint32_t dst = sb + sub * 18432 + r * 144 + c * 16;
        const bf16* src = (sub ? ql : qh) +
            (bh * S_ + (size_t)qblk * 128 + r) * HD_ + c * 8;
        CP_ASYNC16(dst, src);
    }
    CP_COMMIT();
    flash_issue_kv(sb, 0, 0, bh, tid, kh, kl, vth, vtl);

    float m0 = -1e30f, m1 = -1e30f, l0 = 0.f, l1 = 0.f;
    float oacc[8][4];
    #pragma unroll
    for (int nt = 0; nt < 8; nt++)
        #pragma unroll
        for (int c = 0; c < 4; c++) oacc[nt][c] = 0.f;

    const int NT = S_ / 32;   // 64 kv tiles
    for (int kt = 0; kt < NT; kt++) {
        int buf = kt & 1;
        if (kt + 1 < NT) {
            flash_issue_kv(sb, buf ^ 1, kt + 1, bh, tid, kh, kl, vth, vtl);
            CP_WAIT1();
        } else {
            CP_WAIT0();
        }
        __syncthreads();
        uint32_t kvb = sb + FKV + buf * FKVB;

        // ---- S = Q K^T (3-term split): warp rows mw..mw+15, kv cols 0..31
        float sacc[4][4];
        #pragma unroll
        for (int nt = 0; nt < 4; nt++)
            #pragma unroll
            for (int c = 0; c < 4; c++) sacc[nt][c] = 0.f;

        #pragma unroll
        for (int ks = 0; ks < 4; ks++) {
            uint32_t ah[4], al[4];
            uint32_t ra = sb + (uint32_t)(mw + (lid & 15)) * 144 +
                          ks * 32 + (lid >> 4) * 16;
            ldsm_x4(ah, ra);
            ldsm_x4(al, ra + FQL);
            #pragma unroll
            for (int p = 0; p < 2; p++) {
                uint32_t row = (uint32_t)(p * 16 + ((g >> 1) << 3) + (lid & 7));
                uint32_t rbadr = kvb + row * 144 + ks * 32 + (g & 1) * 16;
                uint32_t bh4[4], bl4[4];
                ldsm_x4(bh4, rbadr);
                ldsm_x4(bl4, rbadr + 4608);
                mma16816(sacc[2*p],   ah, bh4);
                mma16816(sacc[2*p],   al, bh4);
                mma16816(sacc[2*p],   ah, bl4);
                mma16816(sacc[2*p+1], ah, bh4 + 2);
                mma16816(sacc[2*p+1], al, bh4 + 2);
                mma16816(sacc[2*p+1], ah, bl4 + 2);
            }
        }

        // ---- online softmax; regs [0,1] -> row mw+lid/4; [2,3] -> +8
        float mx0 = -1e30f, mx1 = -1e30f;
        #pragma unroll
        for (int nt = 0; nt < 4; nt++) {
            mx0 = fmaxf(mx0, fmaxf(sacc[nt][0], sacc[nt][1]));
            mx1 = fmaxf(mx1, fmaxf(sacc[nt][2], sacc[nt][3]));
        }
        mx0 = fmaxf(mx0, __shfl_xor_sync(0xffffffffu, mx0, 1));
        mx0 = fmaxf(mx0, __shfl_xor_sync(0xffffffffu, mx0, 2));
        mx1 = fmaxf(mx1, __shfl_xor_sync(0xffffffffu, mx1, 1));
        mx1 = fmaxf(mx1, __shfl_xor_sync(0xffffffffu, mx1, 2));
        float mn0 = fmaxf(m0, mx0), mn1 = fmaxf(m1, mx1);
        float corr0 = __expf(m0 - mn0), corr1 = __expf(m1 - mn1);
        m0 = mn0; m1 = mn1;

        int r0 = mw + (lid >> 2);
        uint32_t pcol = (uint32_t)((lid & 3) * 4);
        float sum0 = 0.f, sum1 = 0.f;
        #pragma unroll
        for (int nt = 0; nt < 4; nt++) {
            float p00 = __expf(sacc[nt][0] - mn0);
            float p01 = __expf(sacc[nt][1] - mn0);
            float p10 = __expf(sacc[nt][2] - mn1);
            float p11 = __expf(sacc[nt][3] - mn1);
            sum0 += p00 + p01; sum1 += p10 + p11;
            uint32_t off0 = (uint32_t)r0 * 80 + nt * 16 + pcol;
            bf162 h0 = mk2(p00, p01), h1 = mk2(p10, p11);
            *(bf162*)(smem + FPH + off0) = h0;
            *(bf162*)(smem + FPH + off0 + 8 * 80) = h1;
            *(bf162*)(smem + FPL + off0) =
                mk2(p00 - __bfloat162float(h0.x), p01 - __bfloat162float(h0.y));
            *(bf162*)(smem + FPL + off0 + 8 * 80) =
                mk2(p10 - __bfloat162float(h1.x), p11 - __bfloat162float(h1.y));
        }
        sum0 += __shfl_xor_sync(0xffffffffu, sum0, 1);
        sum0 += __shfl_xor_sync(0xffffffffu, sum0, 2);
        sum1 += __shfl_xor_sync(0xffffffffu, sum1, 1);
        sum1 += __shfl_xor_sync(0xffffffffu, sum1, 2);
        l0 = l0 * corr0 + sum0;
        l1 = l1 * corr1 + sum1;
        #pragma unroll
        for (int nt = 0; nt < 8; nt++) {
            oacc[nt][0] *= corr0; oacc[nt][1] *= corr0;
            oacc[nt][2] *= corr1; oacc[nt][3] *= corr1;
        }
        __syncwarp();

        // ---- O += P V  (A = P rows [pitch 80], B = Vt [hd rows][kv cols])
        #pragma unroll
        for (int ks = 0; ks < 2; ks++) {
            uint32_t ap[4], apl[4];
            uint32_t ra = sb + FPH + (uint32_t)(mw + (lid & 15)) * 80 +
                          ks * 32 + (lid >> 4) * 16;
            ldsm_x4(ap, ra);
            ldsm_x4(apl, ra + (FPL - FPH));
            #pragma unroll
            for (int p = 0; p < 4; p++) {
                uint32_t row = (uint32_t)(p * 16 + ((g >> 1) << 3) + (lid & 7));
                uint32_t rbadr = kvb + 9216 + row * 80 + ks * 32 + (g & 1) * 16;
                uint32_t bv4h[4], bv4l[4];
                ldsm_x4(bv4h, rbadr);
                ldsm_x4(bv4l, rbadr + 5120);
                mma16816(oacc[2*p],   ap,  bv4h);
                mma16816(oacc[2*p],   apl, bv4h);
                mma16816(oacc[2*p],   ap,  bv4l);
                mma16816(oacc[2*p+1], ap,  bv4h + 2);
                mma16816(oacc[2*p+1], apl, bv4h + 2);
                mma16816(oacc[2*p+1], ap,  bv4l + 2);
            }
        }
        __syncthreads();
    }

    // ---- epilogue: ctx[b, s, h*64+hd] bf16 hi/lo
    float inv0 = 1.0f / l0, inv1 = 1.0f / l1;
    int s0 = qblk * 128 + mw + (lid >> 2);
    #pragma unroll
    for (int nt = 0; nt < 8; nt++) {
        int cidx = nt * 8 + (lid & 3) * 2;
        float v0 = oacc[nt][0] * inv0, v1 = oacc[nt][1] * inv0;
        float v2 = oacc[nt][2] * inv1, v3 = oacc[nt][3] * inv1;
        size_t base0 = ((size_t)b * S_ + s0) * D_ + h * 64 + cidx;
        size_t base1 = ((size_t)b * S_ + s0 + 8) * D_ + h * 64 + cidx;
        bf162 h0 = mk2(v0, v1), h1 = mk2(v2, v3);
        *(bf162*)(ctxh + base0) = h0;
        *(bf162*)(ctxh + base1) = h1;
        *(bf162*)(ctxl + base0) = mk2(v0 - __bfloat162float(h0.x),
                                      v1 - __bfloat162float(h0.y));
        *(bf162*)(ctxl + base1) = mk2(v2 - __bfloat162float(h1.x),
                                      v3 - __bfloat162float(h1.y));
    }
}

// ---------------------------------------------------------------------------
extern "C" void kernel_launch(void* const* d_in, const int* in_sizes, int n_in,
                              void* d_out, int out_size)
{
    const float* xq = (const float*)d_in[0];
    const float* xk = (const float*)d_in[1];
    const float* xv = (const float*)d_in[2];
    const float* Wq = (const float*)d_in[3];
    const float* bq = (const float*)d_in[4];
    const float* Wk = (const float*)d_in[5];
    const float* bk = (const float*)d_in[6];
    const float* Wv = (const float*)d_in[7];
    const float* bv = (const float*)d_in[8];
    const float* Wo = (const float*)d_in[9];
    const float* bo = (const float*)d_in[10];
    float* out = (float*)d_out;

    bf16 *qh, *ql, *kh, *kl, *vth, *vtl, *ctxh, *ctxl, *xh, *xl, *wh, *wl;
    cudaGetSymbolAddress((void**)&qh,   g_qh);
    cudaGetSymbolAddress((void**)&ql,   g_ql);
    cudaGetSymbolAddress((void**)&kh,   g_kh);
    cudaGetSymbolAddress((void**)&kl,   g_kl);
    cudaGetSymbolAddress((void**)&vth,  g_vth);
    cudaGetSymbolAddress((void**)&vtl,  g_vtl);
    cudaGetSymbolAddress((void**)&ctxh, g_ctxh);
    cudaGetSymbolAddress((void**)&ctxl, g_ctxl);
    cudaGetSymbolAddress((void**)&xh,   g_xh);
    cudaGetSymbolAddress((void**)&xl,   g_xl);
    cudaGetSymbolAddress((void**)&wh,   g_wh);
    cudaGetSymbolAddress((void**)&wl,   g_wl);

    static bool attr_done = false;
    if (!attr_done) {
        cudaFuncSetAttribute(gemm_mma_kernel<0>,
                             cudaFuncAttributeMaxDynamicSharedMemorySize, G_SMEM_TOTAL);
        cudaFuncSetAttribute(gemm_mma_kernel<1>,
                             cudaFuncAttributeMaxDynamicSharedMemorySize, G_SMEM_TOTAL);
        cudaFuncSetAttribute(gemm_mma_kernel<2>,
                             cudaFuncAttributeMaxDynamicSharedMemorySize, G_SMEM_TOTAL);
        cudaFuncSetAttribute(flash_mma_kernel,
                             cudaFuncAttributeMaxDynamicSharedMemorySize, F_SMEM_TOTAL);
        attr_done = true;
    }

    const size_t MD = (size_t)M_ * D_;
    const size_t DD = (size_t)D_ * D_;

    // Fused conversions
    convert_wT_kernel<<<dim3(32, 32, 4), dim3(32, 8)>>>(Wq, Wk, Wv, Wo, wh, wl);
    convert_hl_kernel<<<dim3(4096, 3), 256>>>(xq, xk, xv, xh, xl);

    dim3 ggrid(D_ / 128, M_ / 128);                    // (8, 32)
    // Q projection (scaled by 1/sqrt(HD))
    gemm_mma_kernel<1><<<ggrid, 256, G_SMEM_TOTAL>>>(
        xh, xl, wh, wl, bq, 0.125f, qh, ql);
    // K projection
    gemm_mma_kernel<1><<<ggrid, 256, G_SMEM_TOTAL>>>(
        xh + MD, xl + MD, wh + DD, wl + DD, bk, 1.0f, kh, kl);
    // V projection -> transposed [B,H,HD,S]
    gemm_mma_kernel<2><<<ggrid, 256, G_SMEM_TOTAL>>>(
        xh + 2*MD, xl + 2*MD, wh + 2*DD, wl + 2*DD, bv, 1.0f, vth, vtl);

    // Attention (outputs ctx bf16 hi/lo directly)
    flash_mma_kernel<<<dim3(S_ / 128, H_, B_), 256, F_SMEM_TOTAL>>>(
        qh, ql, kh, kl, vth, vtl, ctxh, ctxl);

    // Output projection (fp32 out)
    gemm_mma_kernel<0><<<ggrid, 256, G_SMEM_TOTAL>>>(
        ctxh, ctxl, wh + 3*DD, wl + 3*DD, bo, 1.0f, out, nullptr);
}

// round 8
// speedup vs baseline: 2.8465x; 1.0206x over previous
#include <cuda_runtime.h>
#include <cuda_bf16.h>
#include <cstdint>
#include <math.h>

#define B_  2
#define S_  2048
#define D_  1024
#define H_  16
#define HD_ 64
#define M_  (B_*S_)   // 4096

typedef __nv_bfloat16 bf16;
typedef __nv_bfloat162 bf162;

// ---------------- scratch (__device__ globals; no allocs allowed) ----------
__device__ bf16 g_qh[(size_t)M_*D_];
__device__ bf16 g_ql[(size_t)M_*D_];
__device__ bf16 g_kh[(size_t)M_*D_];
__device__ bf16 g_kl[(size_t)M_*D_];
__device__ bf16 g_vth[(size_t)M_*D_];   // [B,H,HD,S]
__device__ bf16 g_vtl[(size_t)M_*D_];
__device__ bf16 g_ctxh[(size_t)M_*D_];  // [B,S,D]
__device__ bf16 g_ctxl[(size_t)M_*D_];
__device__ bf16 g_xh[(size_t)3*M_*D_];  // 3 inputs
__device__ bf16 g_xl[(size_t)3*M_*D_];
__device__ bf16 g_wh[(size_t)4*D_*D_];  // 4 weights (transposed)
__device__ bf16 g_wl[(size_t)4*D_*D_];

// ---------------- helpers ---------------------------------------------------
__device__ __forceinline__ uint32_t smem_u32(const void* p) {
    uint32_t a;
    asm("{ .reg .u64 t; cvta.to.shared.u64 t, %1; cvt.u32.u64 %0, t; }" : "=r"(a) : "l"(p));
    return a;
}
__device__ __forceinline__ void ldsm_x4(uint32_t* r, uint32_t addr) {
    asm volatile("ldmatrix.sync.aligned.m8n8.x4.shared.b16 {%0,%1,%2,%3}, [%4];"
                 : "=r"(r[0]), "=r"(r[1]), "=r"(r[2]), "=r"(r[3]) : "r"(addr));
}
__device__ __forceinline__ void mma16816(float* d, const uint32_t* a,
                                         const uint32_t* b) {
    asm volatile("mma.sync.aligned.m16n8k16.row.col.f32.bf16.bf16.f32 "
        "{%0,%1,%2,%3}, {%4,%5,%6,%7}, {%8,%9}, {%0,%1,%2,%3};"
        : "+f"(d[0]), "+f"(d[1]), "+f"(d[2]), "+f"(d[3])
        : "r"(a[0]), "r"(a[1]), "r"(a[2]), "r"(a[3]), "r"(b[0]), "r"(b[1]));
}
#define CP_ASYNC16(dst, src) \
    asm volatile("cp.async.cg.shared.global [%0], [%1], 16;" :: "r"(dst), "l"(src))
#define CP_COMMIT() asm volatile("cp.async.commit_group;" ::: "memory")
#define CP_WAIT1()  asm volatile("cp.async.wait_group 1;" ::: "memory")
#define CP_WAIT0()  asm volatile("cp.async.wait_group 0;" ::: "memory")

__device__ __forceinline__ void split_store(bf16* Yh, bf16* Yl, size_t idx, float v) {
    bf16 h = __float2bfloat16(v);
    Yh[idx] = h;
    Yl[idx] = __float2bfloat16(v - __bfloat162float(h));
}
__device__ __forceinline__ bf162 mk2(float a, float b) {
    bf162 r; r.x = __float2bfloat16(a); r.y = __float2bfloat16(b); return r;
}

// ---------------------------------------------------------------------------
// Fused fp32 -> bf16 hi/lo split for 3 inputs (blockIdx.y selects input)
// ---------------------------------------------------------------------------
__global__ __launch_bounds__(256) void convert_hl_kernel(
    const float* __restrict__ X0, const float* __restrict__ X1,
    const float* __restrict__ X2, bf16* __restrict__ Xh, bf16* __restrict__ Xl)
{
    const float* Xs[3] = {X0, X1, X2};
    const float* X = Xs[blockIdx.y];
    size_t off2 = (size_t)blockIdx.y * (M_ * (size_t)D_ / 2);  // bf162 offset
    int i = blockIdx.x * blockDim.x + threadIdx.x;   // float4 index
    float4 x = ((const float4*)X)[i];
    bf16 h0 = __float2bfloat16(x.x), h1 = __float2bfloat16(x.y);
    bf16 h2 = __float2bfloat16(x.z), h3 = __float2bfloat16(x.w);
    bf162 ph0; ph0.x = h0; ph0.y = h1;
    bf162 ph1; ph1.x = h2; ph1.y = h3;
    bf162 pl0; pl0.x = __float2bfloat16(x.x - __bfloat162float(h0));
    pl0.y = __float2bfloat16(x.y - __bfloat162float(h1));
    bf162 pl1; pl1.x = __float2bfloat16(x.z - __bfloat162float(h2));
    pl1.y = __float2bfloat16(x.w - __bfloat162float(h3));
    ((bf162*)Xh)[off2 + 2*i]   = ph0;
    ((bf162*)Xh)[off2 + 2*i+1] = ph1;
    ((bf162*)Xl)[off2 + 2*i]   = pl0;
    ((bf162*)Xl)[off2 + 2*i+1] = pl1;
}

// ---------------------------------------------------------------------------
// Fused W [K,N] fp32 -> transposed Wt [N,K] bf16 hi/lo, 4 weights via blockIdx.z
// ---------------------------------------------------------------------------
__global__ __launch_bounds__(256) void convert_wT_kernel(
    const float* __restrict__ W0, const float* __restrict__ W1,
    const float* __restrict__ W2, const float* __restrict__ W3,
    bf16* __restrict__ Wth, bf16* __restrict__ Wtl)
{
    const float* Ws[4] = {W0, W1, W2, W3};
    const float* W = Ws[blockIdx.z];
    size_t off = (size_t)blockIdx.z * D_ * D_;
    __shared__ float t[32][33];
    int tx = threadIdx.x, ty = threadIdx.y;           // (32, 8)
    int n0 = blockIdx.x * 32, k0 = blockIdx.y * 32;
    #pragma unroll
    for (int i = 0; i < 4; i++)
        t[ty + 8*i][tx] = W[(size_t)(k0 + ty + 8*i) * D_ + n0 + tx];
    __syncthreads();
    #pragma unroll
    for (int i = 0; i < 4; i++) {
        float v = t[tx][ty + 8*i];
        split_store(Wth, Wtl, off + (size_t)(n0 + ty + 8*i) * D_ + k0 + tx, v);
    }
}

// ---------------------------------------------------------------------------
// Shared GEMM mainloop: acc[2][8][4] += A[128xK] @ B^T[128xK] for one CTA tile.
// CTA 128x128, 8 warps (warp tile 32x64), BK=32, cp.async double buffer.
// ---------------------------------------------------------------------------
#define GP 80                       // row pitch, bytes
#define TILE_BYTES 10240            // 128 * 80
#define BUF_BYTES  40960
#define G_SMEM_TOTAL (2 * BUF_BYTES)

__device__ __forceinline__ void gemm_core(
    uint32_t sb, const bf16* __restrict__ Ah, const bf16* __restrict__ Al,
    const bf16* __restrict__ Bh, const bf16* __restrict__ Bl,
    int m0, int n0, int tid, int wid, int lid, float acc[2][8][4])
{
    int wm = (wid >> 1) * 32, wn = (wid & 1) * 64;
    int g = lid >> 3;

    const bf16* srcs[4] = {Ah, Al, Bh, Bl};
    const int rbase[4] = {m0, m0, n0, n0};

    int slot_tile[8], slot_r[8], slot_q[8];
    #pragma unroll
    for (int it = 0; it < 8; it++) {
        int j = tid + it * 256;
        slot_tile[it] = j >> 9;
        int rem = j & 511;
        slot_r[it] = rem >> 2;
        slot_q[it] = rem & 3;
    }

    #pragma unroll
    for (int it = 0; it < 8; it++) {
        uint32_t dst = sb + slot_tile[it] * TILE_BYTES + slot_r[it] * GP + slot_q[it] * 16;
        const bf16* src = srcs[slot_tile[it]] +
            (size_t)(rbase[slot_tile[it]] + slot_r[it]) * D_ + slot_q[it] * 8;
        CP_ASYNC16(dst, src);
    }
    CP_COMMIT();

    for (int kc = 0; kc < 32; kc++) {
        int buf = kc & 1;
        uint32_t bufb = sb + buf * BUF_BYTES;
        if (kc + 1 < 32) {
            uint32_t ob = sb + (buf ^ 1) * BUF_BYTES;
            #pragma unroll
            for (int it = 0; it < 8; it++) {
                uint32_t dst = ob + slot_tile[it] * TILE_BYTES + slot_r[it] * GP + slot_q[it] * 16;
                const bf16* src = srcs[slot_tile[it]] +
                    (size_t)(rbase[slot_tile[it]] + slot_r[it]) * D_ + (kc + 1) * 32 + slot_q[it] * 8;
                CP_ASYNC16(dst, src);
            }
            CP_COMMIT();
            CP_WAIT1();
        } else {
            CP_WAIT0();
        }
        __syncthreads();

        #pragma unroll
        for (int ks = 0; ks < 2; ks++) {
            uint32_t ah[2][4], al[2][4];
            #pragma unroll
            for (int mt = 0; mt < 2; mt++) {
                uint32_t ra = (uint32_t)(wm + mt * 16 + (lid & 15)) * GP +
                              ks * 32 + (lid >> 4) * 16;
                ldsm_x4(ah[mt], bufb + 0 * TILE_BYTES + ra);
                ldsm_x4(al[mt], bufb + 1 * TILE_BYTES + ra);
            }
            #pragma unroll
            for (int p = 0; p < 4; p++) {
                uint32_t row = (uint32_t)(wn + p * 16 + ((g >> 1) << 3) + (lid & 7));
                uint32_t rbadr = row * GP + ks * 32 + (g & 1) * 16;
                uint32_t bh4[4], bl4[4];
                ldsm_x4(bh4, bufb + 2 * TILE_BYTES + rbadr);
                ldsm_x4(bl4, bufb + 3 * TILE_BYTES + rbadr);
                #pragma unroll
                for (int mt = 0; mt < 2; mt++) {
                    mma16816(acc[mt][2*p],   ah[mt], bh4);
                    mma16816(acc[mt][2*p+1], ah[mt], bh4 + 2);
                    mma16816(acc[mt][2*p],   al[mt], bh4);
                    mma16816(acc[mt][2*p+1], al[mt], bh4 + 2);
                    mma16816(acc[mt][2*p],   ah[mt], bl4);
                    mma16816(acc[mt][2*p+1], ah[mt], bl4 + 2);
                }
            }
        }
        __syncthreads();
    }
}

// ---------------------------------------------------------------------------
// Fused QKV projection: blockIdx.z in {0,1,2} -> Q (scaled, head-split),
// K (head-split), V (transposed head-split).
// ---------------------------------------------------------------------------
__global__ __launch_bounds__(256, 2) void qkv_gemm_kernel(
    const bf16* __restrict__ xh, const bf16* __restrict__ xl,
    const bf16* __restrict__ wh, const bf16* __restrict__ wl,
    const float* __restrict__ bq, const float* __restrict__ bk,
    const float* __restrict__ bv,
    bf16* __restrict__ qh, bf16* __restrict__ ql,
    bf16* __restrict__ kh, bf16* __restrict__ kl,
    bf16* __restrict__ vth, bf16* __restrict__ vtl)
{
    extern __shared__ char smem[];
    uint32_t sb = smem_u32(smem);
    int tid = threadIdx.x, wid = tid >> 5, lid = tid & 31;
    int m0 = blockIdx.y * 128, n0 = blockIdx.x * 128;
    int z = blockIdx.z;
    const size_t MD = (size_t)M_ * D_, DD = (size_t)D_ * D_;

    const bf16* Ah = xh + (size_t)z * MD;
    const bf16* Al = xl + (size_t)z * MD;
    const bf16* Bh = wh + (size_t)z * DD;
    const bf16* Bl = wl + (size_t)z * DD;
    const float* bias = (z == 0) ? bq : (z == 1) ? bk : bv;
    float scale = (z == 0) ? 0.125f : 1.0f;

    float acc[2][8][4];
    #pragma unroll
    for (int mt = 0; mt < 2; mt++)
        #pragma unroll
        for (int nt = 0; nt < 8; nt++)
            #pragma unroll
            for (int c = 0; c < 4; c++) acc[mt][nt][c] = 0.f;

    gemm_core(sb, Ah, Al, Bh, Bl, m0, n0, tid, wid, lid, acc);

    int wm = (wid >> 1) * 32, wn = (wid & 1) * 64;
    #pragma unroll
    for (int mt = 0; mt < 2; mt++) {
        #pragma unroll
        for (int nt = 0; nt < 8; nt++) {
            int mA = m0 + wm + mt * 16 + (lid >> 2);
            int nA = n0 + wn + nt * 8 + (lid & 3) * 2;
            float b0 = bias[nA], b1 = bias[nA + 1];
            float v0 = (acc[mt][nt][0] + b0) * scale;
            float v1 = (acc[mt][nt][1] + b1) * scale;
            float v2 = (acc[mt][nt][2] + b0) * scale;
            float v3 = (acc[mt][nt][3] + b1) * scale;
            int h = nA >> 6, hd = nA & 63;
            int b = mA >> 11, s = mA & (S_ - 1);
            if (z < 2) {
                bf16* Yh = (z == 0) ? qh : kh;
                bf16* Yl = (z == 0) ? ql : kl;
                size_t base0 = (((size_t)(b * H_ + h)) * S_ + s) * HD_ + hd;
                size_t base1 = (((size_t)(b * H_ + h)) * S_ + (s + 8)) * HD_ + hd;
                bf162 h0 = mk2(v0, v1), h1 = mk2(v2, v3);
                *(bf162*)(Yh + base0) = h0;
                *(bf162*)(Yh + base1) = h1;
                *(bf162*)(Yl + base0) = mk2(v0 - __bfloat162float(h0.x),
                                            v1 - __bfloat162float(h0.y));
                *(bf162*)(Yl + base1) = mk2(v2 - __bfloat162float(h1.x),
                                            v3 - __bfloat162float(h1.y));
            } else {
                size_t rb = (size_t)(b * H_ + h) * HD_;
                split_store(vth, vtl, (rb + hd)     * S_ + s,     v0);
                split_store(vth, vtl, (rb + hd + 1) * S_ + s,     v1);
                split_store(vth, vtl, (rb + hd)     * S_ + s + 8, v2);
                split_store(vth, vtl, (rb + hd + 1) * S_ + s + 8, v3);
            }
        }
    }
}

// ---------------------------------------------------------------------------
// O-projection GEMM (fp32 row-major out)
// ---------------------------------------------------------------------------
__global__ __launch_bounds__(256, 2) void out_gemm_kernel(
    const bf16* __restrict__ Ah, const bf16* __restrict__ Al,
    const bf16* __restrict__ Bh, const bf16* __restrict__ Bl,
    const float* __restrict__ bias, float* __restrict__ Y)
{
    extern __shared__ char smem[];
    uint32_t sb = smem_u32(smem);
    int tid = threadIdx.x, wid = tid >> 5, lid = tid & 31;
    int m0 = blockIdx.y * 128, n0 = blockIdx.x * 128;

    float acc[2][8][4];
    #pragma unroll
    for (int mt = 0; mt < 2; mt++)
        #pragma unroll
        for (int nt = 0; nt < 8; nt++)
            #pragma unroll
            for (int c = 0; c < 4; c++) acc[mt][nt][c] = 0.f;

    gemm_core(sb, Ah, Al, Bh, Bl, m0, n0, tid, wid, lid, acc);

    int wm = (wid >> 1) * 32, wn = (wid & 1) * 64;
    #pragma unroll
    for (int mt = 0; mt < 2; mt++) {
        #pragma unroll
        for (int nt = 0; nt < 8; nt++) {
            int mA = m0 + wm + mt * 16 + (lid >> 2);
            int nA = n0 + wn + nt * 8 + (lid & 3) * 2;
            float b0 = bias[nA], b1 = bias[nA + 1];
            *(float2*)(Y + (size_t)mA * D_ + nA) =
                make_float2(acc[mt][nt][0] + b0, acc[mt][nt][1] + b1);
            *(float2*)(Y + (size_t)(mA + 8) * D_ + nA) =
                make_float2(acc[mt][nt][2] + b0, acc[mt][nt][3] + b1);
        }
    }
}

// ---------------------------------------------------------------------------
// Flash attention via mma.sync. CTA = 128 q-rows x (b,h). 8 warps x 16 rows.
// Bc=32 kv tiles, double-buffered cp.async, 94KB smem -> 2 CTAs/SM.
// ---------------------------------------------------------------------------
#define FQL  18432
#define FKV  36864
#define FKVB 19456
#define FPH  75776
#define FPL  86016
#define F_SMEM_TOTAL 96256

__device__ __forceinline__ void flash_issue_kv(
    uint32_t sb, int buf, int kt, size_t bh, int tid,
    const bf16* kh, const bf16* kl, const bf16* vth, const bf16* vtl)
{
    uint32_t kvbase = sb + FKV + buf * FKVB;
    #pragma unroll
    for (int it = 0; it < 4; it++) {
        int j = tid + it * 256;
        int sub = j >> 8, rem = j & 255;
        uint32_t dst; const bf16* src;
        if (sub < 2) {
            int r = rem >> 3, c = rem & 7;
            dst = kvbase + sub * 4608 + r * 144 + c * 16;
            src = (sub ? kl : kh) + (bh * S_ + (size_t)kt * 32 + r) * HD_ + c * 8;
        } else {
            int r = rem >> 2, c = rem & 3;
            dst = kvbase + 9216 + (sub - 2) * 5120 + r * 80 + c * 16;
            src = (sub == 2 ? vth : vtl) + (bh * HD_ + r) * S_ + kt * 32 + c * 8;
        }
        CP_ASYNC16(dst, src);
    }
    CP_COMMIT();
}

__global__ __launch_bounds__(256, 2) void flash_mma_kernel(
    const bf16* __restrict__ qh, const bf16* __restrict__ ql,
    const bf16* __restrict__ kh, const bf16* __restrict__ kl,
    const bf16* __restrict__ vth, const bf16* __restrict__ vtl,
    bf16* __restrict__ ctxh, bf16* __restrict__ ctxl)
{
    extern __shared__ char smem[];
    uint32_t sb = smem_u32(smem);

    int tid = threadIdx.x, wid = tid >> 5, lid = tid & 31;
    int qblk = blockIdx.x, h = blockIdx.y, b = blockIdx.z;
    size_t bh = (size_t)(b * H_ + h);
    int mw = wid * 16;
    int g = lid >> 3;

    #pragma unroll
    for (int it = 0; it < 8; it++) {
        int j = tid + it * 256;
        int sub = j >> 10, rem = j & 1023, r = rem >> 3, c = rem & 7;
        uint32_t dst = sb + sub * 18432 + r * 144 + c * 16;
        const bf16* src = (sub ? ql : qh) +
            (bh * S_ + (size_t)qblk * 128 + r) * HD_ + c * 8;
        CP_ASYNC16(dst, src);
    }
    CP_COMMIT();
    flash_issue_kv(sb, 0, 0, bh, tid, kh, kl, vth, vtl);

    float m0 = -1e30f, m1 = -1e30f, l0 = 0.f, l1 = 0.f;
    float oacc[8][4];
    #pragma unroll
    for (int nt = 0; nt < 8; nt++)
        #pragma unroll
        for (int c = 0; c < 4; c++) oacc[nt][c] = 0.f;

    const int NT = S_ / 32;   // 64 kv tiles
    for (int kt = 0; kt < NT; kt++) {
        int buf = kt & 1;
        if (kt + 1 < NT) {
            flash_issue_kv(sb, buf ^ 1, kt + 1, bh, tid, kh, kl, vth, vtl);
            CP_WAIT1();
        } else {
            CP_WAIT0();
        }
        __syncthreads();
        uint32_t kvb = sb + FKV + buf * FKVB;

        float sacc[4][4];
        #pragma unroll
        for (int nt = 0; nt < 4; nt++)
            #pragma unroll
            for (int c = 0; c < 4; c++) sacc[nt][c] = 0.f;

        #pragma unroll
        for (int ks = 0; ks < 4; ks++) {
            uint32_t ah[4], al[4];
            uint32_t ra = sb + (uint32_t)(mw + (lid & 15)) * 144 +
                          ks * 32 + (lid >> 4) * 16;
            ldsm_x4(ah, ra);
            ldsm_x4(al, ra + FQL);
            #pragma unroll
            for (int p = 0; p < 2; p++) {
                uint32_t row = (uint32_t)(p * 16 + ((g >> 1) << 3) + (lid & 7));
                uint32_t rbadr = kvb + row * 144 + ks * 32 + (g & 1) * 16;
                uint32_t bh4[4], bl4[4];
                ldsm_x4(bh4, rbadr);
                ldsm_x4(bl4, rbadr + 4608);
                mma16816(sacc[2*p],   ah, bh4);
                mma16816(sacc[2*p+1], ah, bh4 + 2);
                mma16816(sacc[2*p],   al, bh4);
                mma16816(sacc[2*p+1], al, bh4 + 2);
                mma16816(sacc[2*p],   ah, bl4);
                mma16816(sacc[2*p+1], ah, bl4 + 2);
            }
        }

        float mx0 = -1e30f, mx1 = -1e30f;
        #pragma unroll
        for (int nt = 0; nt < 4; nt++) {
            mx0 = fmaxf(mx0, fmaxf(sacc[nt][0], sacc[nt][1]));
            mx1 = fmaxf(mx1, fmaxf(sacc[nt][2], sacc[nt][3]));
        }
        mx0 = fmaxf(mx0, __shfl_xor_sync(0xffffffffu, mx0, 1));
        mx0 = fmaxf(mx0, __shfl_xor_sync(0xffffffffu, mx0, 2));
        mx1 = fmaxf(mx1, __shfl_xor_sync(0xffffffffu, mx1, 1));
        mx1 = fmaxf(mx1, __shfl_xor_sync(0xffffffffu, mx1, 2));
        float mn0 = fmaxf(m0, mx0), mn1 = fmaxf(m1, mx1);
        float corr0 = __expf(m0 - mn0), corr1 = __expf(m1 - mn1);
        m0 = mn0; m1 = mn1;

        int r0 = mw + (lid >> 2);
        uint32_t pcol = (uint32_t)((lid & 3) * 4);
        float sum0 = 0.f, sum1 = 0.f;
        #pragma unroll
        for (int nt = 0; nt < 4; nt++) {
            float p00 = __expf(sacc[nt][0] - mn0);
            float p01 = __expf(sacc[nt][1] - mn0);
            float p10 = __expf(sacc[nt][2] - mn1);
            float p11 = __expf(sacc[nt][3] - mn1);
            sum0 += p00 + p01; sum1 += p10 + p11;
            uint32_t off0 = (uint32_t)r0 * 80 + nt * 16 + pcol;
            bf162 h0 = mk2(p00, p01), h1 = mk2(p10, p11);
            *(bf162*)(smem + FPH + off0) = h0;
            *(bf162*)(smem + FPH + off0 + 8 * 80) = h1;
            *(bf162*)(smem + FPL + off0) =
                mk2(p00 - __bfloat162float(h0.x), p01 - __bfloat162float(h0.y));
            *(bf162*)(smem + FPL + off0 + 8 * 80) =
                mk2(p10 - __bfloat162float(h1.x), p11 - __bfloat162float(h1.y));
        }
        sum0 += __shfl_xor_sync(0xffffffffu, sum0, 1);
        sum0 += __shfl_xor_sync(0xffffffffu, sum0, 2);
        sum1 += __shfl_xor_sync(0xffffffffu, sum1, 1);
        sum1 += __shfl_xor_sync(0xffffffffu, sum1, 2);
        l0 = l0 * corr0 + sum0;
        l1 = l1 * corr1 + sum1;
        #pragma unroll
        for (int nt = 0; nt < 8; nt++) {
            oacc[nt][0] *= corr0; oacc[nt][1] *= corr0;
            oacc[nt][2] *= corr1; oacc[nt][3] *= corr1;
        }
        __syncwarp();

        #pragma unroll
        for (int ks = 0; ks < 2; ks++) {
            uint32_t ap[4], apl[4];
            uint32_t ra = sb + FPH + (uint32_t)(mw + (lid & 15)) * 80 +
                          ks * 32 + (lid >> 4) * 16;
            ldsm_x4(ap, ra);
            ldsm_x4(apl, ra + (FPL - FPH));
            #pragma unroll
            for (int p = 0; p < 4; p++) {
                uint32_t row = (uint32_t)(p * 16 + ((g >> 1) << 3) + (lid & 7));
                uint32_t rbadr = kvb + 9216 + row * 80 + ks * 32 + (g & 1) * 16;
                uint32_t bv4h[4], bv4l[4];
                ldsm_x4(bv4h, rbadr);
                ldsm_x4(bv4l, rbadr + 5120);
                mma16816(oacc[2*p],   ap,  bv4h);
                mma16816(oacc[2*p+1], ap,  bv4h + 2);
                mma16816(oacc[2*p],   apl, bv4h);
                mma16816(oacc[2*p+1], apl, bv4h + 2);
                mma16816(oacc[2*p],   ap,  bv4l);
                mma16816(oacc[2*p+1], ap,  bv4l + 2);
            }
        }
        __syncthreads();
    }

    float inv0 = 1.0f / l0, inv1 = 1.0f / l1;
    int s0 = qblk * 128 + mw + (lid >> 2);
    #pragma unroll
    for (int nt = 0; nt < 8; nt++) {
        int cidx = nt * 8 + (lid & 3) * 2;
        float v0 = oacc[nt][0] * inv0, v1 = oacc[nt][1] * inv0;
        float v2 = oacc[nt][2] * inv1, v3 = oacc[nt][3] * inv1;
        size_t base0 = ((size_t)b * S_ + s0) * D_ + h * 64 + cidx;
        size_t base1 = ((size_t)b * S_ + s0 + 8) * D_ + h * 64 + cidx;
        bf162 h0 = mk2(v0, v1), h1 = mk2(v2, v3);
        *(bf162*)(ctxh + base0) = h0;
        *(bf162*)(ctxh + base1) = h1;
        *(bf162*)(ctxl + base0) = mk2(v0 - __bfloat162float(h0.x),
                                      v1 - __bfloat162float(h0.y));
        *(bf162*)(ctxl + base1) = mk2(v2 - __bfloat162float(h1.x),
                                      v3 - __bfloat162float(h1.y));
    }
}

// ---------------------------------------------------------------------------
extern "C" void kernel_launch(void* const* d_in, const int* in_sizes, int n_in,
                              void* d_out, int out_size)
{
    const float* xq = (const float*)d_in[0];
    const float* xk = (const float*)d_in[1];
    const float* xv = (const float*)d_in[2];
    const float* Wq = (const float*)d_in[3];
    const float* bq = (const float*)d_in[4];
    const float* Wk = (const float*)d_in[5];
    const float* bk = (const float*)d_in[6];
    const float* Wv = (const float*)d_in[7];
    const float* bv = (const float*)d_in[8];
    const float* Wo = (const float*)d_in[9];
    const float* bo = (const float*)d_in[10];
    float* out = (float*)d_out;

    bf16 *qh, *ql, *kh, *kl, *vth, *vtl, *ctxh, *ctxl, *xh, *xl, *wh, *wl;
    cudaGetSymbolAddress((void**)&qh,   g_qh);
    cudaGetSymbolAddress((void**)&ql,   g_ql);
    cudaGetSymbolAddress((void**)&kh,   g_kh);
    cudaGetSymbolAddress((void**)&kl,   g_kl);
    cudaGetSymbolAddress((void**)&vth,  g_vth);
    cudaGetSymbolAddress((void**)&vtl,  g_vtl);
    cudaGetSymbolAddress((void**)&ctxh, g_ctxh);
    cudaGetSymbolAddress((void**)&ctxl, g_ctxl);
    cudaGetSymbolAddress((void**)&xh,   g_xh);
    cudaGetSymbolAddress((void**)&xl,   g_xl);
    cudaGetSymbolAddress((void**)&wh,   g_wh);
    cudaGetSymbolAddress((void**)&wl,   g_wl);

    static bool attr_done = false;
    if (!attr_done) {
        cudaFuncSetAttribute(qkv_gemm_kernel,
                             cudaFuncAttributeMaxDynamicSharedMemorySize, G_SMEM_TOTAL);
        cudaFuncSetAttribute(out_gemm_kernel,
                             cudaFuncAttributeMaxDynamicSharedMemorySize, G_SMEM_TOTAL);
        cudaFuncSetAttribute(flash_mma_kernel,
                             cudaFuncAttributeMaxDynamicSharedMemorySize, F_SMEM_TOTAL);
        attr_done = true;
    }

    const size_t DD = (size_t)D_ * D_;

    // Fused conversions
    convert_wT_kernel<<<dim3(32, 32, 4), dim3(32, 8)>>>(Wq, Wk, Wv, Wo, wh, wl);
    convert_hl_kernel<<<dim3(4096, 3), 256>>>(xq, xk, xv, xh, xl);

    // Fused Q/K/V projections (grid.z = 3)
    qkv_gemm_kernel<<<dim3(D_ / 128, M_ / 128, 3), 256, G_SMEM_TOTAL>>>(
        xh, xl, wh, wl, bq, bk, bv, qh, ql, kh, kl, vth, vtl);

    // Attention (outputs ctx bf16 hi/lo directly)
    flash_mma_kernel<<<dim3(S_ / 128, H_, B_), 256, F_SMEM_TOTAL>>>(
        qh, ql, kh, kl, vth, vtl, ctxh, ctxl);

    // Output projection (fp32 out)
    out_gemm_kernel<<<dim3(D_ / 128, M_ / 128), 256, G_SMEM_TOTAL>>>(
        ctxh, ctxl, wh + 3*DD, wl + 3*DD, bo, out);
}

// round 9
// speedup vs baseline: 2.9588x; 1.0395x over previous
#include <cuda_runtime.h>
#include <cuda_bf16.h>
#include <cstdint>
#include <math.h>

#define B_  2
#define S_  2048
#define D_  1024
#define H_  16
#define HD_ 64
#define M_  (B_*S_)   // 4096

typedef __nv_bfloat16 bf16;
typedef __nv_bfloat162 bf162;

// ---------------- scratch (__device__ globals; no allocs allowed) ----------
__device__ bf16 g_qh[(size_t)M_*D_];
__device__ bf16 g_ql[(size_t)M_*D_];
__device__ bf16 g_kh[(size_t)M_*D_];
__device__ bf16 g_kl[(size_t)M_*D_];
__device__ bf16 g_vth[(size_t)M_*D_];   // [B,H,HD,S]
__device__ bf16 g_vtl[(size_t)M_*D_];
__device__ bf16 g_ctxh[(size_t)M_*D_];  // [B,S,D]
__device__ bf16 g_ctxl[(size_t)M_*D_];
__device__ bf16 g_xh[(size_t)3*M_*D_];  // 3 inputs
__device__ bf16 g_xl[(size_t)3*M_*D_];
__device__ bf16 g_wh[(size_t)4*D_*D_];  // 4 weights (transposed)
__device__ bf16 g_wl[(size_t)4*D_*D_];

// ---------------- helpers ---------------------------------------------------
__device__ __forceinline__ uint32_t smem_u32(const void* p) {
    uint32_t a;
    asm("{ .reg .u64 t; cvta.to.shared.u64 t, %1; cvt.u32.u64 %0, t; }" : "=r"(a) : "l"(p));
    return a;
}
__device__ __forceinline__ void ldsm_x4(uint32_t* r, uint32_t addr) {
    asm volatile("ldmatrix.sync.aligned.m8n8.x4.shared.b16 {%0,%1,%2,%3}, [%4];"
                 : "=r"(r[0]), "=r"(r[1]), "=r"(r[2]), "=r"(r[3]) : "r"(addr));
}
__device__ __forceinline__ void mma16816(float* d, const uint32_t* a,
                                         const uint32_t* b) {
    asm volatile("mma.sync.aligned.m16n8k16.row.col.f32.bf16.bf16.f32 "
        "{%0,%1,%2,%3}, {%4,%5,%6,%7}, {%8,%9}, {%0,%1,%2,%3};"
        : "+f"(d[0]), "+f"(d[1]), "+f"(d[2]), "+f"(d[3])
        : "r"(a[0]), "r"(a[1]), "r"(a[2]), "r"(a[3]), "r"(b[0]), "r"(b[1]));
}
#define CP_ASYNC16(dst, src) \
    asm volatile("cp.async.cg.shared.global [%0], [%1], 16;" :: "r"(dst), "l"(src))
#define CP_COMMIT() asm volatile("cp.async.commit_group;" ::: "memory")
#define CP_WAIT1()  asm volatile("cp.async.wait_group 1;" ::: "memory")
#define CP_WAIT0()  asm volatile("cp.async.wait_group 0;" ::: "memory")

__device__ __forceinline__ void split_store(bf16* Yh, bf16* Yl, size_t idx, float v) {
    bf16 h = __float2bfloat16(v);
    Yh[idx] = h;
    Yl[idx] = __float2bfloat16(v - __bfloat162float(h));
}
__device__ __forceinline__ bf162 mk2(float a, float b) {
    bf162 r; r.x = __float2bfloat16(a); r.y = __float2bfloat16(b); return r;
}
__device__ __forceinline__ uint32_t pack_hi(float a, float b, uint32_t& lo) {
    bf162 h = mk2(a, b);
    bf162 l = mk2(a - __bfloat162float(h.x), b - __bfloat162float(h.y));
    lo = *(uint32_t*)&l;
    return *(uint32_t*)&h;
}

// ---------------------------------------------------------------------------
// Fused fp32 -> bf16 hi/lo split for 3 inputs (blockIdx.y selects input)
// ---------------------------------------------------------------------------
__global__ __launch_bounds__(256) void convert_hl_kernel(
    const float* __restrict__ X0, const float* __restrict__ X1,
    const float* __restrict__ X2, bf16* __restrict__ Xh, bf16* __restrict__ Xl)
{
    const float* Xs[3] = {X0, X1, X2};
    const float* X = Xs[blockIdx.y];
    size_t off2 = (size_t)blockIdx.y * (M_ * (size_t)D_ / 2);  // bf162 offset
    int i = blockIdx.x * blockDim.x + threadIdx.x;   // float4 index
    float4 x = ((const float4*)X)[i];
    bf16 h0 = __float2bfloat16(x.x), h1 = __float2bfloat16(x.y);
    bf16 h2 = __float2bfloat16(x.z), h3 = __float2bfloat16(x.w);
    bf162 ph0; ph0.x = h0; ph0.y = h1;
    bf162 ph1; ph1.x = h2; ph1.y = h3;
    bf162 pl0; pl0.x = __float2bfloat16(x.x - __bfloat162float(h0));
    pl0.y = __float2bfloat16(x.y - __bfloat162float(h1));
    bf162 pl1; pl1.x = __float2bfloat16(x.z - __bfloat162float(h2));
    pl1.y = __float2bfloat16(x.w - __bfloat162float(h3));
    ((bf162*)Xh)[off2 + 2*i]   = ph0;
    ((bf162*)Xh)[off2 + 2*i+1] = ph1;
    ((bf162*)Xl)[off2 + 2*i]   = pl0;
    ((bf162*)Xl)[off2 + 2*i+1] = pl1;
}

// ---------------------------------------------------------------------------
// Fused W [K,N] fp32 -> transposed Wt [N,K] bf16 hi/lo, 4 weights via blockIdx.z
// ---------------------------------------------------------------------------
__global__ __launch_bounds__(256) void convert_wT_kernel(
    const float* __restrict__ W0, const float* __restrict__ W1,
    const float* __restrict__ W2, const float* __restrict__ W3,
    bf16* __restrict__ Wth, bf16* __restrict__ Wtl)
{
    const float* Ws[4] = {W0, W1, W2, W3};
    const float* W = Ws[blockIdx.z];
    size_t off = (size_t)blockIdx.z * D_ * D_;
    __shared__ float t[32][33];
    int tx = threadIdx.x, ty = threadIdx.y;           // (32, 8)
    int n0 = blockIdx.x * 32, k0 = blockIdx.y * 32;
    #pragma unroll
    for (int i = 0; i < 4; i++)
        t[ty + 8*i][tx] = W[(size_t)(k0 + ty + 8*i) * D_ + n0 + tx];
    __syncthreads();
    #pragma unroll
    for (int i = 0; i < 4; i++) {
        float v = t[tx][ty + 8*i];
        split_store(Wth, Wtl, off + (size_t)(n0 + ty + 8*i) * D_ + k0 + tx, v);
    }
}

// ---------------------------------------------------------------------------
// Shared GEMM mainloop: acc[2][8][4] += A[128xK] @ B^T[128xK] for one CTA tile.
// CTA 128x128, 8 warps (warp tile 32x64), BK=32, cp.async double buffer.
// ---------------------------------------------------------------------------
#define GP 80                       // row pitch, bytes
#define TILE_BYTES 10240            // 128 * 80
#define BUF_BYTES  40960
#define G_SMEM_TOTAL (2 * BUF_BYTES)

__device__ __forceinline__ void gemm_core(
    uint32_t sb, const bf16* __restrict__ Ah, const bf16* __restrict__ Al,
    const bf16* __restrict__ Bh, const bf16* __restrict__ Bl,
    int m0, int n0, int tid, int wid, int lid, float acc[2][8][4])
{
    int wm = (wid >> 1) * 32, wn = (wid & 1) * 64;
    int g = lid >> 3;

    const bf16* srcs[4] = {Ah, Al, Bh, Bl};
    const int rbase[4] = {m0, m0, n0, n0};

    int slot_tile[8], slot_r[8], slot_q[8];
    #pragma unroll
    for (int it = 0; it < 8; it++) {
        int j = tid + it * 256;
        slot_tile[it] = j >> 9;
        int rem = j & 511;
        slot_r[it] = rem >> 2;
        slot_q[it] = rem & 3;
    }

    #pragma unroll
    for (int it = 0; it < 8; it++) {
        uint32_t dst = sb + slot_tile[it] * TILE_BYTES + slot_r[it] * GP + slot_q[it] * 16;
        const bf16* src = srcs[slot_tile[it]] +
            (size_t)(rbase[slot_tile[it]] + slot_r[it]) * D_ + slot_q[it] * 8;
        CP_ASYNC16(dst, src);
    }
    CP_COMMIT();

    for (int kc = 0; kc < 32; kc++) {
        int buf = kc & 1;
        uint32_t bufb = sb + buf * BUF_BYTES;
        if (kc + 1 < 32) {
            uint32_t ob = sb + (buf ^ 1) * BUF_BYTES;
            #pragma unroll
            for (int it = 0; it < 8; it++) {
                uint32_t dst = ob + slot_tile[it] * TILE_BYTES + slot_r[it] * GP + slot_q[it] * 16;
                const bf16* src = srcs[slot_tile[it]] +
                    (size_t)(rbase[slot_tile[it]] + slot_r[it]) * D_ + (kc + 1) * 32 + slot_q[it] * 8;
                CP_ASYNC16(dst, src);
            }
            CP_COMMIT();
            CP_WAIT1();
        } else {
            CP_WAIT0();
        }
        __syncthreads();

        #pragma unroll
        for (int ks = 0; ks < 2; ks++) {
            uint32_t ah[2][4], al[2][4];
            #pragma unroll
            for (int mt = 0; mt < 2; mt++) {
                uint32_t ra = (uint32_t)(wm + mt * 16 + (lid & 15)) * GP +
                              ks * 32 + (lid >> 4) * 16;
                ldsm_x4(ah[mt], bufb + 0 * TILE_BYTES + ra);
                ldsm_x4(al[mt], bufb + 1 * TILE_BYTES + ra);
            }
            #pragma unroll
            for (int p = 0; p < 4; p++) {
                uint32_t row = (uint32_t)(wn + p * 16 + ((g >> 1) << 3) + (lid & 7));
                uint32_t rbadr = row * GP + ks * 32 + (g & 1) * 16;
                uint32_t bh4[4], bl4[4];
                ldsm_x4(bh4, bufb + 2 * TILE_BYTES + rbadr);
                ldsm_x4(bl4, bufb + 3 * TILE_BYTES + rbadr);
                #pragma unroll
                for (int mt = 0; mt < 2; mt++) {
                    mma16816(acc[mt][2*p],   ah[mt], bh4);
                    mma16816(acc[mt][2*p+1], ah[mt], bh4 + 2);
                    mma16816(acc[mt][2*p],   al[mt], bh4);
                    mma16816(acc[mt][2*p+1], al[mt], bh4 + 2);
                    mma16816(acc[mt][2*p],   ah[mt], bl4);
                    mma16816(acc[mt][2*p+1], ah[mt], bl4 + 2);
                }
            }
        }
        __syncthreads();
    }
}

// ---------------------------------------------------------------------------
// Fused QKV projection: blockIdx.z in {0,1,2} -> Q (scaled, head-split),
// K (head-split), V (transposed head-split).
// ---------------------------------------------------------------------------
__global__ __launch_bounds__(256, 2) void qkv_gemm_kernel(
    const bf16* __restrict__ xh, const bf16* __restrict__ xl,
    const bf16* __restrict__ wh, const bf16* __restrict__ wl,
    const float* __restrict__ bq, const float* __restrict__ bk,
    const float* __restrict__ bv,
    bf16* __restrict__ qh, bf16* __restrict__ ql,
    bf16* __restrict__ kh, bf16* __restrict__ kl,
    bf16* __restrict__ vth, bf16* __restrict__ vtl)
{
    extern __shared__ char smem[];
    uint32_t sb = smem_u32(smem);
    int tid = threadIdx.x, wid = tid >> 5, lid = tid & 31;
    int m0 = blockIdx.y * 128, n0 = blockIdx.x * 128;
    int z = blockIdx.z;
    const size_t MD = (size_t)M_ * D_, DD = (size_t)D_ * D_;

    const bf16* Ah = xh + (size_t)z * MD;
    const bf16* Al = xl + (size_t)z * MD;
    const bf16* Bh = wh + (size_t)z * DD;
    const bf16* Bl = wl + (size_t)z * DD;
    const float* bias = (z == 0) ? bq : (z == 1) ? bk : bv;
    float scale = (z == 0) ? 0.125f : 1.0f;

    float acc[2][8][4];
    #pragma unroll
    for (int mt = 0; mt < 2; mt++)
        #pragma unroll
        for (int nt = 0; nt < 8; nt++)
            #pragma unroll
            for (int c = 0; c < 4; c++) acc[mt][nt][c] = 0.f;

    gemm_core(sb, Ah, Al, Bh, Bl, m0, n0, tid, wid, lid, acc);

    int wm = (wid >> 1) * 32, wn = (wid & 1) * 64;
    #pragma unroll
    for (int mt = 0; mt < 2; mt++) {
        #pragma unroll
        for (int nt = 0; nt < 8; nt++) {
            int mA = m0 + wm + mt * 16 + (lid >> 2);
            int nA = n0 + wn + nt * 8 + (lid & 3) * 2;
            float b0 = bias[nA], b1 = bias[nA + 1];
            float v0 = (acc[mt][nt][0] + b0) * scale;
            float v1 = (acc[mt][nt][1] + b1) * scale;
            float v2 = (acc[mt][nt][2] + b0) * scale;
            float v3 = (acc[mt][nt][3] + b1) * scale;
            int h = nA >> 6, hd = nA & 63;
            int b = mA >> 11, s = mA & (S_ - 1);
            if (z < 2) {
                bf16* Yh = (z == 0) ? qh : kh;
                bf16* Yl = (z == 0) ? ql : kl;
                size_t base0 = (((size_t)(b * H_ + h)) * S_ + s) * HD_ + hd;
                size_t base1 = (((size_t)(b * H_ + h)) * S_ + (s + 8)) * HD_ + hd;
                bf162 h0 = mk2(v0, v1), h1 = mk2(v2, v3);
                *(bf162*)(Yh + base0) = h0;
                *(bf162*)(Yh + base1) = h1;
                *(bf162*)(Yl + base0) = mk2(v0 - __bfloat162float(h0.x),
                                            v1 - __bfloat162float(h0.y));
                *(bf162*)(Yl + base1) = mk2(v2 - __bfloat162float(h1.x),
                                            v3 - __bfloat162float(h1.y));
            } else {
                size_t rb = (size_t)(b * H_ + h) * HD_;
                split_store(vth, vtl, (rb + hd)     * S_ + s,     v0);
                split_store(vth, vtl, (rb + hd + 1) * S_ + s,     v1);
                split_store(vth, vtl, (rb + hd)     * S_ + s + 8, v2);
                split_store(vth, vtl, (rb + hd + 1) * S_ + s + 8, v3);
            }
        }
    }
}

// ---------------------------------------------------------------------------
// O-projection GEMM (fp32 row-major out)
// ---------------------------------------------------------------------------
__global__ __launch_bounds__(256, 2) void out_gemm_kernel(
    const bf16* __restrict__ Ah, const bf16* __restrict__ Al,
    const bf16* __restrict__ Bh, const bf16* __restrict__ Bl,
    const float* __restrict__ bias, float* __restrict__ Y)
{
    extern __shared__ char smem[];
    uint32_t sb = smem_u32(smem);
    int tid = threadIdx.x, wid = tid >> 5, lid = tid & 31;
    int m0 = blockIdx.y * 128, n0 = blockIdx.x * 128;

    float acc[2][8][4];
    #pragma unroll
    for (int mt = 0; mt < 2; mt++)
        #pragma unroll
        for (int nt = 0; nt < 8; nt++)
            #pragma unroll
            for (int c = 0; c < 4; c++) acc[mt][nt][c] = 0.f;

    gemm_core(sb, Ah, Al, Bh, Bl, m0, n0, tid, wid, lid, acc);

    int wm = (wid >> 1) * 32, wn = (wid & 1) * 64;
    #pragma unroll
    for (int mt = 0; mt < 2; mt++) {
        #pragma unroll
        for (int nt = 0; nt < 8; nt++) {
            int mA = m0 + wm + mt * 16 + (lid >> 2);
            int nA = n0 + wn + nt * 8 + (lid & 3) * 2;
            float b0 = bias[nA], b1 = bias[nA + 1];
            *(float2*)(Y + (size_t)mA * D_ + nA) =
                make_float2(acc[mt][nt][0] + b0, acc[mt][nt][1] + b1);
            *(float2*)(Y + (size_t)(mA + 8) * D_ + nA) =
                make_float2(acc[mt][nt][2] + b0, acc[mt][nt][3] + b1);
        }
    }
}

// ---------------------------------------------------------------------------
// Flash attention via mma.sync. CTA = 128 q-rows x (b,h). 8 warps x 16 rows.
// Bc=32 kv tiles, double-buffered cp.async.
// P kept in REGISTERS as mma A-fragments (D-layout == A-layout trick):
// no P smem round trip. smem 74KB -> 2 CTAs/SM with lower L1 traffic.
// Layout: Qh@0(18432) Ql@18432 | KV buf{0,1}@36864+buf*19456:
//   Kh@+0(4608,pitch144) Kl@+4608 Vth@+9216(5120,pitch80) Vtl@+14336
// ---------------------------------------------------------------------------
#define FQL  18432
#define FKV  36864
#define FKVB 19456
#define F_SMEM_TOTAL 75776

__device__ __forceinline__ void flash_issue_kv(
    uint32_t sb, int buf, int kt, size_t bh, int tid,
    const bf16* kh, const bf16* kl, const bf16* vth, const bf16* vtl)
{
    uint32_t kvbase = sb + FKV + buf * FKVB;
    #pragma unroll
    for (int it = 0; it < 4; it++) {
        int j = tid + it * 256;
        int sub = j >> 8, rem = j & 255;
        uint32_t dst; const bf16* src;
        if (sub < 2) {
            int r = rem >> 3, c = rem & 7;
            dst = kvbase + sub * 4608 + r * 144 + c * 16;
            src = (sub ? kl : kh) + (bh * S_ + (size_t)kt * 32 + r) * HD_ + c * 8;
        } else {
            int r = rem >> 2, c = rem & 3;
            dst = kvbase + 9216 + (sub - 2) * 5120 + r * 80 + c * 16;
            src = (sub == 2 ? vth : vtl) + (bh * HD_ + r) * S_ + kt * 32 + c * 8;
        }
        CP_ASYNC16(dst, src);
    }
    CP_COMMIT();
}

__global__ __launch_bounds__(256, 2) void flash_mma_kernel(
    const bf16* __restrict__ qh, const bf16* __restrict__ ql,
    const bf16* __restrict__ kh, const bf16* __restrict__ kl,
    const bf16* __restrict__ vth, const bf16* __restrict__ vtl,
    bf16* __restrict__ ctxh, bf16* __restrict__ ctxl)
{
    extern __shared__ char smem[];
    uint32_t sb = smem_u32(smem);

    int tid = threadIdx.x, wid = tid >> 5, lid = tid & 31;
    int qblk = blockIdx.x, h = blockIdx.y, b = blockIdx.z;
    size_t bh = (size_t)(b * H_ + h);
    int mw = wid * 16;
    int g = lid >> 3;

    #pragma unroll
    for (int it = 0; it < 8; it++) {
        int j = tid + it * 256;
        int sub = j >> 10, rem = j & 1023, r = rem >> 3, c = rem & 7;
        uint32_t dst = sb + sub * 18432 + r * 144 + c * 16;
        const bf16* src = (sub ? ql : qh) +
            (bh * S_ + (size_t)qblk * 128 + r) * HD_ + c * 8;
        CP_ASYNC16(dst, src);
    }
    CP_COMMIT();
    flash_issue_kv(sb, 0, 0, bh, tid, kh, kl, vth, vtl);

    float m0 = -1e30f, m1 = -1e30f, l0 = 0.f, l1 = 0.f;
    float oacc[8][4];
    #pragma unroll
    for (int nt = 0; nt < 8; nt++)
        #pragma unroll
        for (int c = 0; c < 4; c++) oacc[nt][c] = 0.f;

    const int NT = S_ / 32;   // 64 kv tiles
    for (int kt = 0; kt < NT; kt++) {
        int buf = kt & 1;
        if (kt + 1 < NT) {
            flash_issue_kv(sb, buf ^ 1, kt + 1, bh, tid, kh, kl, vth, vtl);
            CP_WAIT1();
        } else {
            CP_WAIT0();
        }
        __syncthreads();
        uint32_t kvb = sb + FKV + buf * FKVB;

        // ---- S = Q K^T (3-term split): warp rows mw..mw+15, kv cols 0..31
        float sacc[4][4];
        #pragma unroll
        for (int nt = 0; nt < 4; nt++)
            #pragma unroll
            for (int c = 0; c < 4; c++) sacc[nt][c] = 0.f;

        #pragma unroll
        for (int ks = 0; ks < 4; ks++) {
            uint32_t ah[4], al[4];
            uint32_t ra = sb + (uint32_t)(mw + (lid & 15)) * 144 +
                          ks * 32 + (lid >> 4) * 16;
            ldsm_x4(ah, ra);
            ldsm_x4(al, ra + FQL);
            #pragma unroll
            for (int p = 0; p < 2; p++) {
                uint32_t row = (uint32_t)(p * 16 + ((g >> 1) << 3) + (lid & 7));
                uint32_t rbadr = kvb + row * 144 + ks * 32 + (g & 1) * 16;
                uint32_t bh4[4], bl4[4];
                ldsm_x4(bh4, rbadr);
                ldsm_x4(bl4, rbadr + 4608);
                mma16816(sacc[2*p],   ah, bh4);
                mma16816(sacc[2*p+1], ah, bh4 + 2);
                mma16816(sacc[2*p],   al, bh4);
                mma16816(sacc[2*p+1], al, bh4 + 2);
                mma16816(sacc[2*p],   ah, bl4);
                mma16816(sacc[2*p+1], ah, bl4 + 2);
            }
        }

        // ---- online softmax; regs [0,1] -> row mw+lid/4; [2,3] -> +8
        float mx0 = -1e30f, mx1 = -1e30f;
        #pragma unroll
        for (int nt = 0; nt < 4; nt++) {
            mx0 = fmaxf(mx0, fmaxf(sacc[nt][0], sacc[nt][1]));
            mx1 = fmaxf(mx1, fmaxf(sacc[nt][2], sacc[nt][3]));
        }
        mx0 = fmaxf(mx0, __shfl_xor_sync(0xffffffffu, mx0, 1));
        mx0 = fmaxf(mx0, __shfl_xor_sync(0xffffffffu, mx0, 2));
        mx1 = fmaxf(mx1, __shfl_xor_sync(0xffffffffu, mx1, 1));
        mx1 = fmaxf(mx1, __shfl_xor_sync(0xffffffffu, mx1, 2));
        float mn0 = fmaxf(m0, mx0), mn1 = fmaxf(m1, mx1);
        float corr0 = __expf(m0 - mn0), corr1 = __expf(m1 - mn1);
        m0 = mn0; m1 = mn1;

        // ---- exp + pack P directly as mma A-fragments (hi/lo), in registers
        // tile nt (kv cols nt*8..+7): ks = nt>>1; frag idx base = (nt&1)*2;
        // [base] = rows 0-7 (d0,d1), [base+1] = rows 8-15 (d2,d3)
        uint32_t pfh[2][4], pfl[2][4];
        float sum0 = 0.f, sum1 = 0.f;
        #pragma unroll
        for (int nt = 0; nt < 4; nt++) {
            float p00 = __expf(sacc[nt][0] - mn0);
            float p01 = __expf(sacc[nt][1] - mn0);
            float p10 = __expf(sacc[nt][2] - mn1);
            float p11 = __expf(sacc[nt][3] - mn1);
            sum0 += p00 + p01; sum1 += p10 + p11;
            int ks = nt >> 1, base = (nt & 1) * 2;
            pfh[ks][base]     = pack_hi(p00, p01, pfl[ks][base]);
            pfh[ks][base + 1] = pack_hi(p10, p11, pfl[ks][base + 1]);
        }
        sum0 += __shfl_xor_sync(0xffffffffu, sum0, 1);
        sum0 += __shfl_xor_sync(0xffffffffu, sum0, 2);
        sum1 += __shfl_xor_sync(0xffffffffu, sum1, 1);
        sum1 += __shfl_xor_sync(0xffffffffu, sum1, 2);
        l0 = l0 * corr0 + sum0;
        l1 = l1 * corr1 + sum1;
        #pragma unroll
        for (int nt = 0; nt < 8; nt++) {
            oacc[nt][0] *= corr0; oacc[nt][1] *= corr0;
            oacc[nt][2] *= corr1; oacc[nt][3] *= corr1;
        }

        // ---- O += P V  (A = P register fragments, B = Vt [hd rows][kv cols])
        #pragma unroll
        for (int ks = 0; ks < 2; ks++) {
            #pragma unroll
            for (int p = 0; p < 4; p++) {
                uint32_t row = (uint32_t)(p * 16 + ((g >> 1) << 3) + (lid & 7));
                uint32_t rbadr = kvb + 9216 + row * 80 + ks * 32 + (g & 1) * 16;
                uint32_t bv4h[4], bv4l[4];
                ldsm_x4(bv4h, rbadr);
                ldsm_x4(bv4l, rbadr + 5120);
                mma16816(oacc[2*p],   pfh[ks], bv4h);
                mma16816(oacc[2*p+1], pfh[ks], bv4h + 2);
                mma16816(oacc[2*p],   pfl[ks], bv4h);
                mma16816(oacc[2*p+1], pfl[ks], bv4h + 2);
                mma16816(oacc[2*p],   pfh[ks], bv4l);
                mma16816(oacc[2*p+1], pfh[ks], bv4l + 2);
            }
        }
        __syncthreads();
    }

    // ---- epilogue: ctx[b, s, h*64+hd] bf16 hi/lo
    float inv0 = 1.0f / l0, inv1 = 1.0f / l1;
    int s0 = qblk * 128 + mw + (lid >> 2);
    #pragma unroll
    for (int nt = 0; nt < 8; nt++) {
        int cidx = nt * 8 + (lid & 3) * 2;
        float v0 = oacc[nt][0] * inv0, v1 = oacc[nt][1] * inv0;
        float v2 = oacc[nt][2] * inv1, v3 = oacc[nt][3] * inv1;
        size_t base0 = ((size_t)b * S_ + s0) * D_ + h * 64 + cidx;
        size_t base1 = ((size_t)b * S_ + s0 + 8) * D_ + h * 64 + cidx;
        bf162 h0 = mk2(v0, v1), h1 = mk2(v2, v3);
        *(bf162*)(ctxh + base0) = h0;
        *(bf162*)(ctxh + base1) = h1;
        *(bf162*)(ctxl + base0) = mk2(v0 - __bfloat162float(h0.x),
                                      v1 - __bfloat162float(h0.y));
        *(bf162*)(ctxl + base1) = mk2(v2 - __bfloat162float(h1.x),
                                      v3 - __bfloat162float(h1.y));
    }
}

// ---------------------------------------------------------------------------
extern "C" void kernel_launch(void* const* d_in, const int* in_sizes, int n_in,
                              void* d_out, int out_size)
{
    const float* xq = (const float*)d_in[0];
    const float* xk = (const float*)d_in[1];
    const float* xv = (const float*)d_in[2];
    const float* Wq = (const float*)d_in[3];
    const float* bq = (const float*)d_in[4];
    const float* Wk = (const float*)d_in[5];
    const float* bk = (const float*)d_in[6];
    const float* Wv = (const float*)d_in[7];
    const float* bv = (const float*)d_in[8];
    const float* Wo = (const float*)d_in[9];
    const float* bo = (const float*)d_in[10];
    float* out = (float*)d_out;

    bf16 *qh, *ql, *kh, *kl, *vth, *vtl, *ctxh, *ctxl, *xh, *xl, *wh, *wl;
    cudaGetSymbolAddress((void**)&qh,   g_qh);
    cudaGetSymbolAddress((void**)&ql,   g_ql);
    cudaGetSymbolAddress((void**)&kh,   g_kh);
    cudaGetSymbolAddress((void**)&kl,   g_kl);
    cudaGetSymbolAddress((void**)&vth,  g_vth);
    cudaGetSymbolAddress((void**)&vtl,  g_vtl);
    cudaGetSymbolAddress((void**)&ctxh, g_ctxh);
    cudaGetSymbolAddress((void**)&ctxl, g_ctxl);
    cudaGetSymbolAddress((void**)&xh,   g_xh);
    cudaGetSymbolAddress((void**)&xl,   g_xl);
    cudaGetSymbolAddress((void**)&wh,   g_wh);
    cudaGetSymbolAddress((void**)&wl,   g_wl);

    static bool attr_done = false;
    if (!attr_done) {
        cudaFuncSetAttribute(qkv_gemm_kernel,
                             cudaFuncAttributeMaxDynamicSharedMemorySize, G_SMEM_TOTAL);
        cudaFuncSetAttribute(out_gemm_kernel,
                             cudaFuncAttributeMaxDynamicSharedMemorySize, G_SMEM_TOTAL);
        cudaFuncSetAttribute(flash_mma_kernel,
                             cudaFuncAttributeMaxDynamicSharedMemorySize, F_SMEM_TOTAL);
        attr_done = true;
    }

    const size_t DD = (size_t)D_ * D_;

    // Fused conversions
    convert_wT_kernel<<<dim3(32, 32, 4), dim3(32, 8)>>>(Wq, Wk, Wv, Wo, wh, wl);
    convert_hl_kernel<<<dim3(4096, 3), 256>>>(xq, xk, xv, xh, xl);

    // Fused Q/K/V projections (grid.z = 3)
    qkv_gemm_kernel<<<dim3(D_ / 128, M_ / 128, 3), 256, G_SMEM_TOTAL>>>(
        xh, xl, wh, wl, bq, bk, bv, qh, ql, kh, kl, vth, vtl);

    // Attention (outputs ctx bf16 hi/lo directly)
    flash_mma_kernel<<<dim3(S_ / 128, H_, B_), 256, F_SMEM_TOTAL>>>(
        qh, ql, kh, kl, vth, vtl, ctxh, ctxl);

    // Output projection (fp32 out)
    out_gemm_kernel<<<dim3(D_ / 128, M_ / 128), 256, G_SMEM_TOTAL>>>(
        ctxh, ctxl, wh + 3*DD, wl + 3*DD, bo, out);
}

// round 10
// speedup vs baseline: 3.0967x; 1.0466x over previous
#include <cuda_runtime.h>
#include <cuda_bf16.h>
#include <cstdint>
#include <math.h>

#define B_  2
#define S_  2048
#define D_  1024
#define H_  16
#define HD_ 64
#define M_  (B_*S_)   // 4096

typedef __nv_bfloat16 bf16;
typedef __nv_bfloat162 bf162;

// ---------------- scratch (__device__ globals; no allocs allowed) ----------
__device__ bf16 g_qh[(size_t)M_*D_];
__device__ bf16 g_ql[(size_t)M_*D_];
__device__ bf16 g_kh[(size_t)M_*D_];
__device__ bf16 g_kl[(size_t)M_*D_];
__device__ bf16 g_vth[(size_t)M_*D_];   // [B,H,HD,S]
__device__ bf16 g_vtl[(size_t)M_*D_];
__device__ bf16 g_ctxh[(size_t)M_*D_];  // [B,S,D]
__device__ bf16 g_ctxl[(size_t)M_*D_];
__device__ bf16 g_xh[(size_t)3*M_*D_];  // 3 inputs
__device__ bf16 g_xl[(size_t)3*M_*D_];
__device__ bf16 g_wh[(size_t)4*D_*D_];  // 4 weights (transposed)
__device__ bf16 g_wl[(size_t)4*D_*D_];

// ---------------- helpers ---------------------------------------------------
__device__ __forceinline__ uint32_t smem_u32(const void* p) {
    uint32_t a;
    asm("{ .reg .u64 t; cvta.to.shared.u64 t, %1; cvt.u32.u64 %0, t; }" : "=r"(a) : "l"(p));
    return a;
}
__device__ __forceinline__ void ldsm_x4(uint32_t* r, uint32_t addr) {
    asm volatile("ldmatrix.sync.aligned.m8n8.x4.shared.b16 {%0,%1,%2,%3}, [%4];"
                 : "=r"(r[0]), "=r"(r[1]), "=r"(r[2]), "=r"(r[3]) : "r"(addr));
}
__device__ __forceinline__ void mma16816(float* d, const uint32_t* a,
                                         const uint32_t* b) {
    asm volatile("mma.sync.aligned.m16n8k16.row.col.f32.bf16.bf16.f32 "
        "{%0,%1,%2,%3}, {%4,%5,%6,%7}, {%8,%9}, {%0,%1,%2,%3};"
        : "+f"(d[0]), "+f"(d[1]), "+f"(d[2]), "+f"(d[3])
        : "r"(a[0]), "r"(a[1]), "r"(a[2]), "r"(a[3]), "r"(b[0]), "r"(b[1]));
}
#define CP_ASYNC16(dst, src) \
    asm volatile("cp.async.cg.shared.global [%0], [%1], 16;" :: "r"(dst), "l"(src))
#define CP_COMMIT() asm volatile("cp.async.commit_group;" ::: "memory")
#define CP_WAIT0()  asm volatile("cp.async.wait_group 0;" ::: "memory")

__device__ __forceinline__ void split_store(bf16* Yh, bf16* Yl, size_t idx, float v) {
    bf16 h = __float2bfloat16(v);
    Yh[idx] = h;
    Yl[idx] = __float2bfloat16(v - __bfloat162float(h));
}
__device__ __forceinline__ bf162 mk2(float a, float b) {
    bf162 r; r.x = __float2bfloat16(a); r.y = __float2bfloat16(b); return r;
}
__device__ __forceinline__ uint32_t pack_hi(float a, float b, uint32_t& lo) {
    bf162 h = mk2(a, b);
    bf162 l = mk2(a - __bfloat162float(h.x), b - __bfloat162float(h.y));
    lo = *(uint32_t*)&l;
    return *(uint32_t*)&h;
}

// ---------------------------------------------------------------------------
// Fused fp32 -> bf16 hi/lo split for 3 inputs (blockIdx.y selects input)
// ---------------------------------------------------------------------------
__global__ __launch_bounds__(256) void convert_hl_kernel(
    const float* __restrict__ X0, const float* __restrict__ X1,
    const float* __restrict__ X2, bf16* __restrict__ Xh, bf16* __restrict__ Xl)
{
    const float* Xs[3] = {X0, X1, X2};
    const float* X = Xs[blockIdx.y];
    size_t off2 = (size_t)blockIdx.y * (M_ * (size_t)D_ / 2);  // bf162 offset
    int i = blockIdx.x * blockDim.x + threadIdx.x;   // float4 index
    float4 x = ((const float4*)X)[i];
    bf16 h0 = __float2bfloat16(x.x), h1 = __float2bfloat16(x.y);
    bf16 h2 = __float2bfloat16(x.z), h3 = __float2bfloat16(x.w);
    bf162 ph0; ph0.x = h0; ph0.y = h1;
    bf162 ph1; ph1.x = h2; ph1.y = h3;
    bf162 pl0; pl0.x = __float2bfloat16(x.x - __bfloat162float(h0));
    pl0.y = __float2bfloat16(x.y - __bfloat162float(h1));
    bf162 pl1; pl1.x = __float2bfloat16(x.z - __bfloat162float(h2));
    pl1.y = __float2bfloat16(x.w - __bfloat162float(h3));
    ((bf162*)Xh)[off2 + 2*i]   = ph0;
    ((bf162*)Xh)[off2 + 2*i+1] = ph1;
    ((bf162*)Xl)[off2 + 2*i]   = pl0;
    ((bf162*)Xl)[off2 + 2*i+1] = pl1;
}

// ---------------------------------------------------------------------------
// Fused W [K,N] fp32 -> transposed Wt [N,K] bf16 hi/lo, 4 weights via blockIdx.z
// ---------------------------------------------------------------------------
__global__ __launch_bounds__(256) void convert_wT_kernel(
    const float* __restrict__ W0, const float* __restrict__ W1,
    const float* __restrict__ W2, const float* __restrict__ W3,
    bf16* __restrict__ Wth, bf16* __restrict__ Wtl)
{
    const float* Ws[4] = {W0, W1, W2, W3};
    const float* W = Ws[blockIdx.z];
    size_t off = (size_t)blockIdx.z * D_ * D_;
    __shared__ float t[32][33];
    int tx = threadIdx.x, ty = threadIdx.y;           // (32, 8)
    int n0 = blockIdx.x * 32, k0 = blockIdx.y * 32;
    #pragma unroll
    for (int i = 0; i < 4; i++)
        t[ty + 8*i][tx] = W[(size_t)(k0 + ty + 8*i) * D_ + n0 + tx];
    __syncthreads();
    #pragma unroll
    for (int i = 0; i < 4; i++) {
        float v = t[tx][ty + 8*i];
        split_store(Wth, Wtl, off + (size_t)(n0 + ty + 8*i) * D_ + k0 + tx, v);
    }
}

// ---------------------------------------------------------------------------
// Shared GEMM mainloop: acc[2][8][4] += A[128xK] @ B^T[128xK] for one CTA tile.
// CTA 128x128, 8 warps (warp tile 32x64), BK=32, cp.async double buffer.
// Single __syncthreads per k-chunk: wait -> sync -> issue next -> compute.
// ---------------------------------------------------------------------------
#define GP 80                       // row pitch, bytes
#define TILE_BYTES 10240            // 128 * 80
#define BUF_BYTES  40960
#define G_SMEM_TOTAL (2 * BUF_BYTES)

__device__ __forceinline__ void gemm_core(
    uint32_t sb, const bf16* __restrict__ Ah, const bf16* __restrict__ Al,
    const bf16* __restrict__ Bh, const bf16* __restrict__ Bl,
    int m0, int n0, int tid, int wid, int lid, float acc[2][8][4])
{
    int wm = (wid >> 1) * 32, wn = (wid & 1) * 64;
    int g = lid >> 3;

    const bf16* srcs[4] = {Ah, Al, Bh, Bl};
    const int rbase[4] = {m0, m0, n0, n0};

    int slot_tile[8], slot_r[8], slot_q[8];
    #pragma unroll
    for (int it = 0; it < 8; it++) {
        int j = tid + it * 256;
        slot_tile[it] = j >> 9;
        int rem = j & 511;
        slot_r[it] = rem >> 2;
        slot_q[it] = rem & 3;
    }

    // prologue: chunk 0 -> buf 0
    #pragma unroll
    for (int it = 0; it < 8; it++) {
        uint32_t dst = sb + slot_tile[it] * TILE_BYTES + slot_r[it] * GP + slot_q[it] * 16;
        const bf16* src = srcs[slot_tile[it]] +
            (size_t)(rbase[slot_tile[it]] + slot_r[it]) * D_ + slot_q[it] * 8;
        CP_ASYNC16(dst, src);
    }
    CP_COMMIT();

    for (int kc = 0; kc < 32; kc++) {
        CP_WAIT0();
        __syncthreads();      // data visible + all warps done with buf being refilled
        if (kc + 1 < 32) {
            uint32_t ob = sb + ((kc + 1) & 1) * BUF_BYTES;
            #pragma unroll
            for (int it = 0; it < 8; it++) {
                uint32_t dst = ob + slot_tile[it] * TILE_BYTES + slot_r[it] * GP + slot_q[it] * 16;
                const bf16* src = srcs[slot_tile[it]] +
                    (size_t)(rbase[slot_tile[it]] + slot_r[it]) * D_ + (kc + 1) * 32 + slot_q[it] * 8;
                CP_ASYNC16(dst, src);
            }
            CP_COMMIT();
        }
        uint32_t bufb = sb + (kc & 1) * BUF_BYTES;

        #pragma unroll
        for (int ks = 0; ks < 2; ks++) {
            uint32_t ah[2][4], al[2][4];
            #pragma unroll
            for (int mt = 0; mt < 2; mt++) {
                uint32_t ra = (uint32_t)(wm + mt * 16 + (lid & 15)) * GP +
                              ks * 32 + (lid >> 4) * 16;
                ldsm_x4(ah[mt], bufb + 0 * TILE_BYTES + ra);
                ldsm_x4(al[mt], bufb + 1 * TILE_BYTES + ra);
            }
            #pragma unroll
            for (int p = 0; p < 4; p++) {
                uint32_t row = (uint32_t)(wn + p * 16 + ((g >> 1) << 3) + (lid & 7));
                uint32_t rbadr = row * GP + ks * 32 + (g & 1) * 16;
                uint32_t bh4[4], bl4[4];
                ldsm_x4(bh4, bufb + 2 * TILE_BYTES + rbadr);
                ldsm_x4(bl4, bufb + 3 * TILE_BYTES + rbadr);
                #pragma unroll
                for (int mt = 0; mt < 2; mt++) {
                    mma16816(acc[mt][2*p],   ah[mt], bh4);
                    mma16816(acc[mt][2*p+1], ah[mt], bh4 + 2);
                    mma16816(acc[mt][2*p],   al[mt], bh4);
                    mma16816(acc[mt][2*p+1], al[mt], bh4 + 2);
                    mma16816(acc[mt][2*p],   ah[mt], bl4);
                    mma16816(acc[mt][2*p+1], ah[mt], bl4 + 2);
                }
            }
        }
    }
}

// ---------------------------------------------------------------------------
// Fused QKV projection: blockIdx.z in {0,1,2} -> Q (scaled, head-split),
// K (head-split), V (transposed head-split).
// ---------------------------------------------------------------------------
__global__ __launch_bounds__(256, 2) void qkv_gemm_kernel(
    const bf16* __restrict__ xh, const bf16* __restrict__ xl,
    const bf16* __restrict__ wh, const bf16* __restrict__ wl,
    const float* __restrict__ bq, const float* __restrict__ bk,
    const float* __restrict__ bv,
    bf16* __restrict__ qh, bf16* __restrict__ ql,
    bf16* __restrict__ kh, bf16* __restrict__ kl,
    bf16* __restrict__ vth, bf16* __restrict__ vtl)
{
    extern __shared__ char smem[];
    uint32_t sb = smem_u32(smem);
    int tid = threadIdx.x, wid = tid >> 5, lid = tid & 31;
    int m0 = blockIdx.y * 128, n0 = blockIdx.x * 128;
    int z = blockIdx.z;
    const size_t MD = (size_t)M_ * D_, DD = (size_t)D_ * D_;

    const bf16* Ah = xh + (size_t)z * MD;
    const bf16* Al = xl + (size_t)z * MD;
    const bf16* Bh = wh + (size_t)z * DD;
    const bf16* Bl = wl + (size_t)z * DD;
    const float* bias = (z == 0) ? bq : (z == 1) ? bk : bv;
    float scale = (z == 0) ? 0.125f : 1.0f;

    float acc[2][8][4];
    #pragma unroll
    for (int mt = 0; mt < 2; mt++)
        #pragma unroll
        for (int nt = 0; nt < 8; nt++)
            #pragma unroll
            for (int c = 0; c < 4; c++) acc[mt][nt][c] = 0.f;

    gemm_core(sb, Ah, Al, Bh, Bl, m0, n0, tid, wid, lid, acc);

    int wm = (wid >> 1) * 32, wn = (wid & 1) * 64;
    #pragma unroll
    for (int mt = 0; mt < 2; mt++) {
        #pragma unroll
        for (int nt = 0; nt < 8; nt++) {
            int mA = m0 + wm + mt * 16 + (lid >> 2);
            int nA = n0 + wn + nt * 8 + (lid & 3) * 2;
            float b0 = bias[nA], b1 = bias[nA + 1];
            float v0 = (acc[mt][nt][0] + b0) * scale;
            float v1 = (acc[mt][nt][1] + b1) * scale;
            float v2 = (acc[mt][nt][2] + b0) * scale;
            float v3 = (acc[mt][nt][3] + b1) * scale;
            int h = nA >> 6, hd = nA & 63;
            int b = mA >> 11, s = mA & (S_ - 1);
            if (z < 2) {
                bf16* Yh = (z == 0) ? qh : kh;
                bf16* Yl = (z == 0) ? ql : kl;
                size_t base0 = (((size_t)(b * H_ + h)) * S_ + s) * HD_ + hd;
                size_t base1 = (((size_t)(b * H_ + h)) * S_ + (s + 8)) * HD_ + hd;
                bf162 h0 = mk2(v0, v1), h1 = mk2(v2, v3);
                *(bf162*)(Yh + base0) = h0;
                *(bf162*)(Yh + base1) = h1;
                *(bf162*)(Yl + base0) = mk2(v0 - __bfloat162float(h0.x),
                                            v1 - __bfloat162float(h0.y));
                *(bf162*)(Yl + base1) = mk2(v2 - __bfloat162float(h1.x),
                                            v3 - __bfloat162float(h1.y));
            } else {
                size_t rb = (size_t)(b * H_ + h) * HD_;
                split_store(vth, vtl, (rb + hd)     * S_ + s,     v0);
                split_store(vth, vtl, (rb + hd + 1) * S_ + s,     v1);
                split_store(vth, vtl, (rb + hd)     * S_ + s + 8, v2);
                split_store(vth, vtl, (rb + hd + 1) * S_ + s + 8, v3);
            }
        }
    }
}

// ---------------------------------------------------------------------------
// O-projection GEMM (fp32 row-major out)
// ---------------------------------------------------------------------------
__global__ __launch_bounds__(256, 2) void out_gemm_kernel(
    const bf16* __restrict__ Ah, const bf16* __restrict__ Al,
    const bf16* __restrict__ Bh, const bf16* __restrict__ Bl,
    const float* __restrict__ bias, float* __restrict__ Y)
{
    extern __shared__ char smem[];
    uint32_t sb = smem_u32(smem);
    int tid = threadIdx.x, wid = tid >> 5, lid = tid & 31;
    int m0 = blockIdx.y * 128, n0 = blockIdx.x * 128;

    float acc[2][8][4];
    #pragma unroll
    for (int mt = 0; mt < 2; mt++)
        #pragma unroll
        for (int nt = 0; nt < 8; nt++)
            #pragma unroll
            for (int c = 0; c < 4; c++) acc[mt][nt][c] = 0.f;

    gemm_core(sb, Ah, Al, Bh, Bl, m0, n0, tid, wid, lid, acc);

    int wm = (wid >> 1) * 32, wn = (wid & 1) * 64;
    #pragma unroll
    for (int mt = 0; mt < 2; mt++) {
        #pragma unroll
        for (int nt = 0; nt < 8; nt++) {
            int mA = m0 + wm + mt * 16 + (lid >> 2);
            int nA = n0 + wn + nt * 8 + (lid & 3) * 2;
            float b0 = bias[nA], b1 = bias[nA + 1];
            *(float2*)(Y + (size_t)mA * D_ + nA) =
                make_float2(acc[mt][nt][0] + b0, acc[mt][nt][1] + b1);
            *(float2*)(Y + (size_t)(mA + 8) * D_ + nA) =
                make_float2(acc[mt][nt][2] + b0, acc[mt][nt][3] + b1);
        }
    }
}

// ---------------------------------------------------------------------------
// Flash attention via mma.sync. CTA = 128 q-rows x (b,h). 8 warps x 16 rows.
// Bc=64 kv tiles (32 iterations), double-buffered cp.async, single sync/iter.
// P packed per-ks directly into register A-fragments (no P smem).
// Layout: Qh@0(18432) Ql@18432 | KV buf{0,1}@36864+buf*36864:
//   Kh@+0 (64x144=9216) Kl@+9216 Vth@+18432 (64x144) Vtl@+27648
// Total 110592 -> 2 CTAs/SM.
// ---------------------------------------------------------------------------
#define FQL  18432
#define FKV  36864
#define FKVB 36864
#define F_SMEM_TOTAL 110592

__device__ __forceinline__ void flash_issue_kv(
    uint32_t sb, int buf, int kt, size_t bh, int tid,
    const bf16* kh, const bf16* kl, const bf16* vth, const bf16* vtl)
{
    uint32_t kvbase = sb + FKV + buf * FKVB;
    #pragma unroll
    for (int it = 0; it < 8; it++) {
        int j = tid + it * 256;
        int sub = j >> 9, rem = j & 511;
        int r = rem >> 3, c = rem & 7;
        uint32_t dst = kvbase + sub * 9216 + r * 144 + c * 16;
        const bf16* src;
        if (sub == 0)      src = kh  + (bh * S_ + (size_t)kt * 64 + r) * HD_ + c * 8;
        else if (sub == 1) src = kl  + (bh * S_ + (size_t)kt * 64 + r) * HD_ + c * 8;
        else if (sub == 2) src = vth + (bh * HD_ + r) * S_ + kt * 64 + c * 8;
        else               src = vtl + (bh * HD_ + r) * S_ + kt * 64 + c * 8;
        CP_ASYNC16(dst, src);
    }
    CP_COMMIT();
}

__global__ __launch_bounds__(256, 2) void flash_mma_kernel(
    const bf16* __restrict__ qh, const bf16* __restrict__ ql,
    const bf16* __restrict__ kh, const bf16* __restrict__ kl,
    const bf16* __restrict__ vth, const bf16* __restrict__ vtl,
    bf16* __restrict__ ctxh, bf16* __restrict__ ctxl)
{
    extern __shared__ char smem[];
    uint32_t sb = smem_u32(smem);

    int tid = threadIdx.x, wid = tid >> 5, lid = tid & 31;
    int qblk = blockIdx.x, h = blockIdx.y, b = blockIdx.z;
    size_t bh = (size_t)(b * H_ + h);
    int mw = wid * 16;
    int g = lid >> 3;

    // Q load (group 1)
    #pragma unroll
    for (int it = 0; it < 8; it++) {
        int j = tid + it * 256;
        int sub = j >> 10, rem = j & 1023, r = rem >> 3, c = rem & 7;
        uint32_t dst = sb + sub * 18432 + r * 144 + c * 16;
        const bf16* src = (sub ? ql : qh) +
            (bh * S_ + (size_t)qblk * 128 + r) * HD_ + c * 8;
        CP_ASYNC16(dst, src);
    }
    CP_COMMIT();
    flash_issue_kv(sb, 0, 0, bh, tid, kh, kl, vth, vtl);   // group 2

    float m0 = -1e30f, m1 = -1e30f, l0 = 0.f, l1 = 0.f;
    float oacc[8][4];
    #pragma unroll
    for (int nt = 0; nt < 8; nt++)
        #pragma unroll
        for (int c = 0; c < 4; c++) oacc[nt][c] = 0.f;

    const int NT = S_ / 64;   // 32 kv tiles
    for (int kt = 0; kt < NT; kt++) {
        int buf = kt & 1;
        CP_WAIT0();
        __syncthreads();   // tile data visible + all warps done with buf^1
        if (kt + 1 < NT)
            flash_issue_kv(sb, buf ^ 1, kt + 1, bh, tid, kh, kl, vth, vtl);
        uint32_t kvb = sb + FKV + buf * FKVB;

        // ---- S = Q K^T (3-term split): warp rows mw..mw+15, kv cols 0..63
        float sacc[8][4];
        #pragma unroll
        for (int nt = 0; nt < 8; nt++)
            #pragma unroll
            for (int c = 0; c < 4; c++) sacc[nt][c] = 0.f;

        #pragma unroll
        for (int ks = 0; ks < 4; ks++) {
            uint32_t ah[4], al[4];
            uint32_t ra = sb + (uint32_t)(mw + (lid & 15)) * 144 +
                          ks * 32 + (lid >> 4) * 16;
            ldsm_x4(ah, ra);
            ldsm_x4(al, ra + FQL);
            #pragma unroll
            for (int p = 0; p < 4; p++) {
                uint32_t row = (uint32_t)(p * 16 + ((g >> 1) << 3) + (lid & 7));
                uint32_t rbadr = kvb + row * 144 + ks * 32 + (g & 1) * 16;
                uint32_t bh4[4], bl4[4];
                ldsm_x4(bh4, rbadr);
                ldsm_x4(bl4, rbadr + 9216);
                mma16816(sacc[2*p],   ah, bh4);
                mma16816(sacc[2*p+1], ah, bh4 + 2);
                mma16816(sacc[2*p],   al, bh4);
                mma16816(sacc[2*p+1], al, bh4 + 2);
                mma16816(sacc[2*p],   ah, bl4);
                mma16816(sacc[2*p+1], ah, bl4 + 2);
            }
        }

        // ---- online softmax; regs [0,1] -> row mw+lid/4; [2,3] -> +8
        float mx0 = -1e30f, mx1 = -1e30f;
        #pragma unroll
        for (int nt = 0; nt < 8; nt++) {
            mx0 = fmaxf(mx0, fmaxf(sacc[nt][0], sacc[nt][1]));
            mx1 = fmaxf(mx1, fmaxf(sacc[nt][2], sacc[nt][3]));
        }
        mx0 = fmaxf(mx0, __shfl_xor_sync(0xffffffffu, mx0, 1));
        mx0 = fmaxf(mx0, __shfl_xor_sync(0xffffffffu, mx0, 2));
        mx1 = fmaxf(mx1, __shfl_xor_sync(0xffffffffu, mx1, 1));
        mx1 = fmaxf(mx1, __shfl_xor_sync(0xffffffffu, mx1, 2));
        float mn0 = fmaxf(m0, mx0), mn1 = fmaxf(m1, mx1);
        float corr0 = __expf(m0 - mn0), corr1 = __expf(m1 - mn1);
        m0 = mn0; m1 = mn1;

        // exp in place + row sums
        float sum0 = 0.f, sum1 = 0.f;
        #pragma unroll
        for (int nt = 0; nt < 8; nt++) {
            sacc[nt][0] = __expf(sacc[nt][0] - mn0);
            sacc[nt][1] = __expf(sacc[nt][1] - mn0);
            sacc[nt][2] = __expf(sacc[nt][2] - mn1);
            sacc[nt][3] = __expf(sacc[nt][3] - mn1);
            sum0 += sacc[nt][0] + sacc[nt][1];
            sum1 += sacc[nt][2] + sacc[nt][3];
        }
        sum0 += __shfl_xor_sync(0xffffffffu, sum0, 1);
        sum0 += __shfl_xor_sync(0xffffffffu, sum0, 2);
        sum1 += __shfl_xor_sync(0xffffffffu, sum1, 1);
        sum1 += __shfl_xor_sync(0xffffffffu, sum1, 2);
        l0 = l0 * corr0 + sum0;
        l1 = l1 * corr1 + sum1;
        #pragma unroll
        for (int nt = 0; nt < 8; nt++) {
            oacc[nt][0] *= corr0; oacc[nt][1] *= corr0;
            oacc[nt][2] *= corr1; oacc[nt][3] *= corr1;
        }

        // ---- O += P V: pack P per-ks into register A-fragments, then MMA
        #pragma unroll
        for (int ks = 0; ks < 4; ks++) {
            uint32_t pfh[4], pfl[4];
            pfh[0] = pack_hi(sacc[2*ks][0],   sacc[2*ks][1],   pfl[0]);
            pfh[1] = pack_hi(sacc[2*ks][2],   sacc[2*ks][3],   pfl[1]);
            pfh[2] = pack_hi(sacc[2*ks+1][0], sacc[2*ks+1][1], pfl[2]);
            pfh[3] = pack_hi(sacc[2*ks+1][2], sacc[2*ks+1][3], pfl[3]);
            #pragma unroll
            for (int p = 0; p < 4; p++) {
                uint32_t row = (uint32_t)(p * 16 + ((g >> 1) << 3) + (lid & 7));
                uint32_t rbadr = kvb + 18432 + row * 144 + ks * 32 + (g & 1) * 16;
                uint32_t bv4h[4], bv4l[4];
                ldsm_x4(bv4h, rbadr);
                ldsm_x4(bv4l, rbadr + 9216);
                mma16816(oacc[2*p],   pfh, bv4h);
                mma16816(oacc[2*p+1], pfh, bv4h + 2);
                mma16816(oacc[2*p],   pfl, bv4h);
                mma16816(oacc[2*p+1], pfl, bv4h + 2);
                mma16816(oacc[2*p],   pfh, bv4l);
                mma16816(oacc[2*p+1], pfh, bv4l + 2);
            }
        }
    }

    // ---- epilogue: ctx[b, s, h*64+hd] bf16 hi/lo
    float inv0 = 1.0f / l0, inv1 = 1.0f / l1;
    int s0 = qblk * 128 + mw + (lid >> 2);
    #pragma unroll
    for (int nt = 0; nt < 8; nt++) {
        int cidx = nt * 8 + (lid & 3) * 2;
        float v0 = oacc[nt][0] * inv0, v1 = oacc[nt][1] * inv0;
        float v2 = oacc[nt][2] * inv1, v3 = oacc[nt][3] * inv1;
        size_t base0 = ((size_t)b * S_ + s0) * D_ + h * 64 + cidx;
        size_t base1 = ((size_t)b * S_ + s0 + 8) * D_ + h * 64 + cidx;
        bf162 h0 = mk2(v0, v1), h1 = mk2(v2, v3);
        *(bf162*)(ctxh + base0) = h0;
        *(bf162*)(ctxh + base1) = h1;
        *(bf162*)(ctxl + base0) = mk2(v0 - __bfloat162float(h0.x),
                                      v1 - __bfloat162float(h0.y));
        *(bf162*)(ctxl + base1) = mk2(v2 - __bfloat162float(h1.x),
                                      v3 - __bfloat162float(h1.y));
    }
}

// ---------------------------------------------------------------------------
extern "C" void kernel_launch(void* const* d_in, const int* in_sizes, int n_in,
                              void* d_out, int out_size)
{
    const float* xq = (const float*)d_in[0];
    const float* xk = (const float*)d_in[1];
    const float* xv = (const float*)d_in[2];
    const float* Wq = (const float*)d_in[3];
    const float* bq = (const float*)d_in[4];
    const float* Wk = (const float*)d_in[5];
    const float* bk = (const float*)d_in[6];
    const float* Wv = (const float*)d_in[7];
    const float* bv = (const float*)d_in[8];
    const float* Wo = (const float*)d_in[9];
    const float* bo = (const float*)d_in[10];
    float* out = (float*)d_out;

    bf16 *qh, *ql, *kh, *kl, *vth, *vtl, *ctxh, *ctxl, *xh, *xl, *wh, *wl;
    cudaGetSymbolAddress((void**)&qh,   g_qh);
    cudaGetSymbolAddress((void**)&ql,   g_ql);
    cudaGetSymbolAddress((void**)&kh,   g_kh);
    cudaGetSymbolAddress((void**)&kl,   g_kl);
    cudaGetSymbolAddress((void**)&vth,  g_vth);
    cudaGetSymbolAddress((void**)&vtl,  g_vtl);
    cudaGetSymbolAddress((void**)&ctxh, g_ctxh);
    cudaGetSymbolAddress((void**)&ctxl, g_ctxl);
    cudaGetSymbolAddress((void**)&xh,   g_xh);
    cudaGetSymbolAddress((void**)&xl,   g_xl);
    cudaGetSymbolAddress((void**)&wh,   g_wh);
    cudaGetSymbolAddress((void**)&wl,   g_wl);

    static bool attr_done = false;
    if (!attr_done) {
        cudaFuncSetAttribute(qkv_gemm_kernel,
                             cudaFuncAttributeMaxDynamicSharedMemorySize, G_SMEM_TOTAL);
        cudaFuncSetAttribute(out_gemm_kernel,
                             cudaFuncAttributeMaxDynamicSharedMemorySize, G_SMEM_TOTAL);
        cudaFuncSetAttribute(flash_mma_kernel,
                             cudaFuncAttributeMaxDynamicSharedMemorySize, F_SMEM_TOTAL);
        attr_done = true;
    }

    const size_t DD = (size_t)D_ * D_;

    // Fused conversions
    convert_wT_kernel<<<dim3(32, 32, 4), dim3(32, 8)>>>(Wq, Wk, Wv, Wo, wh, wl);
    convert_hl_kernel<<<dim3(4096, 3), 256>>>(xq, xk, xv, xh, xl);

    // Fused Q/K/V projections (grid.z = 3)
    qkv_gemm_kernel<<<dim3(D_ / 128, M_ / 128, 3), 256, G_SMEM_TOTAL>>>(
        xh, xl, wh, wl, bq, bk, bv, qh, ql, kh, kl, vth, vtl);

    // Attention (outputs ctx bf16 hi/lo directly)
    flash_mma_kernel<<<dim3(S_ / 128, H_, B_), 256, F_SMEM_TOTAL>>>(
        qh, ql, kh, kl, vth, vtl, ctxh, ctxl);

    // Output projection (fp32 out)
    out_gemm_kernel<<<dim3(D_ / 128, M_ / 128), 256, G_SMEM_TOTAL>>>(
        ctxh, ctxl, wh + 3*DD, wl + 3*DD, bo, out);
}